// round 1
// baseline (speedup 1.0000x reference)
#include <cuda_runtime.h>
#include <cstddef>

#define BATCH   4
#define TLEN    1024
#define MEMLEN  1024
#define JDIM    2048      // TLEN + MEMLEN
#define DMODEL  1024
#define NHEAD   16
#define DHEAD   64

// -------- scratch (static __device__ globals; cudaMalloc is forbidden) ------
__device__ float g_q   [(size_t)BATCH * TLEN * DMODEL];        // 16 MB
__device__ float g_kvin[(size_t)BATCH * JDIM * DMODEL];        // 32 MB
__device__ float g_kv  [(size_t)BATCH * JDIM * 2 * DMODEL];    // 64 MB
__device__ float g_attn[(size_t)BATCH * TLEN * DMODEL];        // 16 MB

// ---------------------------------------------------------------------------
// kvin = concat(mem, x) along seq dim, per batch.  float4 copy.
// ---------------------------------------------------------------------------
__global__ void build_kvin(const float* __restrict__ x, const float* __restrict__ mem) {
    size_t i = (size_t)blockIdx.x * blockDim.x + threadIdx.x;     // float4 index
    const size_t total = (size_t)BATCH * JDIM * DMODEL / 4;
    if (i >= total) return;
    size_t f   = i * 4;
    size_t row = f / DMODEL;           // b*JDIM + m
    size_t c   = f % DMODEL;
    size_t b   = row / JDIM;
    size_t m   = row % JDIM;
    float4 v;
    if (m < MEMLEN) v = *(const float4*)&mem[(b * MEMLEN + m) * DMODEL + c];
    else            v = *(const float4*)&x  [(b * TLEN + (m - MEMLEN)) * DMODEL + c];
    ((float4*)g_kvin)[i] = v;
}

// mem_next = x (since mem_len == t, concat(mem,x)[:, -mem_len:] == x)
__global__ void copy_x(const float* __restrict__ x, float* __restrict__ dst) {
    size_t i = (size_t)blockIdx.x * blockDim.x + threadIdx.x;
    const size_t total = (size_t)BATCH * TLEN * DMODEL / 4;
    if (i < total) ((float4*)dst)[i] = ((const float4*)x)[i];
}

// ---------------------------------------------------------------------------
// SGEMM: C[M,N] = A[M,K] @ B[K,N] (+ bias[n]).  Row-major everywhere.
// BM=BN=128, BK=8, 256 threads, 8x8 per-thread tile, float4 global loads.
// Requires M%128==0, N%128==0, K%8==0 (true for all our shapes).
// ---------------------------------------------------------------------------
__global__ __launch_bounds__(256)
void sgemm128(const float* __restrict__ A, const float* __restrict__ Bm,
              const float* __restrict__ bias, float* __restrict__ C,
              int M, int N, int K) {
    __shared__ float As[8][128];
    __shared__ float Bs[8][132];

    const int tid  = threadIdx.x;
    const int row0 = blockIdx.y * 128;
    const int col0 = blockIdx.x * 128;
    const int ty   = tid >> 4;          // 0..15  -> rows ty*8..
    const int tx   = tid & 15;          // 0..15  -> cols tx*8..

    const int arow = tid >> 1;          // A tile 128x8: each thread 1 float4
    const int acol = (tid & 1) * 4;
    const int brow = tid >> 5;          // B tile 8x128
    const int bcol = (tid & 31) * 4;

    float acc[8][8];
#pragma unroll
    for (int i = 0; i < 8; ++i)
#pragma unroll
        for (int j = 0; j < 8; ++j) acc[i][j] = 0.f;

    for (int k0 = 0; k0 < K; k0 += 8) {
        float4 a4 = *(const float4*)&A[(size_t)(row0 + arow) * K + k0 + acol];
        As[acol + 0][arow] = a4.x;
        As[acol + 1][arow] = a4.y;
        As[acol + 2][arow] = a4.z;
        As[acol + 3][arow] = a4.w;
        float4 b4 = *(const float4*)&Bm[(size_t)(k0 + brow) * N + col0 + bcol];
        *(float4*)&Bs[brow][bcol] = b4;
        __syncthreads();

#pragma unroll
        for (int kk = 0; kk < 8; ++kk) {
            float ar[8], br[8];
#pragma unroll
            for (int i = 0; i < 8; ++i) ar[i] = As[kk][ty * 8 + i];
#pragma unroll
            for (int j = 0; j < 8; ++j) br[j] = Bs[kk][tx * 8 + j];
#pragma unroll
            for (int i = 0; i < 8; ++i)
#pragma unroll
                for (int j = 0; j < 8; ++j) acc[i][j] += ar[i] * br[j];
        }
        __syncthreads();
    }

#pragma unroll
    for (int i = 0; i < 8; ++i) {
        size_t r = (size_t)(row0 + ty * 8 + i) * N + col0 + tx * 8;
#pragma unroll
        for (int j = 0; j < 8; ++j) {
            float v = acc[i][j];
            if (bias) v += bias[col0 + tx * 8 + j];
            C[r + j] = v;
        }
    }
}

// ---------------------------------------------------------------------------
// Fused flash attention with Transformer-XL relative shift.
// Block = (row-block rb, head h, batch b); 64 rows per block, 64-col tiles.
// Score(r, m) = scale*q_r·k_m + scale*q_r·w_{m + t-1 - r}, masked m > r+MEMLEN.
// Per tile we compute combined GEMM Q(64x64) @ [K^T | Wspan^T] (64x192):
// W span rows = base + [0,128), base = m0 + 960 - r0; rel col for (r,m0+mm)
// is 64 + mm + (63 - r_local).
// ---------------------------------------------------------------------------
struct AttnSmem {
    float Qs[64][68];
    float KWs[192][68];   // rows 0..63: K tile (later V tile); 64..191: W span
    float CS[64][196];    // combined raw scores
    float Ps[64][68];     // probabilities
    float m_s[64];
    float l_s[64];
    float alpha_s[64];
};

__global__ __launch_bounds__(256, 1)
void attn_kernel(const float* __restrict__ q, const float* __restrict__ kv,
                 const float* __restrict__ rel, float* __restrict__ out) {
    extern __shared__ char smem_raw[];
    AttnSmem& S = *reinterpret_cast<AttnSmem*>(smem_raw);

    const int b  = blockIdx.z;
    const int h  = blockIdx.y;
    const int rb = blockIdx.x;
    const int r0 = rb * 64;
    const int tid = threadIdx.x;
    const int sy = tid >> 4;   // 0..15
    const int sx = tid & 15;   // 0..15
    const float scale = 0.125f;   // 64^-0.5

    // Load Q (scaled)
    for (int i = tid; i < 64 * 16; i += 256) {
        int r = i >> 4, c4 = (i & 15) * 4;
        float4 v = *(const float4*)&q[((size_t)(b * TLEN + r0 + r)) * DMODEL + h * DHEAD + c4];
        v.x *= scale; v.y *= scale; v.z *= scale; v.w *= scale;
        *(float4*)&S.Qs[r][c4] = v;
    }
    if (tid < 64) { S.m_s[tid] = -1e30f; S.l_s[tid] = 0.f; }

    float acc[4][4];
#pragma unroll
    for (int i = 0; i < 4; ++i)
#pragma unroll
        for (int j = 0; j < 4; ++j) acc[i][j] = 0.f;

    __syncthreads();

    const int ntiles = min(32, rb + 17);
    for (int mt = 0; mt < ntiles; ++mt) {
        const int m0 = mt * 64;
        const int base = m0 + 960 - r0;            // >= 0 always

        // K tile -> KWs[0:64]
        for (int i = tid; i < 64 * 16; i += 256) {
            int r = i >> 4, c4 = (i & 15) * 4;
            float4 v = *(const float4*)&kv[((size_t)(b * JDIM + m0 + r)) * (2 * DMODEL) + h * DHEAD + c4];
            *(float4*)&S.KWs[r][c4] = v;
        }
        // W span -> KWs[64:192] (zero-fill past jdim; those entries are masked)
        for (int i = tid; i < 128 * 16; i += 256) {
            int o = i >> 4, c4 = (i & 15) * 4;
            int j = base + o;
            float4 v = make_float4(0.f, 0.f, 0.f, 0.f);
            if (j < JDIM) v = *(const float4*)&rel[((size_t)j * NHEAD + h) * DHEAD + c4];
            *(float4*)&S.KWs[64 + o][c4] = v;
        }
        __syncthreads();

        // Combined score GEMM: 64x192, each thread 4 rows x 12 cols
        float sc[4][12];
#pragma unroll
        for (int i = 0; i < 4; ++i)
#pragma unroll
            for (int j = 0; j < 12; ++j) sc[i][j] = 0.f;

        const int qr = sy * 4;
        const int kc = sx * 12;
#pragma unroll 4
        for (int cc = 0; cc < 64; ++cc) {
            float a0 = S.Qs[qr + 0][cc];
            float a1 = S.Qs[qr + 1][cc];
            float a2 = S.Qs[qr + 2][cc];
            float a3 = S.Qs[qr + 3][cc];
#pragma unroll
            for (int j = 0; j < 12; ++j) {
                float w = S.KWs[kc + j][cc];
                sc[0][j] += a0 * w;
                sc[1][j] += a1 * w;
                sc[2][j] += a2 * w;
                sc[3][j] += a3 * w;
            }
        }
#pragma unroll
        for (int i = 0; i < 4; ++i)
#pragma unroll
            for (int j = 0; j < 12; ++j) S.CS[qr + i][kc + j] = sc[i][j];
        __syncthreads();

        // V tile -> KWs[0:64] (K no longer needed); runs alongside softmax
        for (int i = tid; i < 64 * 16; i += 256) {
            int r = i >> 4, c4 = (i & 15) * 4;
            float4 v = *(const float4*)&kv[((size_t)(b * JDIM + m0 + r)) * (2 * DMODEL) + DMODEL + h * DHEAD + c4];
            *(float4*)&S.KWs[r][c4] = v;
        }

        // Online softmax, one thread per row
        if (tid < 64) {
            const int r = tid;
            const int mlim = r0 + r + MEMLEN - m0;      // unmasked: mm <= mlim
            const int reloff = 64 + 63 - r;             // rel col = reloff + mm
            float rmax = -1e30f;
            for (int mm = 0; mm < 64; ++mm) {
                float s = (mm <= mlim) ? (S.CS[r][mm] + S.CS[r][reloff + mm]) : -1e30f;
                S.Ps[r][mm] = s;
                rmax = fmaxf(rmax, s);
            }
            float mold = S.m_s[r];
            float mnew = fmaxf(mold, rmax);
            float alpha = __expf(mold - mnew);
            float lsum = 0.f;
            for (int mm = 0; mm < 64; ++mm) {
                float p = __expf(S.Ps[r][mm] - mnew);
                S.Ps[r][mm] = p;
                lsum += p;
            }
            S.l_s[r] = S.l_s[r] * alpha + lsum;
            S.m_s[r] = mnew;
            S.alpha_s[r] = alpha;
        }
        __syncthreads();

        // O = O*alpha + P @ V ; each thread 4 rows x 4 cols
        const int pr = sy * 4;
        const int pc = sx * 4;
        float al0 = S.alpha_s[pr + 0];
        float al1 = S.alpha_s[pr + 1];
        float al2 = S.alpha_s[pr + 2];
        float al3 = S.alpha_s[pr + 3];
#pragma unroll
        for (int j = 0; j < 4; ++j) {
            acc[0][j] *= al0; acc[1][j] *= al1; acc[2][j] *= al2; acc[3][j] *= al3;
        }
#pragma unroll 4
        for (int mm = 0; mm < 64; ++mm) {
            float p0 = S.Ps[pr + 0][mm];
            float p1 = S.Ps[pr + 1][mm];
            float p2 = S.Ps[pr + 2][mm];
            float p3 = S.Ps[pr + 3][mm];
#pragma unroll
            for (int j = 0; j < 4; ++j) {
                float v = S.KWs[mm][pc + j];
                acc[0][j] += p0 * v;
                acc[1][j] += p1 * v;
                acc[2][j] += p2 * v;
                acc[3][j] += p3 * v;
            }
        }
        __syncthreads();
    }

    // epilogue: divide by l, write (b, t, d) layout
    const int pr = sy * 4;
    const int pc = sx * 4;
#pragma unroll
    for (int i = 0; i < 4; ++i) {
        float inv = 1.f / S.l_s[pr + i];
        size_t o = ((size_t)(b * TLEN + r0 + pr + i)) * DMODEL + h * DHEAD + pc;
#pragma unroll
        for (int j = 0; j < 4; ++j) out[o + j] = acc[i][j] * inv;
    }
}

// ---------------------------------------------------------------------------
extern "C" void kernel_launch(void* const* d_in, const int* in_sizes, int n_in,
                              void* d_out, int out_size) {
    const float* x    = (const float*)d_in[0];
    const float* mem  = (const float*)d_in[1];
    const float* wq   = (const float*)d_in[2];
    const float* wkv  = (const float*)d_in[3];
    const float* wo   = (const float*)d_in[4];
    const float* bo   = (const float*)d_in[5];
    const float* relw = (const float*)d_in[6];

    float* out_main = (float*)d_out;                               // (b,t,d)
    float* mem_next = out_main + (size_t)BATCH * TLEN * DMODEL;    // (b,t,d)

    float *q, *kvin, *kv, *attn;
    cudaGetSymbolAddress((void**)&q,    g_q);
    cudaGetSymbolAddress((void**)&kvin, g_kvin);
    cudaGetSymbolAddress((void**)&kv,   g_kv);
    cudaGetSymbolAddress((void**)&attn, g_attn);

    // 1) kvin = concat(mem, x)
    {
        size_t n4 = (size_t)BATCH * JDIM * DMODEL / 4;
        build_kvin<<<(unsigned)((n4 + 255) / 256), 256>>>(x, mem);
    }
    // 2) q = x @ wq
    {
        dim3 g(DMODEL / 128, BATCH * TLEN / 128);
        sgemm128<<<g, 256>>>(x, wq, nullptr, q, BATCH * TLEN, DMODEL, DMODEL);
    }
    // 3) kv = kvin @ wkv
    {
        dim3 g(2 * DMODEL / 128, BATCH * JDIM / 128);
        sgemm128<<<g, 256>>>(kvin, wkv, nullptr, kv, BATCH * JDIM, 2 * DMODEL, DMODEL);
    }
    // 4) fused relative-position flash attention
    {
        const int smem_bytes = (int)sizeof(AttnSmem);
        cudaFuncSetAttribute(attn_kernel, cudaFuncAttributeMaxDynamicSharedMemorySize, smem_bytes);
        dim3 g(TLEN / 64, NHEAD, BATCH);
        attn_kernel<<<g, 256, smem_bytes>>>(q, kv, relw, attn);
    }
    // 5) out = attn @ wo + bo
    {
        dim3 g(DMODEL / 128, BATCH * TLEN / 128);
        sgemm128<<<g, 256>>>(attn, wo, bo, out_main, BATCH * TLEN, DMODEL, DMODEL);
    }
    // 6) mem_next = x
    {
        size_t n4 = (size_t)BATCH * TLEN * DMODEL / 4;
        copy_x<<<(unsigned)((n4 + 255) / 256), 256>>>(x, mem_next);
    }
}

// round 2
// speedup vs baseline: 1.2316x; 1.2316x over previous
#include <cuda_runtime.h>
#include <cstddef>
#include <cstdint>

#define BATCH   4
#define TLEN    1024
#define MEMLEN  1024
#define JDIM    2048      // TLEN + MEMLEN
#define DMODEL  1024
#define NHEAD   16
#define DHEAD   64

// -------- scratch (static __device__ globals; cudaMalloc is forbidden) ------
__device__ float g_q   [(size_t)BATCH * TLEN * DMODEL];        // 16 MB
__device__ float g_kvin[(size_t)BATCH * JDIM * DMODEL];        // 32 MB
__device__ float g_kv  [(size_t)BATCH * JDIM * 2 * DMODEL];    // 64 MB
__device__ float g_attn[(size_t)BATCH * TLEN * DMODEL];        // 16 MB

// ---------------------------------------------------------------------------
// cp.async helpers
// ---------------------------------------------------------------------------
__device__ __forceinline__ void cpasync16(void* smem_dst, const void* gsrc, int srcbytes) {
    unsigned saddr = (unsigned)__cvta_generic_to_shared(smem_dst);
    asm volatile("cp.async.cg.shared.global [%0], [%1], 16, %2;\n"
                 :: "r"(saddr), "l"(gsrc), "r"(srcbytes));
}
__device__ __forceinline__ void cp_commit() { asm volatile("cp.async.commit_group;\n"); }
__device__ __forceinline__ void cp_wait0()  { asm volatile("cp.async.wait_group 0;\n"); }

// ---------------------------------------------------------------------------
// kvin = concat(mem, x) along seq dim, per batch.  float4 copy.
// ---------------------------------------------------------------------------
__global__ void build_kvin(const float* __restrict__ x, const float* __restrict__ mem) {
    size_t i = (size_t)blockIdx.x * blockDim.x + threadIdx.x;     // float4 index
    const size_t total = (size_t)BATCH * JDIM * DMODEL / 4;
    if (i >= total) return;
    size_t f   = i * 4;
    size_t row = f / DMODEL;           // b*JDIM + m
    size_t c   = f % DMODEL;
    size_t b   = row / JDIM;
    size_t m   = row % JDIM;
    float4 v;
    if (m < MEMLEN) v = *(const float4*)&mem[(b * MEMLEN + m) * DMODEL + c];
    else            v = *(const float4*)&x  [(b * TLEN + (m - MEMLEN)) * DMODEL + c];
    ((float4*)g_kvin)[i] = v;
}

// mem_next = x (since mem_len == t, concat(mem,x)[:, -mem_len:] == x)
__global__ void copy_x(const float* __restrict__ x, float* __restrict__ dst) {
    size_t i = (size_t)blockIdx.x * blockDim.x + threadIdx.x;
    const size_t total = (size_t)BATCH * TLEN * DMODEL / 4;
    if (i < total) ((float4*)dst)[i] = ((const float4*)x)[i];
}

// ---------------------------------------------------------------------------
// SGEMM: C[M,N] = A[M,K] @ B[K,N] (+ bias[n]).  Row-major.
// BM=BN=128, BK=16, 256 threads, 8x8 per-thread tile, double-buffered smem.
// Requires M%128==0, N%128==0, K%16==0.
// ---------------------------------------------------------------------------
__global__ __launch_bounds__(256)
void sgemm128(const float* __restrict__ A, const float* __restrict__ Bm,
              const float* __restrict__ bias, float* __restrict__ C,
              int M, int N, int K) {
    __shared__ float As[2][16][128];   // transposed: As[k][m]
    __shared__ float Bs[2][16][132];   // natural:    Bs[k][n]

    const int tid  = threadIdx.x;
    const int row0 = blockIdx.y * 128;
    const int col0 = blockIdx.x * 128;
    const int ty   = tid >> 4;          // 0..15
    const int tx   = tid & 15;          // 0..15

    const int arow  = tid >> 1;         // 0..127
    const int acol4 = (tid & 1) * 8;    // 0 or 8
    const int brow  = tid >> 5;         // 0..7  (and brow+8)
    const int bcol  = (tid & 31) * 4;

    float4 ra0, ra1, rb0, rb1;

    // global load of one BK=16 slab into registers
    auto loadG = [&](int k0) {
        const float* ap = &A[(size_t)(row0 + arow) * K + k0 + acol4];
        ra0 = *(const float4*)(ap);
        ra1 = *(const float4*)(ap + 4);
        rb0 = *(const float4*)&Bm[(size_t)(k0 + brow)     * N + col0 + bcol];
        rb1 = *(const float4*)&Bm[(size_t)(k0 + brow + 8) * N + col0 + bcol];
    };
    auto storeS = [&](int bb) {
        As[bb][acol4 + 0][arow] = ra0.x;
        As[bb][acol4 + 1][arow] = ra0.y;
        As[bb][acol4 + 2][arow] = ra0.z;
        As[bb][acol4 + 3][arow] = ra0.w;
        As[bb][acol4 + 4][arow] = ra1.x;
        As[bb][acol4 + 5][arow] = ra1.y;
        As[bb][acol4 + 6][arow] = ra1.z;
        As[bb][acol4 + 7][arow] = ra1.w;
        *(float4*)&Bs[bb][brow][bcol]     = rb0;
        *(float4*)&Bs[bb][brow + 8][bcol] = rb1;
    };

    float acc[8][8];
#pragma unroll
    for (int i = 0; i < 8; ++i)
#pragma unroll
        for (int j = 0; j < 8; ++j) acc[i][j] = 0.f;

    loadG(0);
    storeS(0);
    __syncthreads();

    const int nk = K / 16;
    for (int kt = 0; kt < nk; ++kt) {
        const int cur = kt & 1;
        if (kt + 1 < nk) loadG((kt + 1) * 16);   // issue early; latency hidden by compute

#pragma unroll
        for (int kk = 0; kk < 16; ++kk) {
            float4 a0 = *(const float4*)&As[cur][kk][ty * 8];
            float4 a1 = *(const float4*)&As[cur][kk][ty * 8 + 4];
            float4 b0 = *(const float4*)&Bs[cur][kk][tx * 8];
            float4 b1 = *(const float4*)&Bs[cur][kk][tx * 8 + 4];
            float av[8] = {a0.x, a0.y, a0.z, a0.w, a1.x, a1.y, a1.z, a1.w};
            float bv[8] = {b0.x, b0.y, b0.z, b0.w, b1.x, b1.y, b1.z, b1.w};
#pragma unroll
            for (int i = 0; i < 8; ++i)
#pragma unroll
                for (int j = 0; j < 8; ++j) acc[i][j] += av[i] * bv[j];
        }

        if (kt + 1 < nk) {
            storeS(cur ^ 1);      // writes the OTHER buffer; readers use cur
            __syncthreads();
        }
    }

#pragma unroll
    for (int i = 0; i < 8; ++i) {
        size_t r = (size_t)(row0 + ty * 8 + i) * N + col0 + tx * 8;
        float4 o0 = make_float4(acc[i][0], acc[i][1], acc[i][2], acc[i][3]);
        float4 o1 = make_float4(acc[i][4], acc[i][5], acc[i][6], acc[i][7]);
        if (bias) {
            float4 z0 = *(const float4*)&bias[col0 + tx * 8];
            float4 z1 = *(const float4*)&bias[col0 + tx * 8 + 4];
            o0.x += z0.x; o0.y += z0.y; o0.z += z0.z; o0.w += z0.w;
            o1.x += z1.x; o1.y += z1.y; o1.z += z1.z; o1.w += z1.w;
        }
        *(float4*)&C[r]     = o0;
        *(float4*)&C[r + 4] = o1;
    }
}

// ---------------------------------------------------------------------------
// Fused flash attention with Transformer-XL relative shift.
// Block = (row-block rb, head h, batch b); 64 rows per block, 64-col tiles.
// Score(r, m) = scale*q_r·k_m + scale*q_r·w_{m + t-1 - r}, masked m > r+MEMLEN.
// Combined GEMM Q(64x64) @ [K^T | Wspan^T] (64x192); rel col for (r, m0+mm)
// is 64 + mm + (63 - r_local).  K/W/V tiles double-buffered via cp.async.
// ---------------------------------------------------------------------------
struct __align__(16) AttnSmem {
    float Qs[64][68];          // natural [row][dh]
    float KW[2][192][68];      // rows 0..63: K^T-ish (K rows), 64..191: W span
    float Vs[2][64][68];
    float CS[64][196];         // combined raw scores
    float Ps[64][68];          // probabilities
    float m_s[64];
    float l_s[64];
    float alpha_s[64];
};

__device__ __forceinline__ void attn_prefetch(
    AttnSmem& S, int bb, const float* __restrict__ kv, const float* __restrict__ rel,
    int b, int h, int m0, int base, int tid)
{
    // K tile: 64 rows x 16 float4
#pragma unroll
    for (int p = 0; p < 4; ++p) {
        int i = tid + p * 256;
        int r = i >> 4, c4 = (i & 15) * 4;
        cpasync16(&S.KW[bb][r][c4],
                  &kv[((size_t)(b * JDIM + m0 + r)) * (2 * DMODEL) + h * DHEAD + c4], 16);
    }
    // W span: 128 rows x 16 float4 (zero-fill past jdim)
#pragma unroll
    for (int p = 0; p < 8; ++p) {
        int i = tid + p * 256;
        int o = i >> 4, c4 = (i & 15) * 4;
        int j = base + o;
        bool ok = (j < JDIM);
        const float* src = ok ? &rel[((size_t)j * NHEAD + h) * DHEAD + c4] : rel;
        cpasync16(&S.KW[bb][64 + o][c4], src, ok ? 16 : 0);
    }
    // V tile: 64 rows x 16 float4
#pragma unroll
    for (int p = 0; p < 4; ++p) {
        int i = tid + p * 256;
        int r = i >> 4, c4 = (i & 15) * 4;
        cpasync16(&S.Vs[bb][r][c4],
                  &kv[((size_t)(b * JDIM + m0 + r)) * (2 * DMODEL) + DMODEL + h * DHEAD + c4], 16);
    }
}

__global__ __launch_bounds__(256, 1)
void attn_kernel(const float* __restrict__ q, const float* __restrict__ kv,
                 const float* __restrict__ rel, float* __restrict__ out) {
    extern __shared__ char smem_raw[];
    AttnSmem& S = *reinterpret_cast<AttnSmem*>(smem_raw);

    const int b  = blockIdx.z;
    const int h  = blockIdx.y;
    const int rb = blockIdx.x;
    const int r0 = rb * 64;
    const int tid = threadIdx.x;
    const int sy = tid >> 4;   // 0..15
    const int sx = tid & 15;   // 0..15
    const float scale = 0.125f;   // 64^-0.5

    // Load Q (scaled)
#pragma unroll
    for (int p = 0; p < 4; ++p) {
        int i = tid + p * 256;
        int r = i >> 4, c4 = (i & 15) * 4;
        float4 v = *(const float4*)&q[((size_t)(b * TLEN + r0 + r)) * DMODEL + h * DHEAD + c4];
        v.x *= scale; v.y *= scale; v.z *= scale; v.w *= scale;
        *(float4*)&S.Qs[r][c4] = v;
    }
    if (tid < 64) { S.m_s[tid] = -1e30f; S.l_s[tid] = 0.f; }

    float acc[4][4];
#pragma unroll
    for (int i = 0; i < 4; ++i)
#pragma unroll
        for (int j = 0; j < 4; ++j) acc[i][j] = 0.f;

    const int ntiles = min(32, rb + 17);

    // prefetch tile 0
    attn_prefetch(S, 0, kv, rel, b, h, 0, 960 - r0, tid);
    cp_commit();

    // softmax thread mapping: 4 threads per row
    const int srow  = tid >> 2;      // 0..63
    const int part  = tid & 3;       // 0..3
    const int reloff = 64 + 63 - srow;

    for (int mt = 0; mt < ntiles; ++mt) {
        const int cur = mt & 1;
        const int m0  = mt * 64;

        cp_wait0();
        __syncthreads();

        // ---- combined score GEMM: 64x192, thread tile 4 rows x 12 cols ----
        {
            const int qr = sy * 4;
            const int kc = sx * 12;
            float sc[4][12];
#pragma unroll
            for (int i = 0; i < 4; ++i)
#pragma unroll
                for (int j = 0; j < 12; ++j) sc[i][j] = 0.f;

#pragma unroll
            for (int c4 = 0; c4 < 16; ++c4) {
                float4 q0 = *(const float4*)&S.Qs[qr + 0][c4 * 4];
                float4 q1 = *(const float4*)&S.Qs[qr + 1][c4 * 4];
                float4 q2 = *(const float4*)&S.Qs[qr + 2][c4 * 4];
                float4 q3 = *(const float4*)&S.Qs[qr + 3][c4 * 4];
#pragma unroll
                for (int j = 0; j < 12; ++j) {
                    float4 w = *(const float4*)&S.KW[cur][kc + j][c4 * 4];
                    sc[0][j] += q0.x * w.x + q0.y * w.y + q0.z * w.z + q0.w * w.w;
                    sc[1][j] += q1.x * w.x + q1.y * w.y + q1.z * w.z + q1.w * w.w;
                    sc[2][j] += q2.x * w.x + q2.y * w.y + q2.z * w.z + q2.w * w.w;
                    sc[3][j] += q3.x * w.x + q3.y * w.y + q3.z * w.z + q3.w * w.w;
                }
            }
#pragma unroll
            for (int i = 0; i < 4; ++i) {
#pragma unroll
                for (int j4 = 0; j4 < 3; ++j4) {
                    *(float4*)&S.CS[qr + i][kc + j4 * 4] =
                        make_float4(sc[i][j4 * 4 + 0], sc[i][j4 * 4 + 1],
                                    sc[i][j4 * 4 + 2], sc[i][j4 * 4 + 3]);
                }
            }
        }
        __syncthreads();

        // prefetch next tile (overlaps with softmax + PV below)
        if (mt + 1 < ntiles) {
            attn_prefetch(S, cur ^ 1, kv, rel, b, h, m0 + 64, m0 + 64 + 960 - r0, tid);
            cp_commit();
        }

        // ---- parallel online softmax: 4 threads per row, 16 cols each ----
        {
            const int mlim = r0 + srow + MEMLEN - m0;   // unmasked: mm <= mlim
            float sreg[16];
            float rmax = -1e30f;
#pragma unroll
            for (int k = 0; k < 16; ++k) {
                int mm = part * 16 + k;
                float s = (mm <= mlim) ? (S.CS[srow][mm] + S.CS[srow][reloff + mm]) : -1e30f;
                sreg[k] = s;
                rmax = fmaxf(rmax, s);
            }
            rmax = fmaxf(rmax, __shfl_xor_sync(0xffffffffu, rmax, 1));
            rmax = fmaxf(rmax, __shfl_xor_sync(0xffffffffu, rmax, 2));
            float mold = S.m_s[srow];
            float mnew = fmaxf(mold, rmax);
            float lsum = 0.f;
#pragma unroll
            for (int k = 0; k < 16; ++k) {
                float p = __expf(sreg[k] - mnew);
                S.Ps[srow][part * 16 + k] = p;
                lsum += p;
            }
            lsum += __shfl_xor_sync(0xffffffffu, lsum, 1);
            lsum += __shfl_xor_sync(0xffffffffu, lsum, 2);
            if (part == 0) {
                float alpha = __expf(mold - mnew);
                S.l_s[srow] = S.l_s[srow] * alpha + lsum;
                S.m_s[srow] = mnew;
                S.alpha_s[srow] = alpha;
            }
        }
        __syncthreads();

        // ---- O = O*alpha + P @ V ; thread tile 4 rows x 4 cols ----
        {
            const int pr = sy * 4;
            const int pc = sx * 4;
            float al0 = S.alpha_s[pr + 0];
            float al1 = S.alpha_s[pr + 1];
            float al2 = S.alpha_s[pr + 2];
            float al3 = S.alpha_s[pr + 3];
#pragma unroll
            for (int j = 0; j < 4; ++j) {
                acc[0][j] *= al0; acc[1][j] *= al1; acc[2][j] *= al2; acc[3][j] *= al3;
            }
#pragma unroll
            for (int m4 = 0; m4 < 16; ++m4) {
                float4 p0 = *(const float4*)&S.Ps[pr + 0][m4 * 4];
                float4 p1 = *(const float4*)&S.Ps[pr + 1][m4 * 4];
                float4 p2 = *(const float4*)&S.Ps[pr + 2][m4 * 4];
                float4 p3 = *(const float4*)&S.Ps[pr + 3][m4 * 4];
                float4 v0 = *(const float4*)&S.Vs[cur][m4 * 4 + 0][pc];
                float4 v1 = *(const float4*)&S.Vs[cur][m4 * 4 + 1][pc];
                float4 v2 = *(const float4*)&S.Vs[cur][m4 * 4 + 2][pc];
                float4 v3 = *(const float4*)&S.Vs[cur][m4 * 4 + 3][pc];

                acc[0][0] += p0.x*v0.x + p0.y*v1.x + p0.z*v2.x + p0.w*v3.x;
                acc[0][1] += p0.x*v0.y + p0.y*v1.y + p0.z*v2.y + p0.w*v3.y;
                acc[0][2] += p0.x*v0.z + p0.y*v1.z + p0.z*v2.z + p0.w*v3.z;
                acc[0][3] += p0.x*v0.w + p0.y*v1.w + p0.z*v2.w + p0.w*v3.w;

                acc[1][0] += p1.x*v0.x + p1.y*v1.x + p1.z*v2.x + p1.w*v3.x;
                acc[1][1] += p1.x*v0.y + p1.y*v1.y + p1.z*v2.y + p1.w*v3.y;
                acc[1][2] += p1.x*v0.z + p1.y*v1.z + p1.z*v2.z + p1.w*v3.z;
                acc[1][3] += p1.x*v0.w + p1.y*v1.w + p1.z*v2.w + p1.w*v3.w;

                acc[2][0] += p2.x*v0.x + p2.y*v1.x + p2.z*v2.x + p2.w*v3.x;
                acc[2][1] += p2.x*v0.y + p2.y*v1.y + p2.z*v2.y + p2.w*v3.y;
                acc[2][2] += p2.x*v0.z + p2.y*v1.z + p2.z*v2.z + p2.w*v3.z;
                acc[2][3] += p2.x*v0.w + p2.y*v1.w + p2.z*v2.w + p2.w*v3.w;

                acc[3][0] += p3.x*v0.x + p3.y*v1.x + p3.z*v2.x + p3.w*v3.x;
                acc[3][1] += p3.x*v0.y + p3.y*v1.y + p3.z*v2.y + p3.w*v3.y;
                acc[3][2] += p3.x*v0.z + p3.y*v1.z + p3.z*v2.z + p3.w*v3.z;
                acc[3][3] += p3.x*v0.w + p3.y*v1.w + p3.z*v2.w + p3.w*v3.w;
            }
        }
        __syncthreads();
    }

    // epilogue: divide by l, write (b, t, d) layout
    {
        const int pr = sy * 4;
        const int pc = sx * 4;
#pragma unroll
        for (int i = 0; i < 4; ++i) {
            float inv = 1.f / S.l_s[pr + i];
            size_t o = ((size_t)(b * TLEN + r0 + pr + i)) * DMODEL + h * DHEAD + pc;
            float4 ov = make_float4(acc[i][0] * inv, acc[i][1] * inv,
                                    acc[i][2] * inv, acc[i][3] * inv);
            *(float4*)&out[o] = ov;
        }
    }
}

// ---------------------------------------------------------------------------
extern "C" void kernel_launch(void* const* d_in, const int* in_sizes, int n_in,
                              void* d_out, int out_size) {
    const float* x    = (const float*)d_in[0];
    const float* mem  = (const float*)d_in[1];
    const float* wq   = (const float*)d_in[2];
    const float* wkv  = (const float*)d_in[3];
    const float* wo   = (const float*)d_in[4];
    const float* bo   = (const float*)d_in[5];
    const float* relw = (const float*)d_in[6];

    float* out_main = (float*)d_out;                               // (b,t,d)
    float* mem_next = out_main + (size_t)BATCH * TLEN * DMODEL;    // (b,t,d)

    float *q, *kvin, *kv, *attn;
    cudaGetSymbolAddress((void**)&q,    g_q);
    cudaGetSymbolAddress((void**)&kvin, g_kvin);
    cudaGetSymbolAddress((void**)&kv,   g_kv);
    cudaGetSymbolAddress((void**)&attn, g_attn);

    // 1) kvin = concat(mem, x)
    {
        size_t n4 = (size_t)BATCH * JDIM * DMODEL / 4;
        build_kvin<<<(unsigned)((n4 + 255) / 256), 256>>>(x, mem);
    }
    // 2) q = x @ wq
    {
        dim3 g(DMODEL / 128, BATCH * TLEN / 128);
        sgemm128<<<g, 256>>>(x, wq, nullptr, q, BATCH * TLEN, DMODEL, DMODEL);
    }
    // 3) kv = kvin @ wkv
    {
        dim3 g(2 * DMODEL / 128, BATCH * JDIM / 128);
        sgemm128<<<g, 256>>>(kvin, wkv, nullptr, kv, BATCH * JDIM, 2 * DMODEL, DMODEL);
    }
    // 4) fused relative-position flash attention
    {
        const int smem_bytes = (int)sizeof(AttnSmem);
        cudaFuncSetAttribute(attn_kernel, cudaFuncAttributeMaxDynamicSharedMemorySize, smem_bytes);
        dim3 g(TLEN / 64, NHEAD, BATCH);
        attn_kernel<<<g, 256, smem_bytes>>>(q, kv, relw, attn);
    }
    // 5) out = attn @ wo + bo
    {
        dim3 g(DMODEL / 128, BATCH * TLEN / 128);
        sgemm128<<<g, 256>>>(attn, wo, bo, out_main, BATCH * TLEN, DMODEL, DMODEL);
    }
    // 6) mem_next = x
    {
        size_t n4 = (size_t)BATCH * TLEN * DMODEL / 4;
        copy_x<<<(unsigned)((n4 + 255) / 256), 256>>>(x, mem_next);
    }
}

// round 4
// speedup vs baseline: 1.7930x; 1.4559x over previous
#include <cuda_runtime.h>
#include <cstddef>
#include <cstdint>

#define BATCH   4
#define TLEN    1024
#define MEMLEN  1024
#define JDIM    2048      // TLEN + MEMLEN
#define DMODEL  1024
#define NHEAD   16
#define DHEAD   64

// -------- scratch (static __device__ globals; cudaMalloc is forbidden) ------
__device__ float g_q   [(size_t)BATCH * TLEN * DMODEL];          // 16 MB
__device__ float g_kvin[(size_t)BATCH * JDIM * DMODEL];          // 32 MB
__device__ float g_kv  [(size_t)BATCH * JDIM * 2 * DMODEL];      // 64 MB
__device__ float g_attn[(size_t)BATCH * TLEN * DMODEL];          // 16 MB
__device__ float g_gsh [(size_t)BATCH * NHEAD * TLEN * JDIM];    // 512 MB (shifted rel scores)

// ---------------------------------------------------------------------------
// cp.async helpers
// ---------------------------------------------------------------------------
__device__ __forceinline__ void cpasync16(void* smem_dst, const void* gsrc) {
    unsigned saddr = (unsigned)__cvta_generic_to_shared(smem_dst);
    asm volatile("cp.async.cg.shared.global [%0], [%1], 16;\n"
                 :: "r"(saddr), "l"(gsrc));
}
__device__ __forceinline__ void cp_commit() { asm volatile("cp.async.commit_group;\n"); }
__device__ __forceinline__ void cp_wait0()  { asm volatile("cp.async.wait_group 0;\n"); }

// ---------------------------------------------------------------------------
// kvin = concat(mem, x) along seq dim, per batch.  float4 copy.
// ---------------------------------------------------------------------------
__global__ void build_kvin(const float* __restrict__ x, const float* __restrict__ mem) {
    size_t i = (size_t)blockIdx.x * blockDim.x + threadIdx.x;     // float4 index
    const size_t total = (size_t)BATCH * JDIM * DMODEL / 4;
    if (i >= total) return;
    size_t f   = i * 4;
    size_t row = f / DMODEL;           // b*JDIM + m
    size_t c   = f % DMODEL;
    size_t b   = row / JDIM;
    size_t m   = row % JDIM;
    float4 v;
    if (m < MEMLEN) v = *(const float4*)&mem[(b * MEMLEN + m) * DMODEL + c];
    else            v = *(const float4*)&x  [(b * TLEN + (m - MEMLEN)) * DMODEL + c];
    ((float4*)g_kvin)[i] = v;
}

// mem_next = x (since mem_len == t, concat(mem,x)[:, -mem_len:] == x)
__global__ void copy_x(const float* __restrict__ x, float* __restrict__ dst) {
    size_t i = (size_t)blockIdx.x * blockDim.x + threadIdx.x;
    const size_t total = (size_t)BATCH * TLEN * DMODEL / 4;
    if (i < total) ((float4*)dst)[i] = ((const float4*)x)[i];
}

// ---------------------------------------------------------------------------
// SGEMM: C[M,N] = A[M,K] @ B[K,N] (+ bias[n]).  Row-major.
// BM=BN=128, BK=16, 256 threads, 8x8 per-thread tile, double-buffered smem.
// B-read conflict-free: thread cols = {tx*4..+3, 64+tx*4..+3}.
// ---------------------------------------------------------------------------
__global__ __launch_bounds__(256)
void sgemm128(const float* __restrict__ A, const float* __restrict__ Bm,
              const float* __restrict__ bias, float* __restrict__ C,
              int M, int N, int K) {
    __shared__ float As[2][16][128];   // transposed: As[k][m]
    __shared__ float Bs[2][16][132];   // natural:    Bs[k][n]

    const int tid  = threadIdx.x;
    const int row0 = blockIdx.y * 128;
    const int col0 = blockIdx.x * 128;
    const int ty   = tid >> 4;          // 0..15
    const int tx   = tid & 15;          // 0..15

    const int arow  = tid >> 1;         // 0..127
    const int acol4 = (tid & 1) * 8;    // 0 or 8
    const int brow  = tid >> 5;         // 0..7  (and brow+8)
    const int bcol  = (tid & 31) * 4;

    float4 ra0, ra1, rb0, rb1;

    auto loadG = [&](int k0) {
        const float* ap = &A[(size_t)(row0 + arow) * K + k0 + acol4];
        ra0 = *(const float4*)(ap);
        ra1 = *(const float4*)(ap + 4);
        rb0 = *(const float4*)&Bm[(size_t)(k0 + brow)     * N + col0 + bcol];
        rb1 = *(const float4*)&Bm[(size_t)(k0 + brow + 8) * N + col0 + bcol];
    };
    auto storeS = [&](int bb) {
        As[bb][acol4 + 0][arow] = ra0.x;
        As[bb][acol4 + 1][arow] = ra0.y;
        As[bb][acol4 + 2][arow] = ra0.z;
        As[bb][acol4 + 3][arow] = ra0.w;
        As[bb][acol4 + 4][arow] = ra1.x;
        As[bb][acol4 + 5][arow] = ra1.y;
        As[bb][acol4 + 6][arow] = ra1.z;
        As[bb][acol4 + 7][arow] = ra1.w;
        *(float4*)&Bs[bb][brow][bcol]     = rb0;
        *(float4*)&Bs[bb][brow + 8][bcol] = rb1;
    };

    float acc[8][8];
#pragma unroll
    for (int i = 0; i < 8; ++i)
#pragma unroll
        for (int j = 0; j < 8; ++j) acc[i][j] = 0.f;

    loadG(0);
    storeS(0);
    __syncthreads();

    const int nk = K / 16;
    for (int kt = 0; kt < nk; ++kt) {
        const int cur = kt & 1;
        if (kt + 1 < nk) loadG((kt + 1) * 16);

#pragma unroll
        for (int kk = 0; kk < 16; ++kk) {
            float4 a0 = *(const float4*)&As[cur][kk][ty * 8];
            float4 a1 = *(const float4*)&As[cur][kk][ty * 8 + 4];
            float4 b0 = *(const float4*)&Bs[cur][kk][tx * 4];
            float4 b1 = *(const float4*)&Bs[cur][kk][64 + tx * 4];
            float av[8] = {a0.x, a0.y, a0.z, a0.w, a1.x, a1.y, a1.z, a1.w};
            float bv[8] = {b0.x, b0.y, b0.z, b0.w, b1.x, b1.y, b1.z, b1.w};
#pragma unroll
            for (int i = 0; i < 8; ++i)
#pragma unroll
                for (int j = 0; j < 8; ++j) acc[i][j] += av[i] * bv[j];
        }

        if (kt + 1 < nk) {
            storeS(cur ^ 1);
            __syncthreads();
        }
    }

#pragma unroll
    for (int i = 0; i < 8; ++i) {
        size_t r = (size_t)(row0 + ty * 8 + i) * N;
        int c0 = col0 + tx * 4;
        int c1 = col0 + 64 + tx * 4;
        float4 o0 = make_float4(acc[i][0], acc[i][1], acc[i][2], acc[i][3]);
        float4 o1 = make_float4(acc[i][4], acc[i][5], acc[i][6], acc[i][7]);
        if (bias) {
            float4 z0 = *(const float4*)&bias[c0];
            float4 z1 = *(const float4*)&bias[c1];
            o0.x += z0.x; o0.y += z0.y; o0.z += z0.z; o0.w += z0.w;
            o1.x += z1.x; o1.y += z1.y; o1.z += z1.z; o1.w += z1.w;
        }
        *(float4*)&C[r + c0] = o0;
        *(float4*)&C[r + c1] = o1;
    }
}

// ---------------------------------------------------------------------------
// Gshift GEMM: for each (b,h):  G[r][u] = scale * q[b,r,h*64:] · rel[u,h,:]
// written SHIFTED:  Gshift[b,h,r, j] = G[r][ j + 1023 - r ]  (only 0<=j<2048)
// NT GEMM, K=64 single-shot, 128x128 tiles, 8x8 per thread, band-skipped.
// ---------------------------------------------------------------------------
__global__ __launch_bounds__(256)
void gshift_gemm(const float* __restrict__ q, const float* __restrict__ rel,
                 float* __restrict__ gsh) {
    const int z  = blockIdx.z;           // b*16 + h
    const int r0 = blockIdx.y * 128;
    const int u0 = blockIdx.x * 128;
    // tile contributes iff exists (r,u) with j = u-1023+r >= 0
    if (u0 + 127 + r0 + 127 < 1023) return;

    __shared__ float As[64][132];
    __shared__ float Bs[64][132];

    const int b = z >> 4, h = z & 15;
    const int tid = threadIdx.x;
    const int ty = tid >> 4, tx = tid & 15;

#pragma unroll
    for (int p = 0; p < 8; ++p) {
        int idx = tid + p * 256;
        int r = idx >> 4, c4 = (idx & 15) * 4;
        float4 v = *(const float4*)&q[((size_t)(b * TLEN + r0 + r)) * DMODEL + h * DHEAD + c4];
        As[c4 + 0][r] = v.x; As[c4 + 1][r] = v.y; As[c4 + 2][r] = v.z; As[c4 + 3][r] = v.w;
    }
#pragma unroll
    for (int p = 0; p < 8; ++p) {
        int idx = tid + p * 256;
        int u = idx >> 4, c4 = (idx & 15) * 4;
        float4 v = *(const float4*)&rel[((size_t)(u0 + u) * NHEAD + h) * DHEAD + c4];
        Bs[c4 + 0][u] = v.x; Bs[c4 + 1][u] = v.y; Bs[c4 + 2][u] = v.z; Bs[c4 + 3][u] = v.w;
    }
    __syncthreads();

    float acc[8][8];
#pragma unroll
    for (int i = 0; i < 8; ++i)
#pragma unroll
        for (int j = 0; j < 8; ++j) acc[i][j] = 0.f;

#pragma unroll 8
    for (int kk = 0; kk < 64; ++kk) {
        float4 a0 = *(const float4*)&As[kk][ty * 8];
        float4 a1 = *(const float4*)&As[kk][ty * 8 + 4];
        float4 b0 = *(const float4*)&Bs[kk][tx * 4];
        float4 b1 = *(const float4*)&Bs[kk][64 + tx * 4];
        float av[8] = {a0.x, a0.y, a0.z, a0.w, a1.x, a1.y, a1.z, a1.w};
        float bv[8] = {b0.x, b0.y, b0.z, b0.w, b1.x, b1.y, b1.z, b1.w};
#pragma unroll
        for (int i = 0; i < 8; ++i)
#pragma unroll
            for (int j = 0; j < 8; ++j) acc[i][j] += av[i] * bv[j];
    }

    const float scale = 0.125f;
#pragma unroll
    for (int i = 0; i < 8; ++i) {
        int gr = r0 + ty * 8 + i;
        float* rowp = &gsh[((size_t)z * TLEN + gr) * JDIM];
#pragma unroll
        for (int e = 0; e < 4; ++e) {
            int u  = u0 + tx * 4 + e;
            int jc = u - 1023 + gr;
            if (jc >= 0 && jc < JDIM) rowp[jc] = scale * acc[i][e];
        }
#pragma unroll
        for (int e = 0; e < 4; ++e) {
            int u  = u0 + 64 + tx * 4 + e;
            int jc = u - 1023 + gr;
            if (jc >= 0 && jc < JDIM) rowp[jc] = scale * acc[i][4 + e];
        }
    }
}

// ---------------------------------------------------------------------------
// Fused flash attention.  score(r,j) = qk + Gshift[r][j], masked j > r+1024.
// 64-row blocks, 64-col kv tiles.  K double-buffered, V/G single-buffered
// cp.async.  Rotate-swizzled smem (conflict-free).  Softmax in registers via
// half-warp shuffles.  2 CTAs/SM.
// ---------------------------------------------------------------------------
struct __align__(16) AttnSmem3 {
    float Qs[64][68];         // [row][dh], broadcast reads
    float Ks[2][64][64];      // rotate-swizzled rows
    float Vs[64][64];         // rotate-swizzled rows
    float Gs[64][64];         // rotate-swizzled rows
    float Ps[64][68];         // probabilities
    float m_s[64];
    float l_s[64];
};

__device__ __forceinline__ void pf_K(AttnSmem3& S, int bb, const float* __restrict__ kv,
                                     int b, int h, int m0, int tid) {
#pragma unroll
    for (int p = 0; p < 4; ++p) {
        int i = tid + p * 256;
        int r = i >> 4, c4 = i & 15;
        int slot = (c4 + r) & 15;
        cpasync16(&S.Ks[bb][r][slot * 4],
                  &kv[((size_t)(b * JDIM + m0 + r)) * (2 * DMODEL) + h * DHEAD + c4 * 4]);
    }
}
__device__ __forceinline__ void pf_V(AttnSmem3& S, const float* __restrict__ kv,
                                     int b, int h, int m0, int tid) {
#pragma unroll
    for (int p = 0; p < 4; ++p) {
        int i = tid + p * 256;
        int r = i >> 4, c4 = i & 15;
        int slot = (c4 + r) & 15;
        cpasync16(&S.Vs[r][slot * 4],
                  &kv[((size_t)(b * JDIM + m0 + r)) * (2 * DMODEL) + DMODEL + h * DHEAD + c4 * 4]);
    }
}
__device__ __forceinline__ void pf_G(AttnSmem3& S, const float* __restrict__ gsh,
                                     int bh, int r0, int m0, int tid) {
#pragma unroll
    for (int p = 0; p < 4; ++p) {
        int i = tid + p * 256;
        int r = i >> 4, c4 = i & 15;
        int slot = (c4 + r) & 15;
        cpasync16(&S.Gs[r][slot * 4],
                  &gsh[((size_t)bh * TLEN + r0 + r) * JDIM + m0 + c4 * 4]);
    }
}

__global__ __launch_bounds__(256, 2)
void attn_kernel(const float* __restrict__ q, const float* __restrict__ kv,
                 const float* __restrict__ gsh, float* __restrict__ out) {
    extern __shared__ char smem_raw[];
    AttnSmem3& S = *reinterpret_cast<AttnSmem3*>(smem_raw);

    const int b  = blockIdx.z;
    const int h  = blockIdx.y;
    const int rb = blockIdx.x;
    const int r0 = rb * 64;
    const int bh = b * NHEAD + h;
    const int tid = threadIdx.x;
    const int sy = tid >> 4;   // 0..15
    const int sx = tid & 15;   // 0..15
    const float scale = 0.125f;

    // Load Q (scaled)
#pragma unroll
    for (int p = 0; p < 4; ++p) {
        int i = tid + p * 256;
        int r = i >> 4, c4 = (i & 15) * 4;
        float4 v = *(const float4*)&q[((size_t)(b * TLEN + r0 + r)) * DMODEL + h * DHEAD + c4];
        v.x *= scale; v.y *= scale; v.z *= scale; v.w *= scale;
        *(float4*)&S.Qs[r][c4] = v;
    }
    if (tid < 64) { S.m_s[tid] = -1e30f; S.l_s[tid] = 0.f; }

    float acc[4][4];
#pragma unroll
    for (int i = 0; i < 4; ++i)
#pragma unroll
        for (int j = 0; j < 4; ++j) acc[i][j] = 0.f;

    const int ntiles = min(32, rb + 17);

    pf_K(S, 0, kv, b, h, 0, tid); cp_commit();
    pf_G(S, gsh, bh, r0, 0, tid);
    pf_V(S, kv, b, h, 0, tid);   cp_commit();

    for (int mt = 0; mt < ntiles; ++mt) {
        const int cur = mt & 1;
        const int m0  = mt * 64;

        cp_wait0();
        __syncthreads();                       // K(t), V(t), G(t) ready; prior phases done

        if (mt + 1 < ntiles) { pf_K(S, cur ^ 1, kv, b, h, m0 + 64, tid); cp_commit(); }

        // ---- score GEMM 64x64, thread tile 4x4, registers ----
        float sc[4][4];
#pragma unroll
        for (int i = 0; i < 4; ++i)
#pragma unroll
            for (int j = 0; j < 4; ++j) sc[i][j] = 0.f;

#pragma unroll
        for (int c4 = 0; c4 < 16; ++c4) {
            float4 qv[4], kw[4];
#pragma unroll
            for (int i = 0; i < 4; ++i)
                qv[i] = *(const float4*)&S.Qs[4 * sy + i][c4 * 4];
#pragma unroll
            for (int j = 0; j < 4; ++j) {
                int m = 4 * sx + j;
                kw[j] = *(const float4*)&S.Ks[cur][m][((c4 + m) & 15) * 4];
            }
#pragma unroll
            for (int i = 0; i < 4; ++i)
#pragma unroll
                for (int j = 0; j < 4; ++j)
                    sc[i][j] += qv[i].x * kw[j].x + qv[i].y * kw[j].y +
                                qv[i].z * kw[j].z + qv[i].w * kw[j].w;
        }

        // ---- add shifted rel scores + mask ----
#pragma unroll
        for (int i = 0; i < 4; ++i) {
            int rl = 4 * sy + i;
            int mlim = r0 + rl + MEMLEN - m0;          // unmasked: mm <= mlim
            float4 g = *(const float4*)&S.Gs[rl][((sx + rl) & 15) * 4];
            float ga[4] = {g.x, g.y, g.z, g.w};
#pragma unroll
            for (int j = 0; j < 4; ++j) {
                int mm = 4 * sx + j;
                float s = sc[i][j] + ga[j];
                sc[i][j] = (mm <= mlim) ? s : -1e30f;
            }
        }

        // ---- softmax: per row, reduce across the 16-lane sx group ----
#pragma unroll
        for (int i = 0; i < 4; ++i) {
            int rl = 4 * sy + i;
            float rmax = fmaxf(fmaxf(sc[i][0], sc[i][1]), fmaxf(sc[i][2], sc[i][3]));
            rmax = fmaxf(rmax, __shfl_xor_sync(0xffffffffu, rmax, 1));
            rmax = fmaxf(rmax, __shfl_xor_sync(0xffffffffu, rmax, 2));
            rmax = fmaxf(rmax, __shfl_xor_sync(0xffffffffu, rmax, 4));
            rmax = fmaxf(rmax, __shfl_xor_sync(0xffffffffu, rmax, 8));
            float mold = S.m_s[rl];
            float mnew = fmaxf(mold, rmax);
            float alpha = __expf(mold - mnew);
            float lsum = 0.f;
#pragma unroll
            for (int j = 0; j < 4; ++j) {
                float p = __expf(sc[i][j] - mnew);
                sc[i][j] = p;
                lsum += p;
            }
            lsum += __shfl_xor_sync(0xffffffffu, lsum, 1);
            lsum += __shfl_xor_sync(0xffffffffu, lsum, 2);
            lsum += __shfl_xor_sync(0xffffffffu, lsum, 4);
            lsum += __shfl_xor_sync(0xffffffffu, lsum, 8);
            if (sx == 0) {
                S.m_s[rl] = mnew;
                S.l_s[rl] = S.l_s[rl] * alpha + lsum;
            }
            // rescale accumulator (same thread owns the same rows)
#pragma unroll
            for (int j = 0; j < 4; ++j) acc[i][j] *= alpha;
            *(float4*)&S.Ps[rl][4 * sx] = make_float4(sc[i][0], sc[i][1], sc[i][2], sc[i][3]);
        }
        __syncthreads();                       // Ps ready; Gs consumed

        if (mt + 1 < ntiles) { pf_G(S, gsh, bh, r0, m0 + 64, tid); cp_commit(); }

        // ---- O += P @ V ; thread tile 4x4 ----
#pragma unroll
        for (int m4 = 0; m4 < 16; ++m4) {
            float4 pv[4], vv[4];
#pragma unroll
            for (int i = 0; i < 4; ++i)
                pv[i] = *(const float4*)&S.Ps[4 * sy + i][m4 * 4];
#pragma unroll
            for (int k = 0; k < 4; ++k) {
                int mm = m4 * 4 + k;
                vv[k] = *(const float4*)&S.Vs[mm][((sx + mm) & 15) * 4];
            }
#pragma unroll
            for (int i = 0; i < 4; ++i) {
                float pa[4] = {pv[i].x, pv[i].y, pv[i].z, pv[i].w};
#pragma unroll
                for (int k = 0; k < 4; ++k) {
                    acc[i][0] += pa[k] * vv[k].x;
                    acc[i][1] += pa[k] * vv[k].y;
                    acc[i][2] += pa[k] * vv[k].z;
                    acc[i][3] += pa[k] * vv[k].w;
                }
            }
        }
        __syncthreads();                       // Vs consumed

        if (mt + 1 < ntiles) { pf_V(S, kv, b, h, m0 + 64, tid); cp_commit(); }
    }

    // epilogue: divide by l, write (b, t, d) layout
#pragma unroll
    for (int i = 0; i < 4; ++i) {
        int rl = 4 * sy + i;
        float inv = 1.f / S.l_s[rl];
        size_t o = ((size_t)(b * TLEN + r0 + rl)) * DMODEL + h * DHEAD + 4 * sx;
        *(float4*)&out[o] = make_float4(acc[i][0] * inv, acc[i][1] * inv,
                                        acc[i][2] * inv, acc[i][3] * inv);
    }
}

// ---------------------------------------------------------------------------
extern "C" void kernel_launch(void* const* d_in, const int* in_sizes, int n_in,
                              void* d_out, int out_size) {
    const float* x    = (const float*)d_in[0];
    const float* mem  = (const float*)d_in[1];
    const float* wq   = (const float*)d_in[2];
    const float* wkv  = (const float*)d_in[3];
    const float* wo   = (const float*)d_in[4];
    const float* bo   = (const float*)d_in[5];
    const float* relw = (const float*)d_in[6];

    float* out_main = (float*)d_out;                               // (b,t,d)
    float* mem_next = out_main + (size_t)BATCH * TLEN * DMODEL;    // (b,t,d)

    float *q, *kvin, *kv, *attn, *gsh;
    cudaGetSymbolAddress((void**)&q,    g_q);
    cudaGetSymbolAddress((void**)&kvin, g_kvin);
    cudaGetSymbolAddress((void**)&kv,   g_kv);
    cudaGetSymbolAddress((void**)&attn, g_attn);
    cudaGetSymbolAddress((void**)&gsh,  g_gsh);

    // 1) kvin = concat(mem, x)
    {
        size_t n4 = (size_t)BATCH * JDIM * DMODEL / 4;
        build_kvin<<<(unsigned)((n4 + 255) / 256), 256>>>(x, mem);
    }
    // 2) q = x @ wq
    {
        dim3 g(DMODEL / 128, BATCH * TLEN / 128);
        sgemm128<<<g, 256>>>(x, wq, nullptr, q, BATCH * TLEN, DMODEL, DMODEL);
    }
    // 3) kv = kvin @ wkv
    {
        dim3 g(2 * DMODEL / 128, BATCH * JDIM / 128);
        sgemm128<<<g, 256>>>(kvin, wkv, nullptr, kv, BATCH * JDIM, 2 * DMODEL, DMODEL);
    }
    // 4) shifted rel-position table
    {
        dim3 g(JDIM / 128, TLEN / 128, BATCH * NHEAD);
        gshift_gemm<<<g, 256>>>(q, relw, gsh);
    }
    // 5) fused flash attention
    {
        const int smem_bytes = (int)sizeof(AttnSmem3);
        cudaFuncSetAttribute(attn_kernel, cudaFuncAttributeMaxDynamicSharedMemorySize, smem_bytes);
        dim3 g(TLEN / 64, NHEAD, BATCH);
        attn_kernel<<<g, 256, smem_bytes>>>(q, kv, gsh, attn);
    }
    // 6) out = attn @ wo + bo
    {
        dim3 g(DMODEL / 128, BATCH * TLEN / 128);
        sgemm128<<<g, 256>>>(attn, wo, bo, out_main, BATCH * TLEN, DMODEL, DMODEL);
    }
    // 7) mem_next = x
    {
        size_t n4 = (size_t)BATCH * TLEN * DMODEL / 4;
        copy_x<<<(unsigned)((n4 + 255) / 256), 256>>>(x, mem_next);
    }
}

// round 6
// speedup vs baseline: 2.2130x; 1.2342x over previous
#include <cuda_runtime.h>
#include <cuda_bf16.h>
#include <mma.h>
#include <cstddef>
#include <cstdint>

using namespace nvcuda;

#define BATCH   4
#define TLEN    1024
#define MEMLEN  1024
#define JDIM    2048
#define DMODEL  1024
#define NHEAD   16
#define DHEAD   64
#define KP3     3072      // 3 * DMODEL (compensated K)
#define KG3     192       // 3 * DHEAD

// -------- scratch (static __device__ globals; cudaMalloc is forbidden) ------
__device__ float g_q   [(size_t)BATCH * TLEN * DMODEL];          // 16 MB
__device__ float g_kv  [(size_t)BATCH * JDIM * 2 * DMODEL];      // 64 MB
__device__ float g_attn[(size_t)BATCH * TLEN * DMODEL];          // 16 MB
__device__ float g_gsh [(size_t)BATCH * NHEAD * TLEN * JDIM];    // 512 MB

// bf16 K-concatenated operands
__device__ __nv_bfloat16 g_x2   [(size_t)BATCH * TLEN * KP3];    // [h|l|h]
__device__ __nv_bfloat16 g_kvin2[(size_t)BATCH * JDIM * KP3];    // [h|l|h]
__device__ __nv_bfloat16 g_a2   [(size_t)BATCH * TLEN * KP3];    // [h|l|h]
__device__ __nv_bfloat16 g_wq2  [(size_t)DMODEL * KP3];          // [h|h|l] (transposed)
__device__ __nv_bfloat16 g_wkv2 [(size_t)2 * DMODEL * KP3];      // [h|h|l]
__device__ __nv_bfloat16 g_wo2  [(size_t)DMODEL * KP3];          // [h|h|l]
__device__ __nv_bfloat16 g_q2   [(size_t)BATCH * NHEAD * TLEN * KG3];  // [h|l|h]
__device__ __nv_bfloat16 g_rel2 [(size_t)NHEAD * JDIM * KG3];          // [h|h|l]

// ---------------------------------------------------------------------------
__device__ __forceinline__ uint32_t smem_u32(const void* p) {
    uint32_t a;
    asm("{ .reg .u64 t; cvta.to.shared.u64 t, %1; cvt.u32.u64 %0, t; }" : "=r"(a) : "l"(p));
    return a;
}
__device__ __forceinline__ void cpasync16s(uint32_t saddr, const void* gsrc) {
    asm volatile("cp.async.cg.shared.global [%0], [%1], 16;\n" :: "r"(saddr), "l"(gsrc));
}
__device__ __forceinline__ void cpasync16(void* smem_dst, const void* gsrc) {
    cpasync16s((uint32_t)__cvta_generic_to_shared(smem_dst), gsrc);
}
__device__ __forceinline__ void cp_commit() { asm volatile("cp.async.commit_group;\n"); }
__device__ __forceinline__ void cp_wait0()  { asm volatile("cp.async.wait_group 0;\n"); }

__device__ __forceinline__ void split1(float v, __nv_bfloat16& h, __nv_bfloat16& l) {
    h = __float2bfloat16(v);
    l = __float2bfloat16(v - __bfloat162float(h));
}

// ---------------------------------------------------------------------------
// prep kernels
// ---------------------------------------------------------------------------
// fp32 rows [R][1024] -> bf16 [R][3072] ordered [h | l | h]  (A-side)
__global__ void split3_rows(const float* __restrict__ in, __nv_bfloat16* __restrict__ out,
                            size_t total /* R*256 */) {
    size_t i = (size_t)blockIdx.x * blockDim.x + threadIdx.x;
    if (i >= total) return;
    size_t r = i >> 8;
    int c4 = (int)(i & 255) * 4;
    float4 v = *(const float4*)&in[r * DMODEL + c4];
    __nv_bfloat16 h[4], l[4];
    split1(v.x, h[0], l[0]); split1(v.y, h[1], l[1]);
    split1(v.z, h[2], l[2]); split1(v.w, h[3], l[3]);
    __nv_bfloat16* o = out + r * KP3;
    __nv_bfloat162 hp0 = __halves2bfloat162(h[0], h[1]), hp1 = __halves2bfloat162(h[2], h[3]);
    __nv_bfloat162 lp0 = __halves2bfloat162(l[0], l[1]), lp1 = __halves2bfloat162(l[2], l[3]);
    *(__nv_bfloat162*)(o + c4)              = hp0; *(__nv_bfloat162*)(o + c4 + 2)              = hp1;
    *(__nv_bfloat162*)(o + DMODEL + c4)     = lp0; *(__nv_bfloat162*)(o + DMODEL + c4 + 2)     = lp1;
    *(__nv_bfloat162*)(o + 2 * DMODEL + c4) = hp0; *(__nv_bfloat162*)(o + 2 * DMODEL + c4 + 2) = hp1;
}

// kvin = concat(mem, x) -> [R=8192][3072] ordered [h | l | h]
__global__ void build_kvin_split3(const float* __restrict__ x, const float* __restrict__ mem,
                                  __nv_bfloat16* __restrict__ out) {
    size_t i = (size_t)blockIdx.x * blockDim.x + threadIdx.x;
    const size_t total = (size_t)BATCH * JDIM * 256;
    if (i >= total) return;
    size_t r = i >> 8;
    int c4 = (int)(i & 255) * 4;
    size_t b = r / JDIM, m = r % JDIM;
    float4 v;
    if (m < MEMLEN) v = *(const float4*)&mem[(b * MEMLEN + m) * DMODEL + c4];
    else            v = *(const float4*)&x  [(b * TLEN + (m - MEMLEN)) * DMODEL + c4];
    __nv_bfloat16 h[4], l[4];
    split1(v.x, h[0], l[0]); split1(v.y, h[1], l[1]);
    split1(v.z, h[2], l[2]); split1(v.w, h[3], l[3]);
    __nv_bfloat16* o = out + r * KP3;
    __nv_bfloat162 hp0 = __halves2bfloat162(h[0], h[1]), hp1 = __halves2bfloat162(h[2], h[3]);
    __nv_bfloat162 lp0 = __halves2bfloat162(l[0], l[1]), lp1 = __halves2bfloat162(l[2], l[3]);
    *(__nv_bfloat162*)(o + c4)              = hp0; *(__nv_bfloat162*)(o + c4 + 2)              = hp1;
    *(__nv_bfloat162*)(o + DMODEL + c4)     = lp0; *(__nv_bfloat162*)(o + DMODEL + c4 + 2)     = lp1;
    *(__nv_bfloat162*)(o + 2 * DMODEL + c4) = hp0; *(__nv_bfloat162*)(o + 2 * DMODEL + c4 + 2) = hp1;
}

// W[K=1024][N] fp32 -> T2[N][3072] ordered [h | h | l]  (B-side)
__global__ void transpose_split3(const float* __restrict__ W, __nv_bfloat16* __restrict__ T2, int N) {
    __shared__ float t[32][33];
    int k0 = blockIdx.y * 32, n0 = blockIdx.x * 32;
    int tx = threadIdx.x, ty = threadIdx.y;     // 32 x 8
#pragma unroll
    for (int i = 0; i < 32; i += 8)
        t[ty + i][tx] = W[(size_t)(k0 + ty + i) * N + n0 + tx];
    __syncthreads();
#pragma unroll
    for (int i = 0; i < 32; i += 8) {
        float v = t[tx][ty + i];
        int n = n0 + ty + i, k = k0 + tx;
        __nv_bfloat16 h, l;
        split1(v, h, l);
        __nv_bfloat16* o = T2 + (size_t)n * KP3;
        o[k] = h; o[DMODEL + k] = h; o[2 * DMODEL + k] = l;
    }
}

// q fp32 [b][t][1024] -> q2[(b*16+h)][t][192] ordered [h | l | h]
__global__ void build_q2k(const float* __restrict__ q, __nv_bfloat16* __restrict__ q2) {
    size_t i = (size_t)blockIdx.x * blockDim.x + threadIdx.x;
    const size_t total = (size_t)BATCH * TLEN * NHEAD * 16;
    if (i >= total) return;
    int c4 = (int)(i & 15) * 4;
    int h  = (int)(i >> 4) & 15;
    int t  = (int)(i >> 8) & 1023;
    int b  = (int)(i >> 18);
    float4 v = *(const float4*)&q[((size_t)(b * TLEN + t)) * DMODEL + h * DHEAD + c4];
    __nv_bfloat16 hh[4], ll[4];
    split1(v.x, hh[0], ll[0]); split1(v.y, hh[1], ll[1]);
    split1(v.z, hh[2], ll[2]); split1(v.w, hh[3], ll[3]);
    __nv_bfloat16* o = q2 + ((size_t)(b * NHEAD + h) * TLEN + t) * KG3;
    __nv_bfloat162 hp0 = __halves2bfloat162(hh[0], hh[1]), hp1 = __halves2bfloat162(hh[2], hh[3]);
    __nv_bfloat162 lp0 = __halves2bfloat162(ll[0], ll[1]), lp1 = __halves2bfloat162(ll[2], ll[3]);
    *(__nv_bfloat162*)(o + c4)            = hp0; *(__nv_bfloat162*)(o + c4 + 2)            = hp1;
    *(__nv_bfloat162*)(o + DHEAD + c4)    = lp0; *(__nv_bfloat162*)(o + DHEAD + c4 + 2)    = lp1;
    *(__nv_bfloat162*)(o + 2*DHEAD + c4)  = hp0; *(__nv_bfloat162*)(o + 2*DHEAD + c4 + 2)  = hp1;
}

// rel fp32 [u][h][64] -> rel2[h][u][192] ordered [h | h | l]
__global__ void build_rel2k(const float* __restrict__ rel, __nv_bfloat16* __restrict__ rel2) {
    size_t i = (size_t)blockIdx.x * blockDim.x + threadIdx.x;
    const size_t total = (size_t)JDIM * NHEAD * 16;
    if (i >= total) return;
    int c4 = (int)(i & 15) * 4;
    int h  = (int)(i >> 4) & 15;
    int u  = (int)(i >> 8);
    float4 v = *(const float4*)&rel[((size_t)u * NHEAD + h) * DHEAD + c4];
    __nv_bfloat16 hh[4], ll[4];
    split1(v.x, hh[0], ll[0]); split1(v.y, hh[1], ll[1]);
    split1(v.z, hh[2], ll[2]); split1(v.w, hh[3], ll[3]);
    __nv_bfloat16* o = rel2 + ((size_t)h * JDIM + u) * KG3;
    __nv_bfloat162 hp0 = __halves2bfloat162(hh[0], hh[1]), hp1 = __halves2bfloat162(hh[2], hh[3]);
    __nv_bfloat162 lp0 = __halves2bfloat162(ll[0], ll[1]), lp1 = __halves2bfloat162(ll[2], ll[3]);
    *(__nv_bfloat162*)(o + c4)           = hp0; *(__nv_bfloat162*)(o + c4 + 2)           = hp1;
    *(__nv_bfloat162*)(o + DHEAD + c4)   = hp0; *(__nv_bfloat162*)(o + DHEAD + c4 + 2)   = hp1;
    *(__nv_bfloat162*)(o + 2*DHEAD + c4) = lp0; *(__nv_bfloat162*)(o + 2*DHEAD + c4 + 2) = lp1;
}

__global__ void copy_x(const float* __restrict__ x, float* __restrict__ dst) {
    size_t i = (size_t)blockIdx.x * blockDim.x + threadIdx.x;
    const size_t total = (size_t)BATCH * TLEN * DMODEL / 4;
    if (i < total) ((float4*)dst)[i] = ((const float4*)x)[i];
}

// ---------------------------------------------------------------------------
// wmma bf16 GEMM:  C[M,N] = A[M,Kp] @ B[N,Kp]^T (+bias), row-major A/B.
// 128x128 block, 8 warps (2x4), warp tile 64x32, K stages of 32, cp.async x2.
// smem: stage s at s*20480 (A 10240 + B 10240), bias floats at 40960.
// ---------------------------------------------------------------------------
#define STG_BYTES 20480
#define LDS_ROW   40        // bf16 elems per smem row (32 + 8 pad) -> 80B

__global__ __launch_bounds__(256)
void tgemm_wmma(const __nv_bfloat16* __restrict__ A, const __nv_bfloat16* __restrict__ B,
                const float* __restrict__ bias, float* __restrict__ C,
                int M, int N, int Kp) {
    extern __shared__ char sm[];
    const uint32_t sbase = smem_u32(sm);
    float* biasS = (float*)(sm + 2 * STG_BYTES);      // [16 x 128] identical rows

    const int tid = threadIdx.x;
    const int wid = tid >> 5;
    const int wm = wid >> 2;          // 0..1
    const int wn = wid & 3;           // 0..3
    const int row0 = blockIdx.y * 128;
    const int col0 = blockIdx.x * 128;

    // bias staging (all 16 rows identical)
    for (int i = tid; i < 16 * 128; i += 256)
        biasS[i] = bias ? bias[col0 + (i & 127)] : 0.f;

    auto loadStage = [&](int s, int k0) {
        uint32_t ab = sbase + s * STG_BYTES;
        uint32_t bb = ab + STG_BYTES / 2;
#pragma unroll
        for (int p = 0; p < 2; ++p) {
            int i = tid + p * 256;
            int r = i >> 2, qq = i & 3;
            cpasync16s(ab + r * 80 + qq * 16,
                       (const char*)A + (((size_t)(row0 + r)) * Kp + k0 + qq * 8) * 2);
            cpasync16s(bb + r * 80 + qq * 16,
                       (const char*)B + (((size_t)(col0 + r)) * Kp + k0 + qq * 8) * 2);
        }
    };

    wmma::fragment<wmma::accumulator, 16, 16, 16, float> acc[4][2];
    __syncthreads();   // biasS visible
#pragma unroll
    for (int i = 0; i < 4; ++i)
#pragma unroll
        for (int j = 0; j < 2; ++j)
            wmma::load_matrix_sync(acc[i][j], &biasS[wn * 32 + j * 16], 128, wmma::mem_row_major);

    loadStage(0, 0);
    cp_commit();

    const int nst = Kp / 32;
    for (int st = 0; st < nst; ++st) {
        cp_wait0();
        __syncthreads();
        if (st + 1 < nst) { loadStage((st + 1) & 1, (st + 1) * 32); cp_commit(); }

        const __nv_bfloat16* as = (const __nv_bfloat16*)(sm + (st & 1) * STG_BYTES);
        const __nv_bfloat16* bs = as + STG_BYTES / 4;   // bf16 elems: 10240B/2

#pragma unroll
        for (int kk = 0; kk < 2; ++kk) {
            wmma::fragment<wmma::matrix_a, 16, 16, 16, __nv_bfloat16, wmma::row_major> af[4];
            wmma::fragment<wmma::matrix_b, 16, 16, 16, __nv_bfloat16, wmma::col_major> bfr[2];
#pragma unroll
            for (int i = 0; i < 4; ++i)
                wmma::load_matrix_sync(af[i], as + (wm * 64 + i * 16) * LDS_ROW + kk * 16, LDS_ROW);
#pragma unroll
            for (int j = 0; j < 2; ++j)
                wmma::load_matrix_sync(bfr[j], bs + (wn * 32 + j * 16) * LDS_ROW + kk * 16, LDS_ROW);
#pragma unroll
            for (int i = 0; i < 4; ++i)
#pragma unroll
                for (int j = 0; j < 2; ++j)
                    wmma::mma_sync(acc[i][j], af[i], bfr[j], acc[i][j]);
        }
    }

#pragma unroll
    for (int i = 0; i < 4; ++i)
#pragma unroll
        for (int j = 0; j < 2; ++j)
            wmma::store_matrix_sync(&C[(size_t)(row0 + wm * 64 + i * 16) * N + col0 + wn * 32 + j * 16],
                                    acc[i][j], N, wmma::mem_row_major);
}

// ---------------------------------------------------------------------------
// wmma gshift:  per z=(b*16+h):  G[r][u] = 0.125 * q2[z] @ rel2[h]^T  (Kp=192)
// written shifted: gsh[z][r][jc], jc = u - 1023 + r  (0 <= jc < JDIM)
// ---------------------------------------------------------------------------
__global__ __launch_bounds__(256)
void tgshift_wmma(const __nv_bfloat16* __restrict__ q2, const __nv_bfloat16* __restrict__ rel2,
                  float* __restrict__ gsh) {
    const int z  = blockIdx.z;
    const int r0 = blockIdx.y * 128;
    const int u0 = blockIdx.x * 128;
    if (u0 + r0 < 769) return;         // entire tile has jc < 0

    extern __shared__ char sm[];
    const uint32_t sbase = smem_u32(sm);
    const int tid = threadIdx.x;
    const int wid = tid >> 5;
    const int wm = wid >> 2, wn = wid & 3;

    const __nv_bfloat16* A = q2  + (size_t)z * TLEN * KG3;
    const __nv_bfloat16* B = rel2 + (size_t)(z & 15) * JDIM * KG3;

    auto loadStage = [&](int s, int k0) {
        uint32_t ab = sbase + s * STG_BYTES;
        uint32_t bb = ab + STG_BYTES / 2;
#pragma unroll
        for (int p = 0; p < 2; ++p) {
            int i = tid + p * 256;
            int r = i >> 2, qq = i & 3;
            cpasync16s(ab + r * 80 + qq * 16,
                       (const char*)A + (((size_t)(r0 + r)) * KG3 + k0 + qq * 8) * 2);
            cpasync16s(bb + r * 80 + qq * 16,
                       (const char*)B + (((size_t)(u0 + r)) * KG3 + k0 + qq * 8) * 2);
        }
    };

    wmma::fragment<wmma::accumulator, 16, 16, 16, float> acc[4][2];
#pragma unroll
    for (int i = 0; i < 4; ++i)
#pragma unroll
        for (int j = 0; j < 2; ++j)
            wmma::fill_fragment(acc[i][j], 0.f);

    loadStage(0, 0);
    cp_commit();

    const int nst = KG3 / 32;   // 6
    for (int st = 0; st < nst; ++st) {
        cp_wait0();
        __syncthreads();
        if (st + 1 < nst) { loadStage((st + 1) & 1, (st + 1) * 32); cp_commit(); }

        const __nv_bfloat16* as = (const __nv_bfloat16*)(sm + (st & 1) * STG_BYTES);
        const __nv_bfloat16* bs = as + STG_BYTES / 4;

#pragma unroll
        for (int kk = 0; kk < 2; ++kk) {
            wmma::fragment<wmma::matrix_a, 16, 16, 16, __nv_bfloat16, wmma::row_major> af[4];
            wmma::fragment<wmma::matrix_b, 16, 16, 16, __nv_bfloat16, wmma::col_major> bfr[2];
#pragma unroll
            for (int i = 0; i < 4; ++i)
                wmma::load_matrix_sync(af[i], as + (wm * 64 + i * 16) * LDS_ROW + kk * 16, LDS_ROW);
#pragma unroll
            for (int j = 0; j < 2; ++j)
                wmma::load_matrix_sync(bfr[j], bs + (wn * 32 + j * 16) * LDS_ROW + kk * 16, LDS_ROW);
#pragma unroll
            for (int i = 0; i < 4; ++i)
#pragma unroll
                for (int j = 0; j < 2; ++j)
                    wmma::mma_sync(acc[i][j], af[i], bfr[j], acc[i][j]);
        }
    }

    __syncthreads();                       // all stage reads done; reuse smem as fp32 tile
    float* Cs = (float*)sm;                // [128][132]
#pragma unroll
    for (int i = 0; i < 4; ++i)
#pragma unroll
        for (int j = 0; j < 2; ++j)
            wmma::store_matrix_sync(&Cs[(size_t)(wm * 64 + i * 16) * 132 + wn * 32 + j * 16],
                                    acc[i][j], 132, wmma::mem_row_major);
    __syncthreads();

    // shifted scatter
    for (int idx = tid; idx < 128 * 128; idx += 256) {
        int r = idx >> 7, u = idx & 127;
        int jc = (u0 + u) - 1023 + (r0 + r);
        if ((unsigned)jc < (unsigned)JDIM)
            gsh[((size_t)z * TLEN + r0 + r) * JDIM + jc] = 0.125f * Cs[r * 132 + u];
    }
}

// ---------------------------------------------------------------------------
// Fused flash attention (round-4 version; fp32 SIMT)
// ---------------------------------------------------------------------------
struct __align__(16) AttnSmem3 {
    float Qs[64][68];
    float Ks[2][64][64];
    float Vs[64][64];
    float Gs[64][64];
    float Ps[64][68];
    float m_s[64];
    float l_s[64];
};

__device__ __forceinline__ void pf_K(AttnSmem3& S, int bb, const float* __restrict__ kv,
                                     int b, int h, int m0, int tid) {
#pragma unroll
    for (int p = 0; p < 4; ++p) {
        int i = tid + p * 256;
        int r = i >> 4, c4 = i & 15;
        int slot = (c4 + r) & 15;
        cpasync16(&S.Ks[bb][r][slot * 4],
                  &kv[((size_t)(b * JDIM + m0 + r)) * (2 * DMODEL) + h * DHEAD + c4 * 4]);
    }
}
__device__ __forceinline__ void pf_V(AttnSmem3& S, const float* __restrict__ kv,
                                     int b, int h, int m0, int tid) {
#pragma unroll
    for (int p = 0; p < 4; ++p) {
        int i = tid + p * 256;
        int r = i >> 4, c4 = i & 15;
        int slot = (c4 + r) & 15;
        cpasync16(&S.Vs[r][slot * 4],
                  &kv[((size_t)(b * JDIM + m0 + r)) * (2 * DMODEL) + DMODEL + h * DHEAD + c4 * 4]);
    }
}
__device__ __forceinline__ void pf_G(AttnSmem3& S, const float* __restrict__ gsh,
                                     int bh, int r0, int m0, int tid) {
#pragma unroll
    for (int p = 0; p < 4; ++p) {
        int i = tid + p * 256;
        int r = i >> 4, c4 = i & 15;
        int slot = (c4 + r) & 15;
        cpasync16(&S.Gs[r][slot * 4],
                  &gsh[((size_t)bh * TLEN + r0 + r) * JDIM + m0 + c4 * 4]);
    }
}

__global__ __launch_bounds__(256, 2)
void attn_kernel(const float* __restrict__ q, const float* __restrict__ kv,
                 const float* __restrict__ gsh, float* __restrict__ out) {
    extern __shared__ char smem_raw[];
    AttnSmem3& S = *reinterpret_cast<AttnSmem3*>(smem_raw);

    const int b  = blockIdx.z;
    const int h  = blockIdx.y;
    const int rb = blockIdx.x;
    const int r0 = rb * 64;
    const int bh = b * NHEAD + h;
    const int tid = threadIdx.x;
    const int sy = tid >> 4;
    const int sx = tid & 15;
    const float scale = 0.125f;

#pragma unroll
    for (int p = 0; p < 4; ++p) {
        int i = tid + p * 256;
        int r = i >> 4, c4 = (i & 15) * 4;
        float4 v = *(const float4*)&q[((size_t)(b * TLEN + r0 + r)) * DMODEL + h * DHEAD + c4];
        v.x *= scale; v.y *= scale; v.z *= scale; v.w *= scale;
        *(float4*)&S.Qs[r][c4] = v;
    }
    if (tid < 64) { S.m_s[tid] = -1e30f; S.l_s[tid] = 0.f; }

    float acc[4][4];
#pragma unroll
    for (int i = 0; i < 4; ++i)
#pragma unroll
        for (int j = 0; j < 4; ++j) acc[i][j] = 0.f;

    const int ntiles = min(32, rb + 17);

    pf_K(S, 0, kv, b, h, 0, tid); cp_commit();
    pf_G(S, gsh, bh, r0, 0, tid);
    pf_V(S, kv, b, h, 0, tid);   cp_commit();

    for (int mt = 0; mt < ntiles; ++mt) {
        const int cur = mt & 1;
        const int m0  = mt * 64;

        cp_wait0();
        __syncthreads();

        if (mt + 1 < ntiles) { pf_K(S, cur ^ 1, kv, b, h, m0 + 64, tid); cp_commit(); }

        float sc[4][4];
#pragma unroll
        for (int i = 0; i < 4; ++i)
#pragma unroll
            for (int j = 0; j < 4; ++j) sc[i][j] = 0.f;

#pragma unroll
        for (int c4 = 0; c4 < 16; ++c4) {
            float4 qv[4], kw[4];
#pragma unroll
            for (int i = 0; i < 4; ++i)
                qv[i] = *(const float4*)&S.Qs[4 * sy + i][c4 * 4];
#pragma unroll
            for (int j = 0; j < 4; ++j) {
                int m = 4 * sx + j;
                kw[j] = *(const float4*)&S.Ks[cur][m][((c4 + m) & 15) * 4];
            }
#pragma unroll
            for (int i = 0; i < 4; ++i)
#pragma unroll
                for (int j = 0; j < 4; ++j)
                    sc[i][j] += qv[i].x * kw[j].x + qv[i].y * kw[j].y +
                                qv[i].z * kw[j].z + qv[i].w * kw[j].w;
        }

#pragma unroll
        for (int i = 0; i < 4; ++i) {
            int rl = 4 * sy + i;
            int mlim = r0 + rl + MEMLEN - m0;
            float4 g = *(const float4*)&S.Gs[rl][((sx + rl) & 15) * 4];
            float ga[4] = {g.x, g.y, g.z, g.w};
#pragma unroll
            for (int j = 0; j < 4; ++j) {
                int mm = 4 * sx + j;
                float s = sc[i][j] + ga[j];
                sc[i][j] = (mm <= mlim) ? s : -1e30f;
            }
        }

#pragma unroll
        for (int i = 0; i < 4; ++i) {
            int rl = 4 * sy + i;
            float rmax = fmaxf(fmaxf(sc[i][0], sc[i][1]), fmaxf(sc[i][2], sc[i][3]));
            rmax = fmaxf(rmax, __shfl_xor_sync(0xffffffffu, rmax, 1));
            rmax = fmaxf(rmax, __shfl_xor_sync(0xffffffffu, rmax, 2));
            rmax = fmaxf(rmax, __shfl_xor_sync(0xffffffffu, rmax, 4));
            rmax = fmaxf(rmax, __shfl_xor_sync(0xffffffffu, rmax, 8));
            float mold = S.m_s[rl];
            float mnew = fmaxf(mold, rmax);
            float alpha = __expf(mold - mnew);
            float lsum = 0.f;
#pragma unroll
            for (int j = 0; j < 4; ++j) {
                float p = __expf(sc[i][j] - mnew);
                sc[i][j] = p;
                lsum += p;
            }
            lsum += __shfl_xor_sync(0xffffffffu, lsum, 1);
            lsum += __shfl_xor_sync(0xffffffffu, lsum, 2);
            lsum += __shfl_xor_sync(0xffffffffu, lsum, 4);
            lsum += __shfl_xor_sync(0xffffffffu, lsum, 8);
            if (sx == 0) {
                S.m_s[rl] = mnew;
                S.l_s[rl] = S.l_s[rl] * alpha + lsum;
            }
#pragma unroll
            for (int j = 0; j < 4; ++j) acc[i][j] *= alpha;
            *(float4*)&S.Ps[rl][4 * sx] = make_float4(sc[i][0], sc[i][1], sc[i][2], sc[i][3]);
        }
        __syncthreads();

        if (mt + 1 < ntiles) { pf_G(S, gsh, bh, r0, m0 + 64, tid); cp_commit(); }

#pragma unroll
        for (int m4 = 0; m4 < 16; ++m4) {
            float4 pv[4], vv[4];
#pragma unroll
            for (int i = 0; i < 4; ++i)
                pv[i] = *(const float4*)&S.Ps[4 * sy + i][m4 * 4];
#pragma unroll
            for (int k = 0; k < 4; ++k) {
                int mm = m4 * 4 + k;
                vv[k] = *(const float4*)&S.Vs[mm][((sx + mm) & 15) * 4];
            }
#pragma unroll
            for (int i = 0; i < 4; ++i) {
                float pa[4] = {pv[i].x, pv[i].y, pv[i].z, pv[i].w};
#pragma unroll
                for (int k = 0; k < 4; ++k) {
                    acc[i][0] += pa[k] * vv[k].x;
                    acc[i][1] += pa[k] * vv[k].y;
                    acc[i][2] += pa[k] * vv[k].z;
                    acc[i][3] += pa[k] * vv[k].w;
                }
            }
        }
        __syncthreads();

        if (mt + 1 < ntiles) { pf_V(S, kv, b, h, m0 + 64, tid); cp_commit(); }
    }

#pragma unroll
    for (int i = 0; i < 4; ++i) {
        int rl = 4 * sy + i;
        float inv = 1.f / S.l_s[rl];
        size_t o = ((size_t)(b * TLEN + r0 + rl)) * DMODEL + h * DHEAD + 4 * sx;
        *(float4*)&out[o] = make_float4(acc[i][0] * inv, acc[i][1] * inv,
                                        acc[i][2] * inv, acc[i][3] * inv);
    }
}

// ---------------------------------------------------------------------------
extern "C" void kernel_launch(void* const* d_in, const int* in_sizes, int n_in,
                              void* d_out, int out_size) {
    const float* x    = (const float*)d_in[0];
    const float* mem  = (const float*)d_in[1];
    const float* wq   = (const float*)d_in[2];
    const float* wkv  = (const float*)d_in[3];
    const float* wo   = (const float*)d_in[4];
    const float* bo   = (const float*)d_in[5];
    const float* relw = (const float*)d_in[6];

    float* out_main = (float*)d_out;
    float* mem_next = out_main + (size_t)BATCH * TLEN * DMODEL;

    float *q, *kv, *attn, *gsh;
    __nv_bfloat16 *x2, *kvin2, *a2, *wq2, *wkv2, *wo2, *q2, *rel2;
    cudaGetSymbolAddress((void**)&q,     g_q);
    cudaGetSymbolAddress((void**)&kv,    g_kv);
    cudaGetSymbolAddress((void**)&attn,  g_attn);
    cudaGetSymbolAddress((void**)&gsh,   g_gsh);
    cudaGetSymbolAddress((void**)&x2,    g_x2);
    cudaGetSymbolAddress((void**)&kvin2, g_kvin2);
    cudaGetSymbolAddress((void**)&a2,    g_a2);
    cudaGetSymbolAddress((void**)&wq2,   g_wq2);
    cudaGetSymbolAddress((void**)&wkv2,  g_wkv2);
    cudaGetSymbolAddress((void**)&wo2,   g_wo2);
    cudaGetSymbolAddress((void**)&q2,    g_q2);
    cudaGetSymbolAddress((void**)&rel2,  g_rel2);

    const int TG_SMEM = 2 * STG_BYTES + 16 * 128 * 4;   // 49408
    const int GS_SMEM = 128 * 132 * 4;                  // 67584
    cudaFuncSetAttribute(tgemm_wmma,   cudaFuncAttributeMaxDynamicSharedMemorySize, TG_SMEM);
    cudaFuncSetAttribute(tgshift_wmma, cudaFuncAttributeMaxDynamicSharedMemorySize, GS_SMEM);
    cudaFuncSetAttribute(attn_kernel,  cudaFuncAttributeMaxDynamicSharedMemorySize, (int)sizeof(AttnSmem3));

    // operand prep
    {
        size_t tot = (size_t)BATCH * TLEN * 256;
        split3_rows<<<(unsigned)((tot + 255) / 256), 256>>>(x, x2, tot);
    }
    {
        size_t tot = (size_t)BATCH * JDIM * 256;
        build_kvin_split3<<<(unsigned)((tot + 255) / 256), 256>>>(x, mem, kvin2);
    }
    transpose_split3<<<dim3(DMODEL / 32, DMODEL / 32), dim3(32, 8)>>>(wq, wq2, DMODEL);
    transpose_split3<<<dim3(2 * DMODEL / 32, DMODEL / 32), dim3(32, 8)>>>(wkv, wkv2, 2 * DMODEL);
    transpose_split3<<<dim3(DMODEL / 32, DMODEL / 32), dim3(32, 8)>>>(wo, wo2, DMODEL);
    {
        size_t tot = (size_t)JDIM * NHEAD * 16;
        build_rel2k<<<(unsigned)((tot + 255) / 256), 256>>>(relw, rel2);
    }

    // q = x @ wq
    tgemm_wmma<<<dim3(DMODEL / 128, BATCH * TLEN / 128), 256, TG_SMEM>>>(
        x2, wq2, nullptr, q, BATCH * TLEN, DMODEL, KP3);
    {
        size_t tot = (size_t)BATCH * TLEN * NHEAD * 16;
        build_q2k<<<(unsigned)((tot + 255) / 256), 256>>>(q, q2);
    }
    // kv = kvin @ wkv
    tgemm_wmma<<<dim3(2 * DMODEL / 128, BATCH * JDIM / 128), 256, TG_SMEM>>>(
        kvin2, wkv2, nullptr, kv, BATCH * JDIM, 2 * DMODEL, KP3);
    // shifted rel table
    tgshift_wmma<<<dim3(JDIM / 128, TLEN / 128, BATCH * NHEAD), 256, GS_SMEM>>>(q2, rel2, gsh);
    // fused flash attention
    attn_kernel<<<dim3(TLEN / 64, NHEAD, BATCH), 256, (int)sizeof(AttnSmem3)>>>(q, kv, gsh, attn);
    // out = attn @ wo + bo
    {
        size_t tot = (size_t)BATCH * TLEN * 256;
        split3_rows<<<(unsigned)((tot + 255) / 256), 256>>>(attn, a2, tot);
    }
    tgemm_wmma<<<dim3(DMODEL / 128, BATCH * TLEN / 128), 256, TG_SMEM>>>(
        a2, wo2, bo, out_main, BATCH * TLEN, DMODEL, KP3);
    // mem_next = x
    {
        size_t n4 = (size_t)BATCH * TLEN * DMODEL / 4;
        copy_x<<<(unsigned)((n4 + 255) / 256), 256>>>(x, mem_next);
    }
}

// round 7
// speedup vs baseline: 3.1867x; 1.4400x over previous
#include <cuda_runtime.h>
#include <cuda_bf16.h>
#include <mma.h>
#include <cstddef>
#include <cstdint>

using namespace nvcuda;

#define BATCH   4
#define TLEN    1024
#define MEMLEN  1024
#define JDIM    2048
#define DMODEL  1024
#define NHEAD   16
#define DHEAD   64
#define KP3     3072      // 3 * DMODEL (compensated K)
#define KG3     192       // 3 * DHEAD

// -------- scratch (static __device__ globals; cudaMalloc is forbidden) ------
__device__ float g_q   [(size_t)BATCH * TLEN * DMODEL];          // 16 MB
__device__ float g_kv  [(size_t)BATCH * JDIM * 2 * DMODEL];      // 64 MB
__device__ float g_attn[(size_t)BATCH * TLEN * DMODEL];          // 16 MB
__device__ float g_gsh [(size_t)BATCH * NHEAD * TLEN * JDIM];    // 512 MB

// bf16 K-concatenated operands (projection GEMMs)
__device__ __nv_bfloat16 g_x2   [(size_t)BATCH * TLEN * KP3];    // [h|l|h]
__device__ __nv_bfloat16 g_kvin2[(size_t)BATCH * JDIM * KP3];    // [h|l|h]
__device__ __nv_bfloat16 g_a2   [(size_t)BATCH * TLEN * KP3];    // [h|l|h]
__device__ __nv_bfloat16 g_wq2  [(size_t)DMODEL * KP3];          // [h|h|l] (transposed)
__device__ __nv_bfloat16 g_wkv2 [(size_t)2 * DMODEL * KP3];      // [h|h|l]
__device__ __nv_bfloat16 g_wo2  [(size_t)DMODEL * KP3];          // [h|h|l]
__device__ __nv_bfloat16 g_q2   [(size_t)BATCH * NHEAD * TLEN * KG3];  // [h|l|h]
__device__ __nv_bfloat16 g_rel2 [(size_t)NHEAD * JDIM * KG3];          // [h|h|l]

// per-head hi/lo K and V for wmma attention: [bh][m][128] = [h(64) | l(64)]
__device__ __nv_bfloat16 g_khl  [(size_t)BATCH * NHEAD * JDIM * 128];
__device__ __nv_bfloat16 g_vhl  [(size_t)BATCH * NHEAD * JDIM * 128];

// ---------------------------------------------------------------------------
__device__ __forceinline__ uint32_t smem_u32(const void* p) {
    uint32_t a;
    asm("{ .reg .u64 t; cvta.to.shared.u64 t, %1; cvt.u32.u64 %0, t; }" : "=r"(a) : "l"(p));
    return a;
}
__device__ __forceinline__ void cpasync16s(uint32_t saddr, const void* gsrc) {
    asm volatile("cp.async.cg.shared.global [%0], [%1], 16;\n" :: "r"(saddr), "l"(gsrc));
}
__device__ __forceinline__ void cpasync16(void* smem_dst, const void* gsrc) {
    cpasync16s((uint32_t)__cvta_generic_to_shared(smem_dst), gsrc);
}
__device__ __forceinline__ void cp_commit() { asm volatile("cp.async.commit_group;\n"); }
__device__ __forceinline__ void cp_wait0()  { asm volatile("cp.async.wait_group 0;\n"); }

__device__ __forceinline__ void split1(float v, __nv_bfloat16& h, __nv_bfloat16& l) {
    h = __float2bfloat16(v);
    l = __float2bfloat16(v - __bfloat162float(h));
}

// ---------------------------------------------------------------------------
// prep kernels
// ---------------------------------------------------------------------------
__global__ void split3_rows(const float* __restrict__ in, __nv_bfloat16* __restrict__ out,
                            size_t total /* R*256 */) {
    size_t i = (size_t)blockIdx.x * blockDim.x + threadIdx.x;
    if (i >= total) return;
    size_t r = i >> 8;
    int c4 = (int)(i & 255) * 4;
    float4 v = *(const float4*)&in[r * DMODEL + c4];
    __nv_bfloat16 h[4], l[4];
    split1(v.x, h[0], l[0]); split1(v.y, h[1], l[1]);
    split1(v.z, h[2], l[2]); split1(v.w, h[3], l[3]);
    __nv_bfloat16* o = out + r * KP3;
    __nv_bfloat162 hp0 = __halves2bfloat162(h[0], h[1]), hp1 = __halves2bfloat162(h[2], h[3]);
    __nv_bfloat162 lp0 = __halves2bfloat162(l[0], l[1]), lp1 = __halves2bfloat162(l[2], l[3]);
    *(__nv_bfloat162*)(o + c4)              = hp0; *(__nv_bfloat162*)(o + c4 + 2)              = hp1;
    *(__nv_bfloat162*)(o + DMODEL + c4)     = lp0; *(__nv_bfloat162*)(o + DMODEL + c4 + 2)     = lp1;
    *(__nv_bfloat162*)(o + 2 * DMODEL + c4) = hp0; *(__nv_bfloat162*)(o + 2 * DMODEL + c4 + 2) = hp1;
}

__global__ void build_kvin_split3(const float* __restrict__ x, const float* __restrict__ mem,
                                  __nv_bfloat16* __restrict__ out) {
    size_t i = (size_t)blockIdx.x * blockDim.x + threadIdx.x;
    const size_t total = (size_t)BATCH * JDIM * 256;
    if (i >= total) return;
    size_t r = i >> 8;
    int c4 = (int)(i & 255) * 4;
    size_t b = r / JDIM, m = r % JDIM;
    float4 v;
    if (m < MEMLEN) v = *(const float4*)&mem[(b * MEMLEN + m) * DMODEL + c4];
    else            v = *(const float4*)&x  [(b * TLEN + (m - MEMLEN)) * DMODEL + c4];
    __nv_bfloat16 h[4], l[4];
    split1(v.x, h[0], l[0]); split1(v.y, h[1], l[1]);
    split1(v.z, h[2], l[2]); split1(v.w, h[3], l[3]);
    __nv_bfloat16* o = out + r * KP3;
    __nv_bfloat162 hp0 = __halves2bfloat162(h[0], h[1]), hp1 = __halves2bfloat162(h[2], h[3]);
    __nv_bfloat162 lp0 = __halves2bfloat162(l[0], l[1]), lp1 = __halves2bfloat162(l[2], l[3]);
    *(__nv_bfloat162*)(o + c4)              = hp0; *(__nv_bfloat162*)(o + c4 + 2)              = hp1;
    *(__nv_bfloat162*)(o + DMODEL + c4)     = lp0; *(__nv_bfloat162*)(o + DMODEL + c4 + 2)     = lp1;
    *(__nv_bfloat162*)(o + 2 * DMODEL + c4) = hp0; *(__nv_bfloat162*)(o + 2 * DMODEL + c4 + 2) = hp1;
}

__global__ void transpose_split3(const float* __restrict__ W, __nv_bfloat16* __restrict__ T2, int N) {
    __shared__ float t[32][33];
    int k0 = blockIdx.y * 32, n0 = blockIdx.x * 32;
    int tx = threadIdx.x, ty = threadIdx.y;
#pragma unroll
    for (int i = 0; i < 32; i += 8)
        t[ty + i][tx] = W[(size_t)(k0 + ty + i) * N + n0 + tx];
    __syncthreads();
#pragma unroll
    for (int i = 0; i < 32; i += 8) {
        float v = t[tx][ty + i];
        int n = n0 + ty + i, k = k0 + tx;
        __nv_bfloat16 h, l;
        split1(v, h, l);
        __nv_bfloat16* o = T2 + (size_t)n * KP3;
        o[k] = h; o[DMODEL + k] = h; o[2 * DMODEL + k] = l;
    }
}

__global__ void build_q2k(const float* __restrict__ q, __nv_bfloat16* __restrict__ q2) {
    size_t i = (size_t)blockIdx.x * blockDim.x + threadIdx.x;
    const size_t total = (size_t)BATCH * TLEN * NHEAD * 16;
    if (i >= total) return;
    int c4 = (int)(i & 15) * 4;
    int h  = (int)(i >> 4) & 15;
    int t  = (int)(i >> 8) & 1023;
    int b  = (int)(i >> 18);
    float4 v = *(const float4*)&q[((size_t)(b * TLEN + t)) * DMODEL + h * DHEAD + c4];
    __nv_bfloat16 hh[4], ll[4];
    split1(v.x, hh[0], ll[0]); split1(v.y, hh[1], ll[1]);
    split1(v.z, hh[2], ll[2]); split1(v.w, hh[3], ll[3]);
    __nv_bfloat16* o = q2 + ((size_t)(b * NHEAD + h) * TLEN + t) * KG3;
    __nv_bfloat162 hp0 = __halves2bfloat162(hh[0], hh[1]), hp1 = __halves2bfloat162(hh[2], hh[3]);
    __nv_bfloat162 lp0 = __halves2bfloat162(ll[0], ll[1]), lp1 = __halves2bfloat162(ll[2], ll[3]);
    *(__nv_bfloat162*)(o + c4)            = hp0; *(__nv_bfloat162*)(o + c4 + 2)            = hp1;
    *(__nv_bfloat162*)(o + DHEAD + c4)    = lp0; *(__nv_bfloat162*)(o + DHEAD + c4 + 2)    = lp1;
    *(__nv_bfloat162*)(o + 2*DHEAD + c4)  = hp0; *(__nv_bfloat162*)(o + 2*DHEAD + c4 + 2)  = hp1;
}

__global__ void build_rel2k(const float* __restrict__ rel, __nv_bfloat16* __restrict__ rel2) {
    size_t i = (size_t)blockIdx.x * blockDim.x + threadIdx.x;
    const size_t total = (size_t)JDIM * NHEAD * 16;
    if (i >= total) return;
    int c4 = (int)(i & 15) * 4;
    int h  = (int)(i >> 4) & 15;
    int u  = (int)(i >> 8);
    float4 v = *(const float4*)&rel[((size_t)u * NHEAD + h) * DHEAD + c4];
    __nv_bfloat16 hh[4], ll[4];
    split1(v.x, hh[0], ll[0]); split1(v.y, hh[1], ll[1]);
    split1(v.z, hh[2], ll[2]); split1(v.w, hh[3], ll[3]);
    __nv_bfloat16* o = rel2 + ((size_t)h * JDIM + u) * KG3;
    __nv_bfloat162 hp0 = __halves2bfloat162(hh[0], hh[1]), hp1 = __halves2bfloat162(hh[2], hh[3]);
    __nv_bfloat162 lp0 = __halves2bfloat162(ll[0], ll[1]), lp1 = __halves2bfloat162(ll[2], ll[3]);
    *(__nv_bfloat162*)(o + c4)           = hp0; *(__nv_bfloat162*)(o + c4 + 2)           = hp1;
    *(__nv_bfloat162*)(o + DHEAD + c4)   = hp0; *(__nv_bfloat162*)(o + DHEAD + c4 + 2)   = hp1;
    *(__nv_bfloat162*)(o + 2*DHEAD + c4) = lp0; *(__nv_bfloat162*)(o + 2*DHEAD + c4 + 2) = lp1;
}

// kv fp32 -> per-head hi/lo K,V bf16 [bh][m][128] = [h|l]
__global__ void build_khl_vhl(const float* __restrict__ kv,
                              __nv_bfloat16* __restrict__ khl, __nv_bfloat16* __restrict__ vhl) {
    size_t i = (size_t)blockIdx.x * blockDim.x + threadIdx.x;
    const size_t total = (size_t)BATCH * JDIM * NHEAD * 16;
    if (i >= total) return;
    int c4 = (int)(i & 15) * 4;
    int h  = (int)(i >> 4) & 15;
    int m  = (int)(i >> 8) & 2047;
    int b  = (int)(i >> 19);
    const float* base = &kv[((size_t)(b * JDIM + m)) * (2 * DMODEL)];
    float4 kvv = *(const float4*)&base[h * DHEAD + c4];
    float4 vvv = *(const float4*)&base[DMODEL + h * DHEAD + c4];
    size_t orow = ((size_t)(b * NHEAD + h) * JDIM + m) * 128;
    __nv_bfloat16 hh[4], ll[4];
    split1(kvv.x, hh[0], ll[0]); split1(kvv.y, hh[1], ll[1]);
    split1(kvv.z, hh[2], ll[2]); split1(kvv.w, hh[3], ll[3]);
    *(__nv_bfloat162*)(khl + orow + c4)      = __halves2bfloat162(hh[0], hh[1]);
    *(__nv_bfloat162*)(khl + orow + c4 + 2)  = __halves2bfloat162(hh[2], hh[3]);
    *(__nv_bfloat162*)(khl + orow + 64 + c4)     = __halves2bfloat162(ll[0], ll[1]);
    *(__nv_bfloat162*)(khl + orow + 64 + c4 + 2) = __halves2bfloat162(ll[2], ll[3]);
    split1(vvv.x, hh[0], ll[0]); split1(vvv.y, hh[1], ll[1]);
    split1(vvv.z, hh[2], ll[2]); split1(vvv.w, hh[3], ll[3]);
    *(__nv_bfloat162*)(vhl + orow + c4)      = __halves2bfloat162(hh[0], hh[1]);
    *(__nv_bfloat162*)(vhl + orow + c4 + 2)  = __halves2bfloat162(hh[2], hh[3]);
    *(__nv_bfloat162*)(vhl + orow + 64 + c4)     = __halves2bfloat162(ll[0], ll[1]);
    *(__nv_bfloat162*)(vhl + orow + 64 + c4 + 2) = __halves2bfloat162(ll[2], ll[3]);
}

__global__ void copy_x(const float* __restrict__ x, float* __restrict__ dst) {
    size_t i = (size_t)blockIdx.x * blockDim.x + threadIdx.x;
    const size_t total = (size_t)BATCH * TLEN * DMODEL / 4;
    if (i < total) ((float4*)dst)[i] = ((const float4*)x)[i];
}

// ---------------------------------------------------------------------------
// wmma bf16 GEMM (projections) — unchanged from round 6
// ---------------------------------------------------------------------------
#define STG_BYTES 20480
#define LDS_ROW   40

__global__ __launch_bounds__(256)
void tgemm_wmma(const __nv_bfloat16* __restrict__ A, const __nv_bfloat16* __restrict__ B,
                const float* __restrict__ bias, float* __restrict__ C,
                int M, int N, int Kp) {
    extern __shared__ char sm[];
    const uint32_t sbase = smem_u32(sm);
    float* biasS = (float*)(sm + 2 * STG_BYTES);

    const int tid = threadIdx.x;
    const int wid = tid >> 5;
    const int wm = wid >> 2;
    const int wn = wid & 3;
    const int row0 = blockIdx.y * 128;
    const int col0 = blockIdx.x * 128;

    for (int i = tid; i < 16 * 128; i += 256)
        biasS[i] = bias ? bias[col0 + (i & 127)] : 0.f;

    auto loadStage = [&](int s, int k0) {
        uint32_t ab = sbase + s * STG_BYTES;
        uint32_t bb = ab + STG_BYTES / 2;
#pragma unroll
        for (int p = 0; p < 2; ++p) {
            int i = tid + p * 256;
            int r = i >> 2, qq = i & 3;
            cpasync16s(ab + r * 80 + qq * 16,
                       (const char*)A + (((size_t)(row0 + r)) * Kp + k0 + qq * 8) * 2);
            cpasync16s(bb + r * 80 + qq * 16,
                       (const char*)B + (((size_t)(col0 + r)) * Kp + k0 + qq * 8) * 2);
        }
    };

    wmma::fragment<wmma::accumulator, 16, 16, 16, float> acc[4][2];
    __syncthreads();
#pragma unroll
    for (int i = 0; i < 4; ++i)
#pragma unroll
        for (int j = 0; j < 2; ++j)
            wmma::load_matrix_sync(acc[i][j], &biasS[wn * 32 + j * 16], 128, wmma::mem_row_major);

    loadStage(0, 0);
    cp_commit();

    const int nst = Kp / 32;
    for (int st = 0; st < nst; ++st) {
        cp_wait0();
        __syncthreads();
        if (st + 1 < nst) { loadStage((st + 1) & 1, (st + 1) * 32); cp_commit(); }

        const __nv_bfloat16* as = (const __nv_bfloat16*)(sm + (st & 1) * STG_BYTES);
        const __nv_bfloat16* bs = as + STG_BYTES / 4;

#pragma unroll
        for (int kk = 0; kk < 2; ++kk) {
            wmma::fragment<wmma::matrix_a, 16, 16, 16, __nv_bfloat16, wmma::row_major> af[4];
            wmma::fragment<wmma::matrix_b, 16, 16, 16, __nv_bfloat16, wmma::col_major> bfr[2];
#pragma unroll
            for (int i = 0; i < 4; ++i)
                wmma::load_matrix_sync(af[i], as + (wm * 64 + i * 16) * LDS_ROW + kk * 16, LDS_ROW);
#pragma unroll
            for (int j = 0; j < 2; ++j)
                wmma::load_matrix_sync(bfr[j], bs + (wn * 32 + j * 16) * LDS_ROW + kk * 16, LDS_ROW);
#pragma unroll
            for (int i = 0; i < 4; ++i)
#pragma unroll
                for (int j = 0; j < 2; ++j)
                    wmma::mma_sync(acc[i][j], af[i], bfr[j], acc[i][j]);
        }
    }

#pragma unroll
    for (int i = 0; i < 4; ++i)
#pragma unroll
        for (int j = 0; j < 2; ++j)
            wmma::store_matrix_sync(&C[(size_t)(row0 + wm * 64 + i * 16) * N + col0 + wn * 32 + j * 16],
                                    acc[i][j], N, wmma::mem_row_major);
}

// ---------------------------------------------------------------------------
// wmma gshift — unchanged from round 6
// ---------------------------------------------------------------------------
__global__ __launch_bounds__(256)
void tgshift_wmma(const __nv_bfloat16* __restrict__ q2, const __nv_bfloat16* __restrict__ rel2,
                  float* __restrict__ gsh) {
    const int z  = blockIdx.z;
    const int r0 = blockIdx.y * 128;
    const int u0 = blockIdx.x * 128;
    if (u0 + r0 < 769) return;

    extern __shared__ char sm[];
    const uint32_t sbase = smem_u32(sm);
    const int tid = threadIdx.x;
    const int wid = tid >> 5;
    const int wm = wid >> 2, wn = wid & 3;

    const __nv_bfloat16* A = q2  + (size_t)z * TLEN * KG3;
    const __nv_bfloat16* B = rel2 + (size_t)(z & 15) * JDIM * KG3;

    auto loadStage = [&](int s, int k0) {
        uint32_t ab = sbase + s * STG_BYTES;
        uint32_t bb = ab + STG_BYTES / 2;
#pragma unroll
        for (int p = 0; p < 2; ++p) {
            int i = tid + p * 256;
            int r = i >> 2, qq = i & 3;
            cpasync16s(ab + r * 80 + qq * 16,
                       (const char*)A + (((size_t)(r0 + r)) * KG3 + k0 + qq * 8) * 2);
            cpasync16s(bb + r * 80 + qq * 16,
                       (const char*)B + (((size_t)(u0 + r)) * KG3 + k0 + qq * 8) * 2);
        }
    };

    wmma::fragment<wmma::accumulator, 16, 16, 16, float> acc[4][2];
#pragma unroll
    for (int i = 0; i < 4; ++i)
#pragma unroll
        for (int j = 0; j < 2; ++j)
            wmma::fill_fragment(acc[i][j], 0.f);

    loadStage(0, 0);
    cp_commit();

    const int nst = KG3 / 32;
    for (int st = 0; st < nst; ++st) {
        cp_wait0();
        __syncthreads();
        if (st + 1 < nst) { loadStage((st + 1) & 1, (st + 1) * 32); cp_commit(); }

        const __nv_bfloat16* as = (const __nv_bfloat16*)(sm + (st & 1) * STG_BYTES);
        const __nv_bfloat16* bs = as + STG_BYTES / 4;

#pragma unroll
        for (int kk = 0; kk < 2; ++kk) {
            wmma::fragment<wmma::matrix_a, 16, 16, 16, __nv_bfloat16, wmma::row_major> af[4];
            wmma::fragment<wmma::matrix_b, 16, 16, 16, __nv_bfloat16, wmma::col_major> bfr[2];
#pragma unroll
            for (int i = 0; i < 4; ++i)
                wmma::load_matrix_sync(af[i], as + (wm * 64 + i * 16) * LDS_ROW + kk * 16, LDS_ROW);
#pragma unroll
            for (int j = 0; j < 2; ++j)
                wmma::load_matrix_sync(bfr[j], bs + (wn * 32 + j * 16) * LDS_ROW + kk * 16, LDS_ROW);
#pragma unroll
            for (int i = 0; i < 4; ++i)
#pragma unroll
                for (int j = 0; j < 2; ++j)
                    wmma::mma_sync(acc[i][j], af[i], bfr[j], acc[i][j]);
        }
    }

    __syncthreads();
    float* Cs = (float*)sm;
#pragma unroll
    for (int i = 0; i < 4; ++i)
#pragma unroll
        for (int j = 0; j < 2; ++j)
            wmma::store_matrix_sync(&Cs[(size_t)(wm * 64 + i * 16) * 132 + wn * 32 + j * 16],
                                    acc[i][j], 132, wmma::mem_row_major);
    __syncthreads();

    for (int idx = tid; idx < 128 * 128; idx += 256) {
        int r = idx >> 7, u = idx & 127;
        int jc = (u0 + u) - 1023 + (r0 + r);
        if ((unsigned)jc < (unsigned)JDIM)
            gsh[((size_t)z * TLEN + r0 + r) * JDIM + jc] = 0.125f * Cs[r * 132 + u];
    }
}

// ---------------------------------------------------------------------------
// wmma flash attention with hi/lo compensation.
// Block = (64 q-rows, head, batch).  Per 64-col tile:
//   S = Qh Kh^T + Ql Kh^T + Qh Kl^T   (wmma, 3 passes, K=64 each)
//   softmax SIMT on smem S (scale+G+mask), P split to bf16 hi/lo
//   O_tile = Ph Vh + Pl Vh + Ph Vl    (wmma), merged into SIMT fp32 acc
// ---------------------------------------------------------------------------
struct __align__(16) AttnW {
    __nv_bfloat16 Q2s[64][136];       // cols: [Qh(64) | Ql(64)]
    __nv_bfloat16 Khl[2][64][136];    // cols: [Kh | Kl]
    __nv_bfloat16 Vhl[2][64][136];    // cols: [Vh | Vl]
    float         Gs[2][64][68];
    float         SP[64][72];         // scores, then PV result
    __nv_bfloat16 Phl[64][136];       // cols: [Ph | Pl]
    float m_s[64];
    float l_s[64];
};

__device__ __forceinline__ void aw_pf(AttnW& S, int bb,
                                      const __nv_bfloat16* __restrict__ khl,
                                      const __nv_bfloat16* __restrict__ vhl,
                                      const float* __restrict__ gsh,
                                      size_t bh, int r0, int m0, int tid) {
    // K, V: 64 rows x 256B each
#pragma unroll
    for (int p = 0; p < 4; ++p) {
        int i = tid + p * 256;
        int r = i >> 4, c = i & 15;
        const size_t grow = (bh * JDIM + (size_t)(m0 + r)) * 128;
        cpasync16(&S.Khl[bb][r][c * 8], khl + grow + c * 8);
    }
#pragma unroll
    for (int p = 0; p < 4; ++p) {
        int i = tid + p * 256;
        int r = i >> 4, c = i & 15;
        const size_t grow = (bh * JDIM + (size_t)(m0 + r)) * 128;
        cpasync16(&S.Vhl[bb][r][c * 8], vhl + grow + c * 8);
    }
    // G: 64 rows x 256B fp32
#pragma unroll
    for (int p = 0; p < 4; ++p) {
        int i = tid + p * 256;
        int r = i >> 4, c = i & 15;
        cpasync16(&S.Gs[bb][r][c * 4],
                  gsh + (bh * TLEN + (size_t)(r0 + r)) * JDIM + m0 + c * 4);
    }
}

__global__ __launch_bounds__(256, 1)
void attn_wmma(const __nv_bfloat16* __restrict__ q2,
               const __nv_bfloat16* __restrict__ khl,
               const __nv_bfloat16* __restrict__ vhl,
               const float* __restrict__ gsh, float* __restrict__ out) {
    extern __shared__ char smem_raw[];
    AttnW& S = *reinterpret_cast<AttnW*>(smem_raw);

    const int b  = blockIdx.z;
    const int h  = blockIdx.y;
    const int rb = blockIdx.x;
    const int r0 = rb * 64;
    const size_t bh = (size_t)(b * NHEAD + h);
    const int tid = threadIdx.x;
    const int wid = tid >> 5;
    const int wm = wid >> 2;     // 0..1 (row half)
    const int wn = wid & 3;      // 0..3 (col quarter)
    const int sy = tid >> 4;     // 0..15
    const int sx = tid & 15;     // 0..15

    // Q tile: copy cols [0,128) of q2 rows (Qh|Ql)
#pragma unroll
    for (int p = 0; p < 4; ++p) {
        int i = tid + p * 256;
        int r = i >> 4, c = i & 15;
        cpasync16(&S.Q2s[r][c * 8],
                  q2 + (bh * TLEN + (size_t)(r0 + r)) * KG3 + c * 8);
    }
    aw_pf(S, 0, khl, vhl, gsh, bh, r0, 0, tid);
    cp_commit();

    if (tid < 64) { S.m_s[tid] = -1e30f; S.l_s[tid] = 0.f; }

    float acc[4][4];
#pragma unroll
    for (int i = 0; i < 4; ++i)
#pragma unroll
        for (int j = 0; j < 4; ++j) acc[i][j] = 0.f;

    const int ntiles = min(32, rb + 17);

    for (int mt = 0; mt < ntiles; ++mt) {
        const int cur = mt & 1;
        const int m0  = mt * 64;

        cp_wait0();
        __syncthreads();                    // tile data ready; SP merge reads done

        if (mt + 1 < ntiles) { aw_pf(S, cur ^ 1, khl, vhl, gsh, bh, r0, m0 + 64, tid); cp_commit(); }

        // ---- scores: 3 compensated wmma passes ----
        {
            wmma::fragment<wmma::accumulator, 16, 16, 16, float> sacc[2];
#pragma unroll
            for (int i = 0; i < 2; ++i) wmma::fill_fragment(sacc[i], 0.f);
#pragma unroll
            for (int pass = 0; pass < 3; ++pass) {
                const int aoff = (pass == 1) ? 64 : 0;
                const int boff = (pass == 2) ? 64 : 0;
#pragma unroll
                for (int k16 = 0; k16 < 4; ++k16) {
                    wmma::fragment<wmma::matrix_a, 16, 16, 16, __nv_bfloat16, wmma::row_major> af[2];
                    wmma::fragment<wmma::matrix_b, 16, 16, 16, __nv_bfloat16, wmma::col_major> bfr;
#pragma unroll
                    for (int i = 0; i < 2; ++i)
                        wmma::load_matrix_sync(af[i], &S.Q2s[wm * 32 + i * 16][aoff + k16 * 16], 136);
                    wmma::load_matrix_sync(bfr, &S.Khl[cur][wn * 16][boff + k16 * 16], 136);
#pragma unroll
                    for (int i = 0; i < 2; ++i)
                        wmma::mma_sync(sacc[i], af[i], bfr, sacc[i]);
                }
            }
#pragma unroll
            for (int i = 0; i < 2; ++i)
                wmma::store_matrix_sync(&S.SP[wm * 32 + i * 16][wn * 16], sacc[i], 72,
                                        wmma::mem_row_major);
        }
        __syncthreads();                    // SP visible

        // ---- softmax (SIMT), P -> bf16 hi/lo ----
#pragma unroll
        for (int i = 0; i < 4; ++i) {
            const int rl = 4 * sy + i;
            const int mlim = r0 + rl + MEMLEN - m0;
            float4 sv = *(const float4*)&S.SP[rl][4 * sx];
            float4 gv = *(const float4*)&S.Gs[cur][rl][4 * sx];
            float sc[4] = {sv.x * 0.125f + gv.x, sv.y * 0.125f + gv.y,
                           sv.z * 0.125f + gv.z, sv.w * 0.125f + gv.w};
#pragma unroll
            for (int j = 0; j < 4; ++j)
                if (4 * sx + j > mlim) sc[j] = -1e30f;

            float rmax = fmaxf(fmaxf(sc[0], sc[1]), fmaxf(sc[2], sc[3]));
            rmax = fmaxf(rmax, __shfl_xor_sync(0xffffffffu, rmax, 1));
            rmax = fmaxf(rmax, __shfl_xor_sync(0xffffffffu, rmax, 2));
            rmax = fmaxf(rmax, __shfl_xor_sync(0xffffffffu, rmax, 4));
            rmax = fmaxf(rmax, __shfl_xor_sync(0xffffffffu, rmax, 8));
            float mold = S.m_s[rl];
            float mnew = fmaxf(mold, rmax);
            float alpha = __expf(mold - mnew);
            float lsum = 0.f;
            __nv_bfloat16 ph[4], pl[4];
#pragma unroll
            for (int j = 0; j < 4; ++j) {
                float p = __expf(sc[j] - mnew);
                lsum += p;
                ph[j] = __float2bfloat16(p);
                pl[j] = __float2bfloat16(p - __bfloat162float(ph[j]));
            }
            lsum += __shfl_xor_sync(0xffffffffu, lsum, 1);
            lsum += __shfl_xor_sync(0xffffffffu, lsum, 2);
            lsum += __shfl_xor_sync(0xffffffffu, lsum, 4);
            lsum += __shfl_xor_sync(0xffffffffu, lsum, 8);
            if (sx == 0) {
                S.m_s[rl] = mnew;
                S.l_s[rl] = S.l_s[rl] * alpha + lsum;
            }
            *(__nv_bfloat162*)&S.Phl[rl][4 * sx]          = __halves2bfloat162(ph[0], ph[1]);
            *(__nv_bfloat162*)&S.Phl[rl][4 * sx + 2]      = __halves2bfloat162(ph[2], ph[3]);
            *(__nv_bfloat162*)&S.Phl[rl][64 + 4 * sx]     = __halves2bfloat162(pl[0], pl[1]);
            *(__nv_bfloat162*)&S.Phl[rl][64 + 4 * sx + 2] = __halves2bfloat162(pl[2], pl[3]);
#pragma unroll
            for (int j = 0; j < 4; ++j) acc[i][j] *= alpha;
        }
        __syncthreads();                    // Phl visible; SP free

        // ---- PV: 3 compensated wmma passes -> SP ----
        {
            wmma::fragment<wmma::accumulator, 16, 16, 16, float> oacc[2];
#pragma unroll
            for (int i = 0; i < 2; ++i) wmma::fill_fragment(oacc[i], 0.f);
#pragma unroll
            for (int pass = 0; pass < 3; ++pass) {
                const int aoff = (pass == 1) ? 64 : 0;
                const int boff = (pass == 2) ? 64 : 0;
#pragma unroll
                for (int k16 = 0; k16 < 4; ++k16) {
                    wmma::fragment<wmma::matrix_a, 16, 16, 16, __nv_bfloat16, wmma::row_major> af[2];
                    wmma::fragment<wmma::matrix_b, 16, 16, 16, __nv_bfloat16, wmma::row_major> bfr;
#pragma unroll
                    for (int i = 0; i < 2; ++i)
                        wmma::load_matrix_sync(af[i], &S.Phl[wm * 32 + i * 16][aoff + k16 * 16], 136);
                    wmma::load_matrix_sync(bfr, &S.Vhl[cur][k16 * 16][boff + wn * 16], 136);
#pragma unroll
                    for (int i = 0; i < 2; ++i)
                        wmma::mma_sync(oacc[i], af[i], bfr, oacc[i]);
                }
            }
#pragma unroll
            for (int i = 0; i < 2; ++i)
                wmma::store_matrix_sync(&S.SP[wm * 32 + i * 16][wn * 16], oacc[i], 72,
                                        wmma::mem_row_major);
        }
        __syncthreads();                    // PV tile visible

        // merge into SIMT accumulator
#pragma unroll
        for (int i = 0; i < 4; ++i) {
            const int rl = 4 * sy + i;
            float4 ov = *(const float4*)&S.SP[rl][4 * sx];
            acc[i][0] += ov.x; acc[i][1] += ov.y; acc[i][2] += ov.z; acc[i][3] += ov.w;
        }
        // next loop-top __syncthreads orders these reads vs next score store
    }

    __syncthreads();
#pragma unroll
    for (int i = 0; i < 4; ++i) {
        const int rl = 4 * sy + i;
        float inv = 1.f / S.l_s[rl];
        size_t o = ((size_t)(b * TLEN + r0 + rl)) * DMODEL + h * DHEAD + 4 * sx;
        *(float4*)&out[o] = make_float4(acc[i][0] * inv, acc[i][1] * inv,
                                        acc[i][2] * inv, acc[i][3] * inv);
    }
}

// ---------------------------------------------------------------------------
extern "C" void kernel_launch(void* const* d_in, const int* in_sizes, int n_in,
                              void* d_out, int out_size) {
    const float* x    = (const float*)d_in[0];
    const float* mem  = (const float*)d_in[1];
    const float* wq   = (const float*)d_in[2];
    const float* wkv  = (const float*)d_in[3];
    const float* wo   = (const float*)d_in[4];
    const float* bo   = (const float*)d_in[5];
    const float* relw = (const float*)d_in[6];

    float* out_main = (float*)d_out;
    float* mem_next = out_main + (size_t)BATCH * TLEN * DMODEL;

    float *q, *kv, *attn, *gsh;
    __nv_bfloat16 *x2, *kvin2, *a2, *wq2, *wkv2, *wo2, *q2, *rel2, *khl, *vhl;
    cudaGetSymbolAddress((void**)&q,     g_q);
    cudaGetSymbolAddress((void**)&kv,    g_kv);
    cudaGetSymbolAddress((void**)&attn,  g_attn);
    cudaGetSymbolAddress((void**)&gsh,   g_gsh);
    cudaGetSymbolAddress((void**)&x2,    g_x2);
    cudaGetSymbolAddress((void**)&kvin2, g_kvin2);
    cudaGetSymbolAddress((void**)&a2,    g_a2);
    cudaGetSymbolAddress((void**)&wq2,   g_wq2);
    cudaGetSymbolAddress((void**)&wkv2,  g_wkv2);
    cudaGetSymbolAddress((void**)&wo2,   g_wo2);
    cudaGetSymbolAddress((void**)&q2,    g_q2);
    cudaGetSymbolAddress((void**)&rel2,  g_rel2);
    cudaGetSymbolAddress((void**)&khl,   g_khl);
    cudaGetSymbolAddress((void**)&vhl,   g_vhl);

    const int TG_SMEM = 2 * STG_BYTES + 16 * 128 * 4;
    const int GS_SMEM = 128 * 132 * 4;
    const int AW_SMEM = (int)sizeof(AttnW);
    cudaFuncSetAttribute(tgemm_wmma,   cudaFuncAttributeMaxDynamicSharedMemorySize, TG_SMEM);
    cudaFuncSetAttribute(tgshift_wmma, cudaFuncAttributeMaxDynamicSharedMemorySize, GS_SMEM);
    cudaFuncSetAttribute(attn_wmma,    cudaFuncAttributeMaxDynamicSharedMemorySize, AW_SMEM);

    // operand prep
    {
        size_t tot = (size_t)BATCH * TLEN * 256;
        split3_rows<<<(unsigned)((tot + 255) / 256), 256>>>(x, x2, tot);
    }
    {
        size_t tot = (size_t)BATCH * JDIM * 256;
        build_kvin_split3<<<(unsigned)((tot + 255) / 256), 256>>>(x, mem, kvin2);
    }
    transpose_split3<<<dim3(DMODEL / 32, DMODEL / 32), dim3(32, 8)>>>(wq, wq2, DMODEL);
    transpose_split3<<<dim3(2 * DMODEL / 32, DMODEL / 32), dim3(32, 8)>>>(wkv, wkv2, 2 * DMODEL);
    transpose_split3<<<dim3(DMODEL / 32, DMODEL / 32), dim3(32, 8)>>>(wo, wo2, DMODEL);
    {
        size_t tot = (size_t)JDIM * NHEAD * 16;
        build_rel2k<<<(unsigned)((tot + 255) / 256), 256>>>(relw, rel2);
    }

    // q = x @ wq
    tgemm_wmma<<<dim3(DMODEL / 128, BATCH * TLEN / 128), 256, TG_SMEM>>>(
        x2, wq2, nullptr, q, BATCH * TLEN, DMODEL, KP3);
    {
        size_t tot = (size_t)BATCH * TLEN * NHEAD * 16;
        build_q2k<<<(unsigned)((tot + 255) / 256), 256>>>(q, q2);
    }
    // kv = kvin @ wkv
    tgemm_wmma<<<dim3(2 * DMODEL / 128, BATCH * JDIM / 128), 256, TG_SMEM>>>(
        kvin2, wkv2, nullptr, kv, BATCH * JDIM, 2 * DMODEL, KP3);
    {
        size_t tot = (size_t)BATCH * JDIM * NHEAD * 16;
        build_khl_vhl<<<(unsigned)((tot + 255) / 256), 256>>>(kv, khl, vhl);
    }
    // shifted rel table
    tgshift_wmma<<<dim3(JDIM / 128, TLEN / 128, BATCH * NHEAD), 256, GS_SMEM>>>(q2, rel2, gsh);
    // wmma flash attention
    attn_wmma<<<dim3(TLEN / 64, NHEAD, BATCH), 256, AW_SMEM>>>(q2, khl, vhl, gsh, attn);
    // out = attn @ wo + bo
    {
        size_t tot = (size_t)BATCH * TLEN * 256;
        split3_rows<<<(unsigned)((tot + 255) / 256), 256>>>(attn, a2, tot);
    }
    tgemm_wmma<<<dim3(DMODEL / 128, BATCH * TLEN / 128), 256, TG_SMEM>>>(
        a2, wo2, bo, out_main, BATCH * TLEN, DMODEL, KP3);
    // mem_next = x
    {
        size_t n4 = (size_t)BATCH * TLEN * DMODEL / 4;
        copy_x<<<(unsigned)((n4 + 255) / 256), 256>>>(x, mem_next);
    }
}

// round 8
// speedup vs baseline: 3.3676x; 1.0568x over previous
#include <cuda_runtime.h>
#include <cuda_bf16.h>
#include <mma.h>
#include <cstddef>
#include <cstdint>

using namespace nvcuda;

#define BATCH   4
#define TLEN    1024
#define MEMLEN  1024
#define JDIM    2048
#define DMODEL  1024
#define NHEAD   16
#define DHEAD   64
#define KP3     3072      // 3 * DMODEL (compensated K)
#define KG3     192       // 3 * DHEAD

// -------- scratch (static __device__ globals; cudaMalloc is forbidden) ------
__device__ float g_q   [(size_t)BATCH * TLEN * DMODEL];          // 16 MB
__device__ float g_kv  [(size_t)BATCH * JDIM * 2 * DMODEL];      // 64 MB
__device__ float g_attn[(size_t)BATCH * TLEN * DMODEL];          // 16 MB

// bf16 K-concatenated operands (projection GEMMs)
__device__ __nv_bfloat16 g_x2   [(size_t)BATCH * TLEN * KP3];    // [h|l|h]
__device__ __nv_bfloat16 g_kvin2[(size_t)BATCH * JDIM * KP3];    // [h|l|h]
__device__ __nv_bfloat16 g_a2   [(size_t)BATCH * TLEN * KP3];    // [h|l|h]
__device__ __nv_bfloat16 g_wq2  [(size_t)DMODEL * KP3];          // [h|h|l] (transposed)
__device__ __nv_bfloat16 g_wkv2 [(size_t)2 * DMODEL * KP3];      // [h|h|l]
__device__ __nv_bfloat16 g_wo2  [(size_t)DMODEL * KP3];          // [h|h|l]
__device__ __nv_bfloat16 g_q2   [(size_t)BATCH * NHEAD * TLEN * KG3];  // [h|l|h]
__device__ __nv_bfloat16 g_rel2 [(size_t)NHEAD * JDIM * KG3];          // [h|h|l]

// per-head hi/lo K and V: [bh][m][128] = [h(64) | l(64)]
__device__ __nv_bfloat16 g_khl  [(size_t)BATCH * NHEAD * JDIM * 128];
__device__ __nv_bfloat16 g_vhl  [(size_t)BATCH * NHEAD * JDIM * 128];

// ---------------------------------------------------------------------------
__device__ __forceinline__ uint32_t smem_u32(const void* p) {
    uint32_t a;
    asm("{ .reg .u64 t; cvta.to.shared.u64 t, %1; cvt.u32.u64 %0, t; }" : "=r"(a) : "l"(p));
    return a;
}
__device__ __forceinline__ void cpasync16s(uint32_t saddr, const void* gsrc) {
    asm volatile("cp.async.cg.shared.global [%0], [%1], 16;\n" :: "r"(saddr), "l"(gsrc));
}
__device__ __forceinline__ void cpasync16(void* smem_dst, const void* gsrc) {
    cpasync16s((uint32_t)__cvta_generic_to_shared(smem_dst), gsrc);
}
__device__ __forceinline__ void cp_commit() { asm volatile("cp.async.commit_group;\n"); }
__device__ __forceinline__ void cp_wait0()  { asm volatile("cp.async.wait_group 0;\n"); }

__device__ __forceinline__ void split1(float v, __nv_bfloat16& h, __nv_bfloat16& l) {
    h = __float2bfloat16(v);
    l = __float2bfloat16(v - __bfloat162float(h));
}

// ---------------------------------------------------------------------------
// prep kernels
// ---------------------------------------------------------------------------
__global__ void split3_rows(const float* __restrict__ in, __nv_bfloat16* __restrict__ out,
                            size_t total /* R*256 */) {
    size_t i = (size_t)blockIdx.x * blockDim.x + threadIdx.x;
    if (i >= total) return;
    size_t r = i >> 8;
    int c4 = (int)(i & 255) * 4;
    float4 v = *(const float4*)&in[r * DMODEL + c4];
    __nv_bfloat16 h[4], l[4];
    split1(v.x, h[0], l[0]); split1(v.y, h[1], l[1]);
    split1(v.z, h[2], l[2]); split1(v.w, h[3], l[3]);
    __nv_bfloat16* o = out + r * KP3;
    __nv_bfloat162 hp0 = __halves2bfloat162(h[0], h[1]), hp1 = __halves2bfloat162(h[2], h[3]);
    __nv_bfloat162 lp0 = __halves2bfloat162(l[0], l[1]), lp1 = __halves2bfloat162(l[2], l[3]);
    *(__nv_bfloat162*)(o + c4)              = hp0; *(__nv_bfloat162*)(o + c4 + 2)              = hp1;
    *(__nv_bfloat162*)(o + DMODEL + c4)     = lp0; *(__nv_bfloat162*)(o + DMODEL + c4 + 2)     = lp1;
    *(__nv_bfloat162*)(o + 2 * DMODEL + c4) = hp0; *(__nv_bfloat162*)(o + 2 * DMODEL + c4 + 2) = hp1;
}

__global__ void build_kvin_split3(const float* __restrict__ x, const float* __restrict__ mem,
                                  __nv_bfloat16* __restrict__ out) {
    size_t i = (size_t)blockIdx.x * blockDim.x + threadIdx.x;
    const size_t total = (size_t)BATCH * JDIM * 256;
    if (i >= total) return;
    size_t r = i >> 8;
    int c4 = (int)(i & 255) * 4;
    size_t b = r / JDIM, m = r % JDIM;
    float4 v;
    if (m < MEMLEN) v = *(const float4*)&mem[(b * MEMLEN + m) * DMODEL + c4];
    else            v = *(const float4*)&x  [(b * TLEN + (m - MEMLEN)) * DMODEL + c4];
    __nv_bfloat16 h[4], l[4];
    split1(v.x, h[0], l[0]); split1(v.y, h[1], l[1]);
    split1(v.z, h[2], l[2]); split1(v.w, h[3], l[3]);
    __nv_bfloat16* o = out + r * KP3;
    __nv_bfloat162 hp0 = __halves2bfloat162(h[0], h[1]), hp1 = __halves2bfloat162(h[2], h[3]);
    __nv_bfloat162 lp0 = __halves2bfloat162(l[0], l[1]), lp1 = __halves2bfloat162(l[2], l[3]);
    *(__nv_bfloat162*)(o + c4)              = hp0; *(__nv_bfloat162*)(o + c4 + 2)              = hp1;
    *(__nv_bfloat162*)(o + DMODEL + c4)     = lp0; *(__nv_bfloat162*)(o + DMODEL + c4 + 2)     = lp1;
    *(__nv_bfloat162*)(o + 2 * DMODEL + c4) = hp0; *(__nv_bfloat162*)(o + 2 * DMODEL + c4 + 2) = hp1;
}

__global__ void transpose_split3(const float* __restrict__ W, __nv_bfloat16* __restrict__ T2, int N) {
    __shared__ float t[32][33];
    int k0 = blockIdx.y * 32, n0 = blockIdx.x * 32;
    int tx = threadIdx.x, ty = threadIdx.y;
#pragma unroll
    for (int i = 0; i < 32; i += 8)
        t[ty + i][tx] = W[(size_t)(k0 + ty + i) * N + n0 + tx];
    __syncthreads();
#pragma unroll
    for (int i = 0; i < 32; i += 8) {
        float v = t[tx][ty + i];
        int n = n0 + ty + i, k = k0 + tx;
        __nv_bfloat16 h, l;
        split1(v, h, l);
        __nv_bfloat16* o = T2 + (size_t)n * KP3;
        o[k] = h; o[DMODEL + k] = h; o[2 * DMODEL + k] = l;
    }
}

__global__ void build_q2k(const float* __restrict__ q, __nv_bfloat16* __restrict__ q2) {
    size_t i = (size_t)blockIdx.x * blockDim.x + threadIdx.x;
    const size_t total = (size_t)BATCH * TLEN * NHEAD * 16;
    if (i >= total) return;
    int c4 = (int)(i & 15) * 4;
    int h  = (int)(i >> 4) & 15;
    int t  = (int)(i >> 8) & 1023;
    int b  = (int)(i >> 18);
    float4 v = *(const float4*)&q[((size_t)(b * TLEN + t)) * DMODEL + h * DHEAD + c4];
    __nv_bfloat16 hh[4], ll[4];
    split1(v.x, hh[0], ll[0]); split1(v.y, hh[1], ll[1]);
    split1(v.z, hh[2], ll[2]); split1(v.w, hh[3], ll[3]);
    __nv_bfloat16* o = q2 + ((size_t)(b * NHEAD + h) * TLEN + t) * KG3;
    __nv_bfloat162 hp0 = __halves2bfloat162(hh[0], hh[1]), hp1 = __halves2bfloat162(hh[2], hh[3]);
    __nv_bfloat162 lp0 = __halves2bfloat162(ll[0], ll[1]), lp1 = __halves2bfloat162(ll[2], ll[3]);
    *(__nv_bfloat162*)(o + c4)            = hp0; *(__nv_bfloat162*)(o + c4 + 2)            = hp1;
    *(__nv_bfloat162*)(o + DHEAD + c4)    = lp0; *(__nv_bfloat162*)(o + DHEAD + c4 + 2)    = lp1;
    *(__nv_bfloat162*)(o + 2*DHEAD + c4)  = hp0; *(__nv_bfloat162*)(o + 2*DHEAD + c4 + 2)  = hp1;
}

__global__ void build_rel2k(const float* __restrict__ rel, __nv_bfloat16* __restrict__ rel2) {
    size_t i = (size_t)blockIdx.x * blockDim.x + threadIdx.x;
    const size_t total = (size_t)JDIM * NHEAD * 16;
    if (i >= total) return;
    int c4 = (int)(i & 15) * 4;
    int h  = (int)(i >> 4) & 15;
    int u  = (int)(i >> 8);
    float4 v = *(const float4*)&rel[((size_t)u * NHEAD + h) * DHEAD + c4];
    __nv_bfloat16 hh[4], ll[4];
    split1(v.x, hh[0], ll[0]); split1(v.y, hh[1], ll[1]);
    split1(v.z, hh[2], ll[2]); split1(v.w, hh[3], ll[3]);
    __nv_bfloat16* o = rel2 + ((size_t)h * JDIM + u) * KG3;
    __nv_bfloat162 hp0 = __halves2bfloat162(hh[0], hh[1]), hp1 = __halves2bfloat162(hh[2], hh[3]);
    __nv_bfloat162 lp0 = __halves2bfloat162(ll[0], ll[1]), lp1 = __halves2bfloat162(ll[2], ll[3]);
    *(__nv_bfloat162*)(o + c4)           = hp0; *(__nv_bfloat162*)(o + c4 + 2)           = hp1;
    *(__nv_bfloat162*)(o + DHEAD + c4)   = hp0; *(__nv_bfloat162*)(o + DHEAD + c4 + 2)   = hp1;
    *(__nv_bfloat162*)(o + 2*DHEAD + c4) = lp0; *(__nv_bfloat162*)(o + 2*DHEAD + c4 + 2) = lp1;
}

// kv fp32 -> per-head hi/lo K,V bf16 [bh][m][128] = [h|l]
__global__ void build_khl_vhl(const float* __restrict__ kv,
                              __nv_bfloat16* __restrict__ khl, __nv_bfloat16* __restrict__ vhl) {
    size_t i = (size_t)blockIdx.x * blockDim.x + threadIdx.x;
    const size_t total = (size_t)BATCH * JDIM * NHEAD * 16;
    if (i >= total) return;
    int c4 = (int)(i & 15) * 4;
    int h  = (int)(i >> 4) & 15;
    int m  = (int)(i >> 8) & 2047;
    int b  = (int)(i >> 19);
    const float* base = &kv[((size_t)(b * JDIM + m)) * (2 * DMODEL)];
    float4 kvv = *(const float4*)&base[h * DHEAD + c4];
    float4 vvv = *(const float4*)&base[DMODEL + h * DHEAD + c4];
    size_t orow = ((size_t)(b * NHEAD + h) * JDIM + m) * 128;
    __nv_bfloat16 hh[4], ll[4];
    split1(kvv.x, hh[0], ll[0]); split1(kvv.y, hh[1], ll[1]);
    split1(kvv.z, hh[2], ll[2]); split1(kvv.w, hh[3], ll[3]);
    *(__nv_bfloat162*)(khl + orow + c4)      = __halves2bfloat162(hh[0], hh[1]);
    *(__nv_bfloat162*)(khl + orow + c4 + 2)  = __halves2bfloat162(hh[2], hh[3]);
    *(__nv_bfloat162*)(khl + orow + 64 + c4)     = __halves2bfloat162(ll[0], ll[1]);
    *(__nv_bfloat162*)(khl + orow + 64 + c4 + 2) = __halves2bfloat162(ll[2], ll[3]);
    split1(vvv.x, hh[0], ll[0]); split1(vvv.y, hh[1], ll[1]);
    split1(vvv.z, hh[2], ll[2]); split1(vvv.w, hh[3], ll[3]);
    *(__nv_bfloat162*)(vhl + orow + c4)      = __halves2bfloat162(hh[0], hh[1]);
    *(__nv_bfloat162*)(vhl + orow + c4 + 2)  = __halves2bfloat162(hh[2], hh[3]);
    *(__nv_bfloat162*)(vhl + orow + 64 + c4)     = __halves2bfloat162(ll[0], ll[1]);
    *(__nv_bfloat162*)(vhl + orow + 64 + c4 + 2) = __halves2bfloat162(ll[2], ll[3]);
}

__global__ void copy_x(const float* __restrict__ x, float* __restrict__ dst) {
    size_t i = (size_t)blockIdx.x * blockDim.x + threadIdx.x;
    const size_t total = (size_t)BATCH * TLEN * DMODEL / 4;
    if (i < total) ((float4*)dst)[i] = ((const float4*)x)[i];
}

// ---------------------------------------------------------------------------
// wmma bf16 GEMM (projections) — unchanged
// ---------------------------------------------------------------------------
#define STG_BYTES 20480
#define LDS_ROW   40

__global__ __launch_bounds__(256)
void tgemm_wmma(const __nv_bfloat16* __restrict__ A, const __nv_bfloat16* __restrict__ B,
                const float* __restrict__ bias, float* __restrict__ C,
                int M, int N, int Kp) {
    extern __shared__ char sm[];
    const uint32_t sbase = smem_u32(sm);
    float* biasS = (float*)(sm + 2 * STG_BYTES);

    const int tid = threadIdx.x;
    const int wid = tid >> 5;
    const int wm = wid >> 2;
    const int wn = wid & 3;
    const int row0 = blockIdx.y * 128;
    const int col0 = blockIdx.x * 128;

    for (int i = tid; i < 16 * 128; i += 256)
        biasS[i] = bias ? bias[col0 + (i & 127)] : 0.f;

    auto loadStage = [&](int s, int k0) {
        uint32_t ab = sbase + s * STG_BYTES;
        uint32_t bb = ab + STG_BYTES / 2;
#pragma unroll
        for (int p = 0; p < 2; ++p) {
            int i = tid + p * 256;
            int r = i >> 2, qq = i & 3;
            cpasync16s(ab + r * 80 + qq * 16,
                       (const char*)A + (((size_t)(row0 + r)) * Kp + k0 + qq * 8) * 2);
            cpasync16s(bb + r * 80 + qq * 16,
                       (const char*)B + (((size_t)(col0 + r)) * Kp + k0 + qq * 8) * 2);
        }
    };

    wmma::fragment<wmma::accumulator, 16, 16, 16, float> acc[4][2];
    __syncthreads();
#pragma unroll
    for (int i = 0; i < 4; ++i)
#pragma unroll
        for (int j = 0; j < 2; ++j)
            wmma::load_matrix_sync(acc[i][j], &biasS[wn * 32 + j * 16], 128, wmma::mem_row_major);

    loadStage(0, 0);
    cp_commit();

    const int nst = Kp / 32;
    for (int st = 0; st < nst; ++st) {
        cp_wait0();
        __syncthreads();
        if (st + 1 < nst) { loadStage((st + 1) & 1, (st + 1) * 32); cp_commit(); }

        const __nv_bfloat16* as = (const __nv_bfloat16*)(sm + (st & 1) * STG_BYTES);
        const __nv_bfloat16* bs = as + STG_BYTES / 4;

#pragma unroll
        for (int kk = 0; kk < 2; ++kk) {
            wmma::fragment<wmma::matrix_a, 16, 16, 16, __nv_bfloat16, wmma::row_major> af[4];
            wmma::fragment<wmma::matrix_b, 16, 16, 16, __nv_bfloat16, wmma::col_major> bfr[2];
#pragma unroll
            for (int i = 0; i < 4; ++i)
                wmma::load_matrix_sync(af[i], as + (wm * 64 + i * 16) * LDS_ROW + kk * 16, LDS_ROW);
#pragma unroll
            for (int j = 0; j < 2; ++j)
                wmma::load_matrix_sync(bfr[j], bs + (wn * 32 + j * 16) * LDS_ROW + kk * 16, LDS_ROW);
#pragma unroll
            for (int i = 0; i < 4; ++i)
#pragma unroll
                for (int j = 0; j < 2; ++j)
                    wmma::mma_sync(acc[i][j], af[i], bfr[j], acc[i][j]);
        }
    }

#pragma unroll
    for (int i = 0; i < 4; ++i)
#pragma unroll
        for (int j = 0; j < 2; ++j)
            wmma::store_matrix_sync(&C[(size_t)(row0 + wm * 64 + i * 16) * N + col0 + wn * 32 + j * 16],
                                    acc[i][j], N, wmma::mem_row_major);
}

// ---------------------------------------------------------------------------
// wmma flash attention with hi/lo compensation + in-tile rel shift.
// Per 64-col tile:
//   S = Qh Kh^T + Ql Kh^T + Qh Kl^T      (3 passes)
//   R = Qh Wh^T   (64 x 128 span, 1 pass; rel term is ~30x smaller -> bf16 ok)
//   score(r,mm) = 0.125*(S[r][mm] + R[r][mm+63-r]); mask; online softmax
//   O_tile = Ph Vh + Pl Vh + Ph Vl       (3 passes)
// ---------------------------------------------------------------------------
struct __align__(16) AttnW {
    __nv_bfloat16 Q2s[64][136];       // [Qh(64) | Ql(64)]
    __nv_bfloat16 Khl[2][64][136];    // [Kh | Kl] double-buffered
    __nv_bfloat16 Vhl[64][136];       // [Vh | Vl] single
    __nv_bfloat16 Wh[128][72];        // W span hi, single
    float         Sx[64][72];         // QK scores, then PV result
    float         Rx[64][132];        // rel scores (unshifted)
    __nv_bfloat16 Phl[64][136];       // [Ph | Pl]
    float m_s[64];
    float l_s[64];
};

__device__ __forceinline__ void aw_pf_K(AttnW& S, int bb, const __nv_bfloat16* __restrict__ khl,
                                        size_t bh, int m0, int tid) {
#pragma unroll
    for (int p = 0; p < 4; ++p) {
        int i = tid + p * 256;
        int r = i >> 4, c = i & 15;
        cpasync16(&S.Khl[bb][r][c * 8], khl + (bh * JDIM + (size_t)(m0 + r)) * 128 + c * 8);
    }
}
__device__ __forceinline__ void aw_pf_V(AttnW& S, const __nv_bfloat16* __restrict__ vhl,
                                        size_t bh, int m0, int tid) {
#pragma unroll
    for (int p = 0; p < 4; ++p) {
        int i = tid + p * 256;
        int r = i >> 4, c = i & 15;
        cpasync16(&S.Vhl[r][c * 8], vhl + (bh * JDIM + (size_t)(m0 + r)) * 128 + c * 8);
    }
}
__device__ __forceinline__ void aw_pf_W(AttnW& S, const __nv_bfloat16* __restrict__ rel2,
                                        int h, int base, int tid) {
    // 128 rows x 64 bf16 (hi part only); clamp row (OOB rows are masked anyway)
#pragma unroll
    for (int p = 0; p < 4; ++p) {
        int i = tid + p * 256;
        int o = i >> 3, c = i & 7;
        int u = base + o; if (u > JDIM - 1) u = JDIM - 1;
        cpasync16(&S.Wh[o][c * 8], rel2 + ((size_t)h * JDIM + u) * KG3 + c * 8);
    }
}

__global__ __launch_bounds__(256, 1)
void attn_wmma(const __nv_bfloat16* __restrict__ q2,
               const __nv_bfloat16* __restrict__ khl,
               const __nv_bfloat16* __restrict__ vhl,
               const __nv_bfloat16* __restrict__ rel2,
               float* __restrict__ out) {
    extern __shared__ char smem_raw[];
    AttnW& S = *reinterpret_cast<AttnW*>(smem_raw);

    const int b  = blockIdx.z;
    const int h  = blockIdx.y;
    const int rb = blockIdx.x;
    const int r0 = rb * 64;
    const size_t bh = (size_t)(b * NHEAD + h);
    const int tid = threadIdx.x;
    const int wid = tid >> 5;
    const int wm = wid >> 2;     // 0..1
    const int wn = wid & 3;      // 0..3
    const int sy = tid >> 4;     // 0..15
    const int sx = tid & 15;     // 0..15

#pragma unroll
    for (int p = 0; p < 4; ++p) {
        int i = tid + p * 256;
        int r = i >> 4, c = i & 15;
        cpasync16(&S.Q2s[r][c * 8],
                  q2 + (bh * TLEN + (size_t)(r0 + r)) * KG3 + c * 8);
    }
    aw_pf_K(S, 0, khl, bh, 0, tid);
    aw_pf_V(S, vhl, bh, 0, tid);
    aw_pf_W(S, rel2, h, 960 - r0, tid);
    cp_commit();

    if (tid < 64) { S.m_s[tid] = -1e30f; S.l_s[tid] = 0.f; }

    float acc[4][4];
#pragma unroll
    for (int i = 0; i < 4; ++i)
#pragma unroll
        for (int j = 0; j < 4; ++j) acc[i][j] = 0.f;

    const int ntiles = min(32, rb + 17);

    for (int mt = 0; mt < ntiles; ++mt) {
        const int cur = mt & 1;
        const int m0  = mt * 64;

        cp_wait0();
        __syncthreads();                    // K(t), V(t), W(t) ready

        if (mt + 1 < ntiles) { aw_pf_K(S, cur ^ 1, khl, bh, m0 + 64, tid); cp_commit(); }

        // ---- S: 3 compensated passes (64x64) ----
        {
            wmma::fragment<wmma::accumulator, 16, 16, 16, float> sacc[2];
#pragma unroll
            for (int i = 0; i < 2; ++i) wmma::fill_fragment(sacc[i], 0.f);
#pragma unroll
            for (int pass = 0; pass < 3; ++pass) {
                const int aoff = (pass == 1) ? 64 : 0;
                const int boff = (pass == 2) ? 64 : 0;
#pragma unroll
                for (int k16 = 0; k16 < 4; ++k16) {
                    wmma::fragment<wmma::matrix_a, 16, 16, 16, __nv_bfloat16, wmma::row_major> af[2];
                    wmma::fragment<wmma::matrix_b, 16, 16, 16, __nv_bfloat16, wmma::col_major> bfr;
#pragma unroll
                    for (int i = 0; i < 2; ++i)
                        wmma::load_matrix_sync(af[i], &S.Q2s[wm * 32 + i * 16][aoff + k16 * 16], 136);
                    wmma::load_matrix_sync(bfr, &S.Khl[cur][wn * 16][boff + k16 * 16], 136);
#pragma unroll
                    for (int i = 0; i < 2; ++i)
                        wmma::mma_sync(sacc[i], af[i], bfr, sacc[i]);
                }
            }
#pragma unroll
            for (int i = 0; i < 2; ++i)
                wmma::store_matrix_sync(&S.Sx[wm * 32 + i * 16][wn * 16], sacc[i], 72,
                                        wmma::mem_row_major);
        }
        // ---- R: 1 pass (64x128), Qh x Wh^T ----
        {
            wmma::fragment<wmma::accumulator, 16, 16, 16, float> racc[2][2];
#pragma unroll
            for (int i = 0; i < 2; ++i)
#pragma unroll
                for (int j = 0; j < 2; ++j) wmma::fill_fragment(racc[i][j], 0.f);
#pragma unroll
            for (int k16 = 0; k16 < 4; ++k16) {
                wmma::fragment<wmma::matrix_a, 16, 16, 16, __nv_bfloat16, wmma::row_major> af[2];
                wmma::fragment<wmma::matrix_b, 16, 16, 16, __nv_bfloat16, wmma::col_major> bfr[2];
#pragma unroll
                for (int i = 0; i < 2; ++i)
                    wmma::load_matrix_sync(af[i], &S.Q2s[wm * 32 + i * 16][k16 * 16], 136);
#pragma unroll
                for (int j = 0; j < 2; ++j)
                    wmma::load_matrix_sync(bfr[j], &S.Wh[wn * 32 + j * 16][k16 * 16], 72);
#pragma unroll
                for (int i = 0; i < 2; ++i)
#pragma unroll
                    for (int j = 0; j < 2; ++j)
                        wmma::mma_sync(racc[i][j], af[i], bfr[j], racc[i][j]);
            }
#pragma unroll
            for (int i = 0; i < 2; ++i)
#pragma unroll
                for (int j = 0; j < 2; ++j)
                    wmma::store_matrix_sync(&S.Rx[wm * 32 + i * 16][wn * 32 + j * 16],
                                            racc[i][j], 132, wmma::mem_row_major);
        }
        __syncthreads();                    // Sx, Rx visible; W consumed

        if (mt + 1 < ntiles) { aw_pf_W(S, rel2, h, m0 + 64 + 960 - r0, tid); cp_commit(); }

        // ---- softmax (SIMT), P -> bf16 hi/lo ----
#pragma unroll
        for (int i = 0; i < 4; ++i) {
            const int rl = 4 * sy + i;
            const int mlim = r0 + rl + MEMLEN - m0;
            const int ro = 63 - rl;                    // rel col offset
            float4 sv = *(const float4*)&S.Sx[rl][4 * sx];
            float sc[4];
            sc[0] = (sv.x + S.Rx[rl][4 * sx + 0 + ro]) * 0.125f;
            sc[1] = (sv.y + S.Rx[rl][4 * sx + 1 + ro]) * 0.125f;
            sc[2] = (sv.z + S.Rx[rl][4 * sx + 2 + ro]) * 0.125f;
            sc[3] = (sv.w + S.Rx[rl][4 * sx + 3 + ro]) * 0.125f;
#pragma unroll
            for (int j = 0; j < 4; ++j)
                if (4 * sx + j > mlim) sc[j] = -1e30f;

            float rmax = fmaxf(fmaxf(sc[0], sc[1]), fmaxf(sc[2], sc[3]));
            rmax = fmaxf(rmax, __shfl_xor_sync(0xffffffffu, rmax, 1));
            rmax = fmaxf(rmax, __shfl_xor_sync(0xffffffffu, rmax, 2));
            rmax = fmaxf(rmax, __shfl_xor_sync(0xffffffffu, rmax, 4));
            rmax = fmaxf(rmax, __shfl_xor_sync(0xffffffffu, rmax, 8));
            float mold = S.m_s[rl];
            float mnew = fmaxf(mold, rmax);
            float alpha = __expf(mold - mnew);
            float lsum = 0.f;
            __nv_bfloat16 ph[4], pl[4];
#pragma unroll
            for (int j = 0; j < 4; ++j) {
                float p = __expf(sc[j] - mnew);
                lsum += p;
                ph[j] = __float2bfloat16(p);
                pl[j] = __float2bfloat16(p - __bfloat162float(ph[j]));
            }
            lsum += __shfl_xor_sync(0xffffffffu, lsum, 1);
            lsum += __shfl_xor_sync(0xffffffffu, lsum, 2);
            lsum += __shfl_xor_sync(0xffffffffu, lsum, 4);
            lsum += __shfl_xor_sync(0xffffffffu, lsum, 8);
            if (sx == 0) {
                S.m_s[rl] = mnew;
                S.l_s[rl] = S.l_s[rl] * alpha + lsum;
            }
            *(__nv_bfloat162*)&S.Phl[rl][4 * sx]          = __halves2bfloat162(ph[0], ph[1]);
            *(__nv_bfloat162*)&S.Phl[rl][4 * sx + 2]      = __halves2bfloat162(ph[2], ph[3]);
            *(__nv_bfloat162*)&S.Phl[rl][64 + 4 * sx]     = __halves2bfloat162(pl[0], pl[1]);
            *(__nv_bfloat162*)&S.Phl[rl][64 + 4 * sx + 2] = __halves2bfloat162(pl[2], pl[3]);
#pragma unroll
            for (int j = 0; j < 4; ++j) acc[i][j] *= alpha;
        }
        __syncthreads();                    // Phl visible; Sx free

        // ---- PV: 3 compensated passes -> Sx ----
        {
            wmma::fragment<wmma::accumulator, 16, 16, 16, float> oacc[2];
#pragma unroll
            for (int i = 0; i < 2; ++i) wmma::fill_fragment(oacc[i], 0.f);
#pragma unroll
            for (int pass = 0; pass < 3; ++pass) {
                const int aoff = (pass == 1) ? 64 : 0;
                const int boff = (pass == 2) ? 64 : 0;
#pragma unroll
                for (int k16 = 0; k16 < 4; ++k16) {
                    wmma::fragment<wmma::matrix_a, 16, 16, 16, __nv_bfloat16, wmma::row_major> af[2];
                    wmma::fragment<wmma::matrix_b, 16, 16, 16, __nv_bfloat16, wmma::row_major> bfr;
#pragma unroll
                    for (int i = 0; i < 2; ++i)
                        wmma::load_matrix_sync(af[i], &S.Phl[wm * 32 + i * 16][aoff + k16 * 16], 136);
                    wmma::load_matrix_sync(bfr, &S.Vhl[k16 * 16][boff + wn * 16], 136);
#pragma unroll
                    for (int i = 0; i < 2; ++i)
                        wmma::mma_sync(oacc[i], af[i], bfr, oacc[i]);
                }
            }
#pragma unroll
            for (int i = 0; i < 2; ++i)
                wmma::store_matrix_sync(&S.Sx[wm * 32 + i * 16][wn * 16], oacc[i], 72,
                                        wmma::mem_row_major);
        }
        __syncthreads();                    // PV tile visible; V consumed

        if (mt + 1 < ntiles) { aw_pf_V(S, vhl, bh, m0 + 64, tid); cp_commit(); }

        // merge into SIMT accumulator
#pragma unroll
        for (int i = 0; i < 4; ++i) {
            const int rl = 4 * sy + i;
            float4 ov = *(const float4*)&S.Sx[rl][4 * sx];
            acc[i][0] += ov.x; acc[i][1] += ov.y; acc[i][2] += ov.z; acc[i][3] += ov.w;
        }
    }

    __syncthreads();
#pragma unroll
    for (int i = 0; i < 4; ++i) {
        const int rl = 4 * sy + i;
        float inv = 1.f / S.l_s[rl];
        size_t o = ((size_t)(b * TLEN + r0 + rl)) * DMODEL + h * DHEAD + 4 * sx;
        *(float4*)&out[o] = make_float4(acc[i][0] * inv, acc[i][1] * inv,
                                        acc[i][2] * inv, acc[i][3] * inv);
    }
}

// ---------------------------------------------------------------------------
extern "C" void kernel_launch(void* const* d_in, const int* in_sizes, int n_in,
                              void* d_out, int out_size) {
    const float* x    = (const float*)d_in[0];
    const float* mem  = (const float*)d_in[1];
    const float* wq   = (const float*)d_in[2];
    const float* wkv  = (const float*)d_in[3];
    const float* wo   = (const float*)d_in[4];
    const float* bo   = (const float*)d_in[5];
    const float* relw = (const float*)d_in[6];

    float* out_main = (float*)d_out;
    float* mem_next = out_main + (size_t)BATCH * TLEN * DMODEL;

    float *q, *kv, *attn;
    __nv_bfloat16 *x2, *kvin2, *a2, *wq2, *wkv2, *wo2, *q2, *rel2, *khl, *vhl;
    cudaGetSymbolAddress((void**)&q,     g_q);
    cudaGetSymbolAddress((void**)&kv,    g_kv);
    cudaGetSymbolAddress((void**)&attn,  g_attn);
    cudaGetSymbolAddress((void**)&x2,    g_x2);
    cudaGetSymbolAddress((void**)&kvin2, g_kvin2);
    cudaGetSymbolAddress((void**)&a2,    g_a2);
    cudaGetSymbolAddress((void**)&wq2,   g_wq2);
    cudaGetSymbolAddress((void**)&wkv2,  g_wkv2);
    cudaGetSymbolAddress((void**)&wo2,   g_wo2);
    cudaGetSymbolAddress((void**)&q2,    g_q2);
    cudaGetSymbolAddress((void**)&rel2,  g_rel2);
    cudaGetSymbolAddress((void**)&khl,   g_khl);
    cudaGetSymbolAddress((void**)&vhl,   g_vhl);

    const int TG_SMEM = 2 * STG_BYTES + 16 * 128 * 4;
    const int AW_SMEM = (int)sizeof(AttnW);
    cudaFuncSetAttribute(tgemm_wmma, cudaFuncAttributeMaxDynamicSharedMemorySize, TG_SMEM);
    cudaFuncSetAttribute(attn_wmma,  cudaFuncAttributeMaxDynamicSharedMemorySize, AW_SMEM);

    // operand prep
    {
        size_t tot = (size_t)BATCH * TLEN * 256;
        split3_rows<<<(unsigned)((tot + 255) / 256), 256>>>(x, x2, tot);
    }
    {
        size_t tot = (size_t)BATCH * JDIM * 256;
        build_kvin_split3<<<(unsigned)((tot + 255) / 256), 256>>>(x, mem, kvin2);
    }
    transpose_split3<<<dim3(DMODEL / 32, DMODEL / 32), dim3(32, 8)>>>(wq, wq2, DMODEL);
    transpose_split3<<<dim3(2 * DMODEL / 32, DMODEL / 32), dim3(32, 8)>>>(wkv, wkv2, 2 * DMODEL);
    transpose_split3<<<dim3(DMODEL / 32, DMODEL / 32), dim3(32, 8)>>>(wo, wo2, DMODEL);
    {
        size_t tot = (size_t)JDIM * NHEAD * 16;
        build_rel2k<<<(unsigned)((tot + 255) / 256), 256>>>(relw, rel2);
    }

    // q = x @ wq
    tgemm_wmma<<<dim3(DMODEL / 128, BATCH * TLEN / 128), 256, TG_SMEM>>>(
        x2, wq2, nullptr, q, BATCH * TLEN, DMODEL, KP3);
    {
        size_t tot = (size_t)BATCH * TLEN * NHEAD * 16;
        build_q2k<<<(unsigned)((tot + 255) / 256), 256>>>(q, q2);
    }
    // kv = kvin @ wkv
    tgemm_wmma<<<dim3(2 * DMODEL / 128, BATCH * JDIM / 128), 256, TG_SMEM>>>(
        kvin2, wkv2, nullptr, kv, BATCH * JDIM, 2 * DMODEL, KP3);
    {
        size_t tot = (size_t)BATCH * JDIM * NHEAD * 16;
        build_khl_vhl<<<(unsigned)((tot + 255) / 256), 256>>>(kv, khl, vhl);
    }
    // wmma flash attention (rel shift computed in-tile)
    attn_wmma<<<dim3(TLEN / 64, NHEAD, BATCH), 256, AW_SMEM>>>(q2, khl, vhl, rel2, attn);
    // out = attn @ wo + bo
    {
        size_t tot = (size_t)BATCH * TLEN * 256;
        split3_rows<<<(unsigned)((tot + 255) / 256), 256>>>(attn, a2, tot);
    }
    tgemm_wmma<<<dim3(DMODEL / 128, BATCH * TLEN / 128), 256, TG_SMEM>>>(
        a2, wo2, bo, out_main, BATCH * TLEN, DMODEL, KP3);
    // mem_next = x
    {
        size_t n4 = (size_t)BATCH * TLEN * DMODEL / 4;
        copy_x<<<(unsigned)((n4 + 255) / 256), 256>>>(x, mem_next);
    }
}

// round 9
// speedup vs baseline: 3.4099x; 1.0126x over previous
#include <cuda_runtime.h>
#include <cuda_bf16.h>
#include <mma.h>
#include <cstddef>
#include <cstdint>

using namespace nvcuda;

#define BATCH   4
#define TLEN    1024
#define MEMLEN  1024
#define JDIM    2048
#define DMODEL  1024
#define NHEAD   16
#define DHEAD   64
#define KP3     3072      // 3 * DMODEL (compensated K)

// -------- scratch (static __device__ globals; cudaMalloc is forbidden) ------
// bf16 K-concatenated operands (projection GEMMs)
__device__ __nv_bfloat16 g_x2   [(size_t)BATCH * TLEN * KP3];    // [h|l|h]
__device__ __nv_bfloat16 g_kvin2[(size_t)BATCH * JDIM * KP3];    // [h|l|h]
__device__ __nv_bfloat16 g_a2   [(size_t)BATCH * TLEN * KP3];    // [h|l|h]
__device__ __nv_bfloat16 g_wq2  [(size_t)DMODEL * KP3];          // [h|h|l] (transposed)
__device__ __nv_bfloat16 g_wkv2 [(size_t)2 * DMODEL * KP3];      // [h|h|l]
__device__ __nv_bfloat16 g_wo2  [(size_t)DMODEL * KP3];          // [h|h|l]
// per-head operands for attention
__device__ __nv_bfloat16 g_q2   [(size_t)BATCH * NHEAD * TLEN * 128];  // [Qh|Ql]
__device__ __nv_bfloat16 g_rel2 [(size_t)NHEAD * JDIM * 64];           // hi only
__device__ __nv_bfloat16 g_khl  [(size_t)BATCH * NHEAD * JDIM * 128];  // [Kh|Kl]
__device__ __nv_bfloat16 g_vhl  [(size_t)BATCH * NHEAD * JDIM * 128];  // [Vh|Vl]

// ---------------------------------------------------------------------------
__device__ __forceinline__ uint32_t smem_u32(const void* p) {
    uint32_t a;
    asm("{ .reg .u64 t; cvta.to.shared.u64 t, %1; cvt.u32.u64 %0, t; }" : "=r"(a) : "l"(p));
    return a;
}
__device__ __forceinline__ void cpasync16s(uint32_t saddr, const void* gsrc) {
    asm volatile("cp.async.cg.shared.global [%0], [%1], 16;\n" :: "r"(saddr), "l"(gsrc));
}
__device__ __forceinline__ void cpasync16(void* smem_dst, const void* gsrc) {
    cpasync16s((uint32_t)__cvta_generic_to_shared(smem_dst), gsrc);
}
__device__ __forceinline__ void cp_commit() { asm volatile("cp.async.commit_group;\n"); }
__device__ __forceinline__ void cp_wait0()  { asm volatile("cp.async.wait_group 0;\n"); }
__device__ __forceinline__ void cp_wait1()  { asm volatile("cp.async.wait_group 1;\n"); }

__device__ __forceinline__ void split1(float v, __nv_bfloat16& h, __nv_bfloat16& l) {
    h = __float2bfloat16(v);
    l = __float2bfloat16(v - __bfloat162float(h));
}

// ---------------------------------------------------------------------------
// prep kernels
// ---------------------------------------------------------------------------
__global__ void split3_rows(const float* __restrict__ in, __nv_bfloat16* __restrict__ out,
                            size_t total /* R*256 */) {
    size_t i = (size_t)blockIdx.x * blockDim.x + threadIdx.x;
    if (i >= total) return;
    size_t r = i >> 8;
    int c4 = (int)(i & 255) * 4;
    float4 v = *(const float4*)&in[r * DMODEL + c4];
    __nv_bfloat16 h[4], l[4];
    split1(v.x, h[0], l[0]); split1(v.y, h[1], l[1]);
    split1(v.z, h[2], l[2]); split1(v.w, h[3], l[3]);
    __nv_bfloat16* o = out + r * KP3;
    __nv_bfloat162 hp0 = __halves2bfloat162(h[0], h[1]), hp1 = __halves2bfloat162(h[2], h[3]);
    __nv_bfloat162 lp0 = __halves2bfloat162(l[0], l[1]), lp1 = __halves2bfloat162(l[2], l[3]);
    *(__nv_bfloat162*)(o + c4)              = hp0; *(__nv_bfloat162*)(o + c4 + 2)              = hp1;
    *(__nv_bfloat162*)(o + DMODEL + c4)     = lp0; *(__nv_bfloat162*)(o + DMODEL + c4 + 2)     = lp1;
    *(__nv_bfloat162*)(o + 2 * DMODEL + c4) = hp0; *(__nv_bfloat162*)(o + 2 * DMODEL + c4 + 2) = hp1;
}

__global__ void build_kvin_split3(const float* __restrict__ x, const float* __restrict__ mem,
                                  __nv_bfloat16* __restrict__ out) {
    size_t i = (size_t)blockIdx.x * blockDim.x + threadIdx.x;
    const size_t total = (size_t)BATCH * JDIM * 256;
    if (i >= total) return;
    size_t r = i >> 8;
    int c4 = (int)(i & 255) * 4;
    size_t b = r / JDIM, m = r % JDIM;
    float4 v;
    if (m < MEMLEN) v = *(const float4*)&mem[(b * MEMLEN + m) * DMODEL + c4];
    else            v = *(const float4*)&x  [(b * TLEN + (m - MEMLEN)) * DMODEL + c4];
    __nv_bfloat16 h[4], l[4];
    split1(v.x, h[0], l[0]); split1(v.y, h[1], l[1]);
    split1(v.z, h[2], l[2]); split1(v.w, h[3], l[3]);
    __nv_bfloat16* o = out + r * KP3;
    __nv_bfloat162 hp0 = __halves2bfloat162(h[0], h[1]), hp1 = __halves2bfloat162(h[2], h[3]);
    __nv_bfloat162 lp0 = __halves2bfloat162(l[0], l[1]), lp1 = __halves2bfloat162(l[2], l[3]);
    *(__nv_bfloat162*)(o + c4)              = hp0; *(__nv_bfloat162*)(o + c4 + 2)              = hp1;
    *(__nv_bfloat162*)(o + DMODEL + c4)     = lp0; *(__nv_bfloat162*)(o + DMODEL + c4 + 2)     = lp1;
    *(__nv_bfloat162*)(o + 2 * DMODEL + c4) = hp0; *(__nv_bfloat162*)(o + 2 * DMODEL + c4 + 2) = hp1;
}

__global__ void transpose_split3(const float* __restrict__ W, __nv_bfloat16* __restrict__ T2, int N) {
    __shared__ float t[32][33];
    int k0 = blockIdx.y * 32, n0 = blockIdx.x * 32;
    int tx = threadIdx.x, ty = threadIdx.y;
#pragma unroll
    for (int i = 0; i < 32; i += 8)
        t[ty + i][tx] = W[(size_t)(k0 + ty + i) * N + n0 + tx];
    __syncthreads();
#pragma unroll
    for (int i = 0; i < 32; i += 8) {
        float v = t[tx][ty + i];
        int n = n0 + ty + i, k = k0 + tx;
        __nv_bfloat16 h, l;
        split1(v, h, l);
        __nv_bfloat16* o = T2 + (size_t)n * KP3;
        o[k] = h; o[DMODEL + k] = h; o[2 * DMODEL + k] = l;
    }
}

// rel fp32 [u][h][64] -> rel2[h][u][64] hi only
__global__ void build_rel2k(const float* __restrict__ rel, __nv_bfloat16* __restrict__ rel2) {
    size_t i = (size_t)blockIdx.x * blockDim.x + threadIdx.x;
    const size_t total = (size_t)JDIM * NHEAD * 16;
    if (i >= total) return;
    int c4 = (int)(i & 15) * 4;
    int h  = (int)(i >> 4) & 15;
    int u  = (int)(i >> 8);
    float4 v = *(const float4*)&rel[((size_t)u * NHEAD + h) * DHEAD + c4];
    __nv_bfloat16* o = rel2 + ((size_t)h * JDIM + u) * 64;
    *(__nv_bfloat162*)(o + c4)     = __halves2bfloat162(__float2bfloat16(v.x), __float2bfloat16(v.y));
    *(__nv_bfloat162*)(o + c4 + 2) = __halves2bfloat162(__float2bfloat16(v.z), __float2bfloat16(v.w));
}

__global__ void copy_x(const float* __restrict__ x, float* __restrict__ dst) {
    size_t i = (size_t)blockIdx.x * blockDim.x + threadIdx.x;
    const size_t total = (size_t)BATCH * TLEN * DMODEL / 4;
    if (i < total) ((float4*)dst)[i] = ((const float4*)x)[i];
}

// ---------------------------------------------------------------------------
// wmma bf16 GEMM, 3-stage cp.async pipeline, fused epilogues.
// mode 0: C = A@B^T + bias (fp32 out)
// mode 1: q-proj -> q2 [bh][t][128]=[hi|lo]
// mode 2: kv-proj -> khl/vhl [bh][m][128]=[hi|lo]
// ---------------------------------------------------------------------------
#define STG_BYTES 20480
#define LDS_ROW   40
#define NSTAGE    3

__global__ __launch_bounds__(256)
void tgemm_wmma(const __nv_bfloat16* __restrict__ A, const __nv_bfloat16* __restrict__ B,
                const float* __restrict__ bias, float* __restrict__ C,
                __nv_bfloat16* __restrict__ q2o,
                __nv_bfloat16* __restrict__ khlo, __nv_bfloat16* __restrict__ vhlo,
                int M, int N, int Kp, int mode) {
    extern __shared__ char sm[];
    const uint32_t sbase = smem_u32(sm);
    float* biasS = (float*)(sm + NSTAGE * STG_BYTES);

    const int tid = threadIdx.x;
    const int wid = tid >> 5;
    const int wm = wid >> 2;
    const int wn = wid & 3;
    const int row0 = blockIdx.y * 128;
    const int col0 = blockIdx.x * 128;

    if (mode == 0)
        for (int i = tid; i < 16 * 128; i += 256)
            biasS[i] = bias ? bias[col0 + (i & 127)] : 0.f;

    auto loadStage = [&](int s, int k0) {
        uint32_t ab = sbase + s * STG_BYTES;
        uint32_t bb = ab + STG_BYTES / 2;
#pragma unroll
        for (int p = 0; p < 2; ++p) {
            int i = tid + p * 256;
            int r = i >> 2, qq = i & 3;
            cpasync16s(ab + r * 80 + qq * 16,
                       (const char*)A + (((size_t)(row0 + r)) * Kp + k0 + qq * 8) * 2);
            cpasync16s(bb + r * 80 + qq * 16,
                       (const char*)B + (((size_t)(col0 + r)) * Kp + k0 + qq * 8) * 2);
        }
    };

    wmma::fragment<wmma::accumulator, 16, 16, 16, float> acc[4][2];
    __syncthreads();
    if (mode == 0) {
#pragma unroll
        for (int i = 0; i < 4; ++i)
#pragma unroll
            for (int j = 0; j < 2; ++j)
                wmma::load_matrix_sync(acc[i][j], &biasS[wn * 32 + j * 16], 128, wmma::mem_row_major);
    } else {
#pragma unroll
        for (int i = 0; i < 4; ++i)
#pragma unroll
            for (int j = 0; j < 2; ++j)
                wmma::fill_fragment(acc[i][j], 0.f);
    }

    loadStage(0, 0); cp_commit();
    loadStage(1, 32); cp_commit();

    const int nst = Kp / 32;
    for (int st = 0; st < nst; ++st) {
        if (st == nst - 1) cp_wait0(); else cp_wait1();
        __syncthreads();
        if (st + 2 < nst) { loadStage((st + 2) % NSTAGE, (st + 2) * 32); cp_commit(); }

        const __nv_bfloat16* as = (const __nv_bfloat16*)(sm + (st % NSTAGE) * STG_BYTES);
        const __nv_bfloat16* bs = as + STG_BYTES / 4;

#pragma unroll
        for (int kk = 0; kk < 2; ++kk) {
            wmma::fragment<wmma::matrix_a, 16, 16, 16, __nv_bfloat16, wmma::row_major> af[4];
            wmma::fragment<wmma::matrix_b, 16, 16, 16, __nv_bfloat16, wmma::col_major> bfr[2];
#pragma unroll
            for (int i = 0; i < 4; ++i)
                wmma::load_matrix_sync(af[i], as + (wm * 64 + i * 16) * LDS_ROW + kk * 16, LDS_ROW);
#pragma unroll
            for (int j = 0; j < 2; ++j)
                wmma::load_matrix_sync(bfr[j], bs + (wn * 32 + j * 16) * LDS_ROW + kk * 16, LDS_ROW);
#pragma unroll
            for (int i = 0; i < 4; ++i)
#pragma unroll
                for (int j = 0; j < 2; ++j)
                    wmma::mma_sync(acc[i][j], af[i], bfr[j], acc[i][j]);
        }
    }

    if (mode == 0) {
#pragma unroll
        for (int i = 0; i < 4; ++i)
#pragma unroll
            for (int j = 0; j < 2; ++j)
                wmma::store_matrix_sync(&C[(size_t)(row0 + wm * 64 + i * 16) * N + col0 + wn * 32 + j * 16],
                                        acc[i][j], N, wmma::mem_row_major);
        return;
    }

    // modes 1/2: stage fragments to smem fp32 tile, split+scatter
    __syncthreads();
    float* Cs = (float*)sm;   // [128][132]
#pragma unroll
    for (int i = 0; i < 4; ++i)
#pragma unroll
        for (int j = 0; j < 2; ++j)
            wmma::store_matrix_sync(&Cs[(size_t)(wm * 64 + i * 16) * 132 + wn * 32 + j * 16],
                                    acc[i][j], 132, wmma::mem_row_major);
    __syncthreads();

    if (mode == 1) {
        for (int idx = tid; idx < 128 * 128; idx += 256) {
            int r = idx >> 7, c = idx & 127;
            float v = Cs[r * 132 + c];
            __nv_bfloat16 hv, lv; split1(v, hv, lv);
            int bt = row0 + r, gc = col0 + c;
            int b = bt >> 10, t = bt & 1023;
            int h = gc >> 6, cc = gc & 63;
            __nv_bfloat16* o = q2o + (((size_t)(b * NHEAD + h) * TLEN + t)) * 128 + cc;
            o[0] = hv; o[64] = lv;
        }
    } else {
        for (int idx = tid; idx < 128 * 128; idx += 256) {
            int r = idx >> 7, c = idx & 127;
            float v = Cs[r * 132 + c];
            __nv_bfloat16 hv, lv; split1(v, hv, lv);
            int rg = row0 + r, gc = col0 + c;
            int b = rg >> 11, m = rg & 2047;
            __nv_bfloat16* dst = (gc < DMODEL) ? khlo : vhlo;
            int gcl = (gc < DMODEL) ? gc : gc - DMODEL;
            int h = gcl >> 6, cc = gcl & 63;
            __nv_bfloat16* o = dst + (((size_t)(b * NHEAD + h) * JDIM + m)) * 128 + cc;
            o[0] = hv; o[64] = lv;
        }
    }
}

// ---------------------------------------------------------------------------
// wmma flash attention, hi/lo compensation, incremental rel-R ring.
// Per 64-col tile:
//   S = Qh Kh^T + Ql Kh^T + Qh Kl^T   (3 passes)
//   R_new = Qh Wnew^T (64x64, 1 pass); window = [R_prev | R_new]
//   score(r,mm) = 0.125*(S[r][mm] + window[r][mm+63-r]); mask; online softmax
//   O_tile = Ph Vh + Pl Vh + Ph Vl    (3 passes)
// Epilogue writes a2 [row][3072] = [h|l|h] directly.
// ---------------------------------------------------------------------------
struct __align__(16) AttnW {
    __nv_bfloat16 Q2s[64][136];       // [Qh(64) | Ql(64)]
    __nv_bfloat16 Khl[2][64][136];    // [Kh | Kl] double-buffered
    __nv_bfloat16 Vhl[64][136];       // [Vh | Vl] single
    __nv_bfloat16 Wh[2][64][72];      // W span ring (hi only)
    float         Sx[64][72];         // QK scores, then PV result
    float         Rx[2][64][68];      // rel scores ring (64-col halves)
    __nv_bfloat16 Phl[64][136];       // [Ph | Pl]
    float m_s[64];
    float l_s[64];
};

__device__ __forceinline__ void aw_pf_K(AttnW& S, int bb, const __nv_bfloat16* __restrict__ khl,
                                        size_t bh, int m0, int tid) {
#pragma unroll
    for (int p = 0; p < 4; ++p) {
        int i = tid + p * 256;
        int r = i >> 4, c = i & 15;
        cpasync16(&S.Khl[bb][r][c * 8], khl + (bh * JDIM + (size_t)(m0 + r)) * 128 + c * 8);
    }
}
__device__ __forceinline__ void aw_pf_V(AttnW& S, const __nv_bfloat16* __restrict__ vhl,
                                        size_t bh, int m0, int tid) {
#pragma unroll
    for (int p = 0; p < 4; ++p) {
        int i = tid + p * 256;
        int r = i >> 4, c = i & 15;
        cpasync16(&S.Vhl[r][c * 8], vhl + (bh * JDIM + (size_t)(m0 + r)) * 128 + c * 8);
    }
}
// 64 rows x 64 bf16 (hi) into ring slot
__device__ __forceinline__ void aw_pf_W(AttnW& S, int slot, const __nv_bfloat16* __restrict__ rel2,
                                        int h, int ubase, int tid) {
#pragma unroll
    for (int p = 0; p < 2; ++p) {
        int i = tid + p * 256;
        int o = i >> 3, c = i & 7;
        int u = ubase + o; if (u > JDIM - 1) u = JDIM - 1;
        cpasync16(&S.Wh[slot][o][c * 8], rel2 + ((size_t)h * JDIM + u) * 64 + c * 8);
    }
}

__global__ __launch_bounds__(256, 1)
void attn_wmma(const __nv_bfloat16* __restrict__ q2,
               const __nv_bfloat16* __restrict__ khl,
               const __nv_bfloat16* __restrict__ vhl,
               const __nv_bfloat16* __restrict__ rel2,
               __nv_bfloat16* __restrict__ a2) {
    extern __shared__ char smem_raw[];
    AttnW& S = *reinterpret_cast<AttnW*>(smem_raw);

    const int b  = blockIdx.z;
    const int h  = blockIdx.y;
    const int rb = blockIdx.x;
    const int r0 = rb * 64;
    const size_t bh = (size_t)(b * NHEAD + h);
    const int tid = threadIdx.x;
    const int wid = tid >> 5;
    const int wm = wid >> 2;     // 0..1
    const int wn = wid & 3;      // 0..3
    const int sy = tid >> 4;     // 0..15
    const int sx = tid & 15;     // 0..15

#pragma unroll
    for (int p = 0; p < 4; ++p) {
        int i = tid + p * 256;
        int r = i >> 4, c = i & 15;
        cpasync16(&S.Q2s[r][c * 8],
                  q2 + (bh * TLEN + (size_t)(r0 + r)) * 128 + c * 8);
    }
    aw_pf_K(S, 0, khl, bh, 0, tid);
    aw_pf_V(S, vhl, bh, 0, tid);
    aw_pf_W(S, 1, rel2, h, 960 - r0, tid);        // initial LEFT half
    aw_pf_W(S, 0, rel2, h, 1024 - r0, tid);       // tile-0 RIGHT half
    cp_commit();

    if (tid < 64) { S.m_s[tid] = -1e30f; S.l_s[tid] = 0.f; }

    float acc[4][4];
#pragma unroll
    for (int i = 0; i < 4; ++i)
#pragma unroll
        for (int j = 0; j < 4; ++j) acc[i][j] = 0.f;

    const int ntiles = min(32, rb + 17);

    for (int mt = 0; mt < ntiles; ++mt) {
        const int cur = mt & 1;
        const int prv = cur ^ 1;
        const int m0  = mt * 64;

        cp_wait0();
        __syncthreads();                    // K(t), V(t), Wnew(t) ready

        if (mt + 1 < ntiles) { aw_pf_K(S, cur ^ 1, khl, bh, m0 + 64, tid); cp_commit(); }

        // ---- S: 3 compensated passes (64x64) ----
        {
            wmma::fragment<wmma::accumulator, 16, 16, 16, float> sacc[2];
#pragma unroll
            for (int i = 0; i < 2; ++i) wmma::fill_fragment(sacc[i], 0.f);
#pragma unroll
            for (int pass = 0; pass < 3; ++pass) {
                const int aoff = (pass == 1) ? 64 : 0;
                const int boff = (pass == 2) ? 64 : 0;
#pragma unroll
                for (int k16 = 0; k16 < 4; ++k16) {
                    wmma::fragment<wmma::matrix_a, 16, 16, 16, __nv_bfloat16, wmma::row_major> af[2];
                    wmma::fragment<wmma::matrix_b, 16, 16, 16, __nv_bfloat16, wmma::col_major> bfr;
#pragma unroll
                    for (int i = 0; i < 2; ++i)
                        wmma::load_matrix_sync(af[i], &S.Q2s[wm * 32 + i * 16][aoff + k16 * 16], 136);
                    wmma::load_matrix_sync(bfr, &S.Khl[cur][wn * 16][boff + k16 * 16], 136);
#pragma unroll
                    for (int i = 0; i < 2; ++i)
                        wmma::mma_sync(sacc[i], af[i], bfr, sacc[i]);
                }
            }
#pragma unroll
            for (int i = 0; i < 2; ++i)
                wmma::store_matrix_sync(&S.Sx[wm * 32 + i * 16][wn * 16], sacc[i], 72,
                                        wmma::mem_row_major);
        }
        // ---- R: new 64x64 half (Qh x Wnew^T); at mt==0 also the left half ----
        {
            const int nR = (mt == 0) ? 2 : 1;
            for (int rr = 0; rr < nR; ++rr) {
                const int slot = (rr == 0) ? cur : prv;     // mt==0: rr1 fills left (slot 1)
                wmma::fragment<wmma::accumulator, 16, 16, 16, float> racc[2];
#pragma unroll
                for (int i = 0; i < 2; ++i) wmma::fill_fragment(racc[i], 0.f);
#pragma unroll
                for (int k16 = 0; k16 < 4; ++k16) {
                    wmma::fragment<wmma::matrix_a, 16, 16, 16, __nv_bfloat16, wmma::row_major> af[2];
                    wmma::fragment<wmma::matrix_b, 16, 16, 16, __nv_bfloat16, wmma::col_major> bfr;
#pragma unroll
                    for (int i = 0; i < 2; ++i)
                        wmma::load_matrix_sync(af[i], &S.Q2s[wm * 32 + i * 16][k16 * 16], 136);
                    wmma::load_matrix_sync(bfr, &S.Wh[slot][wn * 16][k16 * 16], 72);
#pragma unroll
                    for (int i = 0; i < 2; ++i)
                        wmma::mma_sync(racc[i], af[i], bfr, racc[i]);
                }
#pragma unroll
                for (int i = 0; i < 2; ++i)
                    wmma::store_matrix_sync(&S.Rx[slot][wm * 32 + i * 16][wn * 16], racc[i], 68,
                                            wmma::mem_row_major);
            }
        }
        __syncthreads();                    // Sx, Rx visible; Wh consumed

        if (mt + 1 < ntiles) {
            aw_pf_W(S, (mt + 1) & 1, rel2, h, m0 + 1088 - r0, tid);   // (m0+64) right half
            cp_commit();
        }

        // ---- softmax (SIMT), P -> bf16 hi/lo ----
#pragma unroll
        for (int i = 0; i < 4; ++i) {
            const int rl = 4 * sy + i;
            const int mlim = r0 + rl + MEMLEN - m0;
            const int ro = 63 - rl;
            float4 sv = *(const float4*)&S.Sx[rl][4 * sx];
            float sraw[4] = {sv.x, sv.y, sv.z, sv.w};
            float sc[4];
#pragma unroll
            for (int j = 0; j < 4; ++j) {
                int o = 4 * sx + j + ro;
                float rv = (o < 64) ? S.Rx[prv][rl][o] : S.Rx[cur][rl][o - 64];
                sc[j] = (sraw[j] + rv) * 0.125f;
                if (4 * sx + j > mlim) sc[j] = -1e30f;
            }
            float rmax = fmaxf(fmaxf(sc[0], sc[1]), fmaxf(sc[2], sc[3]));
            rmax = fmaxf(rmax, __shfl_xor_sync(0xffffffffu, rmax, 1));
            rmax = fmaxf(rmax, __shfl_xor_sync(0xffffffffu, rmax, 2));
            rmax = fmaxf(rmax, __shfl_xor_sync(0xffffffffu, rmax, 4));
            rmax = fmaxf(rmax, __shfl_xor_sync(0xffffffffu, rmax, 8));
            float mold = S.m_s[rl];
            float mnew = fmaxf(mold, rmax);
            float alpha = __expf(mold - mnew);
            float lsum = 0.f;
            __nv_bfloat16 ph[4], pl[4];
#pragma unroll
            for (int j = 0; j < 4; ++j) {
                float p = __expf(sc[j] - mnew);
                lsum += p;
                ph[j] = __float2bfloat16(p);
                pl[j] = __float2bfloat16(p - __bfloat162float(ph[j]));
            }
            lsum += __shfl_xor_sync(0xffffffffu, lsum, 1);
            lsum += __shfl_xor_sync(0xffffffffu, lsum, 2);
            lsum += __shfl_xor_sync(0xffffffffu, lsum, 4);
            lsum += __shfl_xor_sync(0xffffffffu, lsum, 8);
            if (sx == 0) {
                S.m_s[rl] = mnew;
                S.l_s[rl] = S.l_s[rl] * alpha + lsum;
            }
            *(__nv_bfloat162*)&S.Phl[rl][4 * sx]          = __halves2bfloat162(ph[0], ph[1]);
            *(__nv_bfloat162*)&S.Phl[rl][4 * sx + 2]      = __halves2bfloat162(ph[2], ph[3]);
            *(__nv_bfloat162*)&S.Phl[rl][64 + 4 * sx]     = __halves2bfloat162(pl[0], pl[1]);
            *(__nv_bfloat162*)&S.Phl[rl][64 + 4 * sx + 2] = __halves2bfloat162(pl[2], pl[3]);
#pragma unroll
            for (int j = 0; j < 4; ++j) acc[i][j] *= alpha;
        }
        __syncthreads();                    // Phl visible; Sx free

        // ---- PV: 3 compensated passes -> Sx ----
        {
            wmma::fragment<wmma::accumulator, 16, 16, 16, float> oacc[2];
#pragma unroll
            for (int i = 0; i < 2; ++i) wmma::fill_fragment(oacc[i], 0.f);
#pragma unroll
            for (int pass = 0; pass < 3; ++pass) {
                const int aoff = (pass == 1) ? 64 : 0;
                const int boff = (pass == 2) ? 64 : 0;
#pragma unroll
                for (int k16 = 0; k16 < 4; ++k16) {
                    wmma::fragment<wmma::matrix_a, 16, 16, 16, __nv_bfloat16, wmma::row_major> af[2];
                    wmma::fragment<wmma::matrix_b, 16, 16, 16, __nv_bfloat16, wmma::row_major> bfr;
#pragma unroll
                    for (int i = 0; i < 2; ++i)
                        wmma::load_matrix_sync(af[i], &S.Phl[wm * 32 + i * 16][aoff + k16 * 16], 136);
                    wmma::load_matrix_sync(bfr, &S.Vhl[k16 * 16][boff + wn * 16], 136);
#pragma unroll
                    for (int i = 0; i < 2; ++i)
                        wmma::mma_sync(oacc[i], af[i], bfr, oacc[i]);
                }
            }
#pragma unroll
            for (int i = 0; i < 2; ++i)
                wmma::store_matrix_sync(&S.Sx[wm * 32 + i * 16][wn * 16], oacc[i], 72,
                                        wmma::mem_row_major);
        }
        __syncthreads();                    // PV tile visible; V consumed

        if (mt + 1 < ntiles) { aw_pf_V(S, vhl, bh, m0 + 64, tid); cp_commit(); }

#pragma unroll
        for (int i = 0; i < 4; ++i) {
            const int rl = 4 * sy + i;
            float4 ov = *(const float4*)&S.Sx[rl][4 * sx];
            acc[i][0] += ov.x; acc[i][1] += ov.y; acc[i][2] += ov.z; acc[i][3] += ov.w;
        }
    }

    __syncthreads();
    // epilogue: write a2 [row][3072] = [h | l | h] directly
#pragma unroll
    for (int i = 0; i < 4; ++i) {
        const int rl = 4 * sy + i;
        float inv = 1.f / S.l_s[rl];
        size_t row = (size_t)(b * TLEN + r0 + rl);
        __nv_bfloat16* o = a2 + row * KP3 + h * 64 + 4 * sx;
        __nv_bfloat16 hv[4], lv[4];
#pragma unroll
        for (int j = 0; j < 4; ++j) split1(acc[i][j] * inv, hv[j], lv[j]);
        *(__nv_bfloat162*)(o)              = __halves2bfloat162(hv[0], hv[1]);
        *(__nv_bfloat162*)(o + 2)          = __halves2bfloat162(hv[2], hv[3]);
        *(__nv_bfloat162*)(o + DMODEL)     = __halves2bfloat162(lv[0], lv[1]);
        *(__nv_bfloat162*)(o + DMODEL + 2) = __halves2bfloat162(lv[2], lv[3]);
        *(__nv_bfloat162*)(o + 2 * DMODEL)     = __halves2bfloat162(hv[0], hv[1]);
        *(__nv_bfloat162*)(o + 2 * DMODEL + 2) = __halves2bfloat162(hv[2], hv[3]);
    }
}

// ---------------------------------------------------------------------------
extern "C" void kernel_launch(void* const* d_in, const int* in_sizes, int n_in,
                              void* d_out, int out_size) {
    const float* x    = (const float*)d_in[0];
    const float* mem  = (const float*)d_in[1];
    const float* wq   = (const float*)d_in[2];
    const float* wkv  = (const float*)d_in[3];
    const float* wo   = (const float*)d_in[4];
    const float* bo   = (const float*)d_in[5];
    const float* relw = (const float*)d_in[6];

    float* out_main = (float*)d_out;
    float* mem_next = out_main + (size_t)BATCH * TLEN * DMODEL;

    __nv_bfloat16 *x2, *kvin2, *a2, *wq2, *wkv2, *wo2, *q2, *rel2, *khl, *vhl;
    cudaGetSymbolAddress((void**)&x2,    g_x2);
    cudaGetSymbolAddress((void**)&kvin2, g_kvin2);
    cudaGetSymbolAddress((void**)&a2,    g_a2);
    cudaGetSymbolAddress((void**)&wq2,   g_wq2);
    cudaGetSymbolAddress((void**)&wkv2,  g_wkv2);
    cudaGetSymbolAddress((void**)&wo2,   g_wo2);
    cudaGetSymbolAddress((void**)&q2,    g_q2);
    cudaGetSymbolAddress((void**)&rel2,  g_rel2);
    cudaGetSymbolAddress((void**)&khl,   g_khl);
    cudaGetSymbolAddress((void**)&vhl,   g_vhl);

    const int TG_SMEM = NSTAGE * STG_BYTES + 16 * 128 * 4;   // 69632
    const int AW_SMEM = (int)sizeof(AttnW);
    cudaFuncSetAttribute(tgemm_wmma, cudaFuncAttributeMaxDynamicSharedMemorySize, TG_SMEM);
    cudaFuncSetAttribute(attn_wmma,  cudaFuncAttributeMaxDynamicSharedMemorySize, AW_SMEM);

    // operand prep
    {
        size_t tot = (size_t)BATCH * TLEN * 256;
        split3_rows<<<(unsigned)((tot + 255) / 256), 256>>>(x, x2, tot);
    }
    {
        size_t tot = (size_t)BATCH * JDIM * 256;
        build_kvin_split3<<<(unsigned)((tot + 255) / 256), 256>>>(x, mem, kvin2);
    }
    transpose_split3<<<dim3(DMODEL / 32, DMODEL / 32), dim3(32, 8)>>>(wq, wq2, DMODEL);
    transpose_split3<<<dim3(2 * DMODEL / 32, DMODEL / 32), dim3(32, 8)>>>(wkv, wkv2, 2 * DMODEL);
    transpose_split3<<<dim3(DMODEL / 32, DMODEL / 32), dim3(32, 8)>>>(wo, wo2, DMODEL);
    {
        size_t tot = (size_t)JDIM * NHEAD * 16;
        build_rel2k<<<(unsigned)((tot + 255) / 256), 256>>>(relw, rel2);
    }

    // q-proj -> q2 directly (mode 1)
    tgemm_wmma<<<dim3(DMODEL / 128, BATCH * TLEN / 128), 256, TG_SMEM>>>(
        x2, wq2, nullptr, nullptr, q2, nullptr, nullptr, BATCH * TLEN, DMODEL, KP3, 1);
    // kv-proj -> khl/vhl directly (mode 2)
    tgemm_wmma<<<dim3(2 * DMODEL / 128, BATCH * JDIM / 128), 256, TG_SMEM>>>(
        kvin2, wkv2, nullptr, nullptr, nullptr, khl, vhl, BATCH * JDIM, 2 * DMODEL, KP3, 2);
    // wmma flash attention -> a2 directly
    attn_wmma<<<dim3(TLEN / 64, NHEAD, BATCH), 256, AW_SMEM>>>(q2, khl, vhl, rel2, a2);
    // out = attn @ wo + bo (mode 0)
    tgemm_wmma<<<dim3(DMODEL / 128, BATCH * TLEN / 128), 256, TG_SMEM>>>(
        a2, wo2, bo, out_main, nullptr, nullptr, nullptr, BATCH * TLEN, DMODEL, KP3, 0);
    // mem_next = x
    {
        size_t n4 = (size_t)BATCH * TLEN * DMODEL / 4;
        copy_x<<<(unsigned)((n4 + 255) / 256), 256>>>(x, mem_next);
    }
}

// round 10
// speedup vs baseline: 3.6636x; 1.0744x over previous
#include <cuda_runtime.h>
#include <cuda_bf16.h>
#include <mma.h>
#include <cstddef>
#include <cstdint>

using namespace nvcuda;

#define BATCH   4
#define TLEN    1024
#define MEMLEN  1024
#define JDIM    2048
#define DMODEL  1024
#define NHEAD   16
#define DHEAD   64
#define KP3     3072      // 3 * DMODEL (compensated K)

// -------- scratch (static __device__ globals; cudaMalloc is forbidden) ------
__device__ __nv_bfloat16 g_x2   [(size_t)BATCH * TLEN * KP3];    // [h|l|h]
__device__ __nv_bfloat16 g_kvin2[(size_t)BATCH * JDIM * KP3];    // [h|l|h]
__device__ __nv_bfloat16 g_a2   [(size_t)BATCH * TLEN * KP3];    // [h|l|h]
__device__ __nv_bfloat16 g_wq2  [(size_t)DMODEL * KP3];          // [h|h|l] (transposed)
__device__ __nv_bfloat16 g_wkv2 [(size_t)2 * DMODEL * KP3];      // [h|h|l]
__device__ __nv_bfloat16 g_wo2  [(size_t)DMODEL * KP3];          // [h|h|l]
__device__ __nv_bfloat16 g_q2   [(size_t)BATCH * NHEAD * TLEN * 128];  // [Qh|Ql]
__device__ __nv_bfloat16 g_rel2 [(size_t)NHEAD * JDIM * 64];           // hi only
__device__ __nv_bfloat16 g_khl  [(size_t)BATCH * NHEAD * JDIM * 128];  // [Kh|Kl]
__device__ __nv_bfloat16 g_vhl  [(size_t)BATCH * NHEAD * JDIM * 128];  // [Vh|Vl]

// ---------------------------------------------------------------------------
__device__ __forceinline__ uint32_t smem_u32(const void* p) {
    uint32_t a;
    asm("{ .reg .u64 t; cvta.to.shared.u64 t, %1; cvt.u32.u64 %0, t; }" : "=r"(a) : "l"(p));
    return a;
}
__device__ __forceinline__ void cpasync16s(uint32_t saddr, const void* gsrc) {
    asm volatile("cp.async.cg.shared.global [%0], [%1], 16;\n" :: "r"(saddr), "l"(gsrc));
}
__device__ __forceinline__ void cpasync16(void* smem_dst, const void* gsrc) {
    cpasync16s((uint32_t)__cvta_generic_to_shared(smem_dst), gsrc);
}
__device__ __forceinline__ void cp_commit() { asm volatile("cp.async.commit_group;\n"); }
__device__ __forceinline__ void cp_wait0()  { asm volatile("cp.async.wait_group 0;\n"); }
__device__ __forceinline__ void cp_wait1()  { asm volatile("cp.async.wait_group 1;\n"); }

__device__ __forceinline__ void split1(float v, __nv_bfloat16& h, __nv_bfloat16& l) {
    h = __float2bfloat16(v);
    l = __float2bfloat16(v - __bfloat162float(h));
}

// raw tensor-core primitives (documented PTX layouts, sm_80+)
__device__ __forceinline__ void ldmx4(uint32_t* r, uint32_t addr) {
    asm volatile("ldmatrix.sync.aligned.m8n8.x4.shared.b16 {%0,%1,%2,%3}, [%4];"
                 : "=r"(r[0]), "=r"(r[1]), "=r"(r[2]), "=r"(r[3]) : "r"(addr));
}
__device__ __forceinline__ void ldmx2t(uint32_t* r, uint32_t addr) {
    asm volatile("ldmatrix.sync.aligned.m8n8.x2.trans.shared.b16 {%0,%1}, [%2];"
                 : "=r"(r[0]), "=r"(r[1]) : "r"(addr));
}
__device__ __forceinline__ void mma16816(float* c, const uint32_t* a, const uint32_t* b) {
    asm volatile("mma.sync.aligned.m16n8k16.row.col.f32.bf16.bf16.f32 "
                 "{%0,%1,%2,%3},{%4,%5,%6,%7},{%8,%9},{%0,%1,%2,%3};"
                 : "+f"(c[0]), "+f"(c[1]), "+f"(c[2]), "+f"(c[3])
                 : "r"(a[0]), "r"(a[1]), "r"(a[2]), "r"(a[3]), "r"(b[0]), "r"(b[1]));
}

// ---------------------------------------------------------------------------
// prep kernels (unchanged)
// ---------------------------------------------------------------------------
__global__ void split3_rows(const float* __restrict__ in, __nv_bfloat16* __restrict__ out,
                            size_t total) {
    size_t i = (size_t)blockIdx.x * blockDim.x + threadIdx.x;
    if (i >= total) return;
    size_t r = i >> 8;
    int c4 = (int)(i & 255) * 4;
    float4 v = *(const float4*)&in[r * DMODEL + c4];
    __nv_bfloat16 h[4], l[4];
    split1(v.x, h[0], l[0]); split1(v.y, h[1], l[1]);
    split1(v.z, h[2], l[2]); split1(v.w, h[3], l[3]);
    __nv_bfloat16* o = out + r * KP3;
    __nv_bfloat162 hp0 = __halves2bfloat162(h[0], h[1]), hp1 = __halves2bfloat162(h[2], h[3]);
    __nv_bfloat162 lp0 = __halves2bfloat162(l[0], l[1]), lp1 = __halves2bfloat162(l[2], l[3]);
    *(__nv_bfloat162*)(o + c4)              = hp0; *(__nv_bfloat162*)(o + c4 + 2)              = hp1;
    *(__nv_bfloat162*)(o + DMODEL + c4)     = lp0; *(__nv_bfloat162*)(o + DMODEL + c4 + 2)     = lp1;
    *(__nv_bfloat162*)(o + 2 * DMODEL + c4) = hp0; *(__nv_bfloat162*)(o + 2 * DMODEL + c4 + 2) = hp1;
}

__global__ void build_kvin_split3(const float* __restrict__ x, const float* __restrict__ mem,
                                  __nv_bfloat16* __restrict__ out) {
    size_t i = (size_t)blockIdx.x * blockDim.x + threadIdx.x;
    const size_t total = (size_t)BATCH * JDIM * 256;
    if (i >= total) return;
    size_t r = i >> 8;
    int c4 = (int)(i & 255) * 4;
    size_t b = r / JDIM, m = r % JDIM;
    float4 v;
    if (m < MEMLEN) v = *(const float4*)&mem[(b * MEMLEN + m) * DMODEL + c4];
    else            v = *(const float4*)&x  [(b * TLEN + (m - MEMLEN)) * DMODEL + c4];
    __nv_bfloat16 h[4], l[4];
    split1(v.x, h[0], l[0]); split1(v.y, h[1], l[1]);
    split1(v.z, h[2], l[2]); split1(v.w, h[3], l[3]);
    __nv_bfloat16* o = out + r * KP3;
    __nv_bfloat162 hp0 = __halves2bfloat162(h[0], h[1]), hp1 = __halves2bfloat162(h[2], h[3]);
    __nv_bfloat162 lp0 = __halves2bfloat162(l[0], l[1]), lp1 = __halves2bfloat162(l[2], l[3]);
    *(__nv_bfloat162*)(o + c4)              = hp0; *(__nv_bfloat162*)(o + c4 + 2)              = hp1;
    *(__nv_bfloat162*)(o + DMODEL + c4)     = lp0; *(__nv_bfloat162*)(o + DMODEL + c4 + 2)     = lp1;
    *(__nv_bfloat162*)(o + 2 * DMODEL + c4) = hp0; *(__nv_bfloat162*)(o + 2 * DMODEL + c4 + 2) = hp1;
}

__global__ void transpose_split3(const float* __restrict__ W, __nv_bfloat16* __restrict__ T2, int N) {
    __shared__ float t[32][33];
    int k0 = blockIdx.y * 32, n0 = blockIdx.x * 32;
    int tx = threadIdx.x, ty = threadIdx.y;
#pragma unroll
    for (int i = 0; i < 32; i += 8)
        t[ty + i][tx] = W[(size_t)(k0 + ty + i) * N + n0 + tx];
    __syncthreads();
#pragma unroll
    for (int i = 0; i < 32; i += 8) {
        float v = t[tx][ty + i];
        int n = n0 + ty + i, k = k0 + tx;
        __nv_bfloat16 h, l;
        split1(v, h, l);
        __nv_bfloat16* o = T2 + (size_t)n * KP3;
        o[k] = h; o[DMODEL + k] = h; o[2 * DMODEL + k] = l;
    }
}

__global__ void build_rel2k(const float* __restrict__ rel, __nv_bfloat16* __restrict__ rel2) {
    size_t i = (size_t)blockIdx.x * blockDim.x + threadIdx.x;
    const size_t total = (size_t)JDIM * NHEAD * 16;
    if (i >= total) return;
    int c4 = (int)(i & 15) * 4;
    int h  = (int)(i >> 4) & 15;
    int u  = (int)(i >> 8);
    float4 v = *(const float4*)&rel[((size_t)u * NHEAD + h) * DHEAD + c4];
    __nv_bfloat16* o = rel2 + ((size_t)h * JDIM + u) * 64;
    *(__nv_bfloat162*)(o + c4)     = __halves2bfloat162(__float2bfloat16(v.x), __float2bfloat16(v.y));
    *(__nv_bfloat162*)(o + c4 + 2) = __halves2bfloat162(__float2bfloat16(v.z), __float2bfloat16(v.w));
}

__global__ void copy_x(const float* __restrict__ x, float* __restrict__ dst) {
    size_t i = (size_t)blockIdx.x * blockDim.x + threadIdx.x;
    const size_t total = (size_t)BATCH * TLEN * DMODEL / 4;
    if (i < total) ((float4*)dst)[i] = ((const float4*)x)[i];
}

// ---------------------------------------------------------------------------
// wmma bf16 GEMM, 3-stage cp.async pipeline, fused epilogues (unchanged)
// ---------------------------------------------------------------------------
#define STG_BYTES 20480
#define LDS_ROW   40
#define NSTAGE    3

__global__ __launch_bounds__(256)
void tgemm_wmma(const __nv_bfloat16* __restrict__ A, const __nv_bfloat16* __restrict__ B,
                const float* __restrict__ bias, float* __restrict__ C,
                __nv_bfloat16* __restrict__ q2o,
                __nv_bfloat16* __restrict__ khlo, __nv_bfloat16* __restrict__ vhlo,
                int M, int N, int Kp, int mode) {
    extern __shared__ char sm[];
    const uint32_t sbase = smem_u32(sm);
    float* biasS = (float*)(sm + NSTAGE * STG_BYTES);

    const int tid = threadIdx.x;
    const int wid = tid >> 5;
    const int wm = wid >> 2;
    const int wn = wid & 3;
    const int row0 = blockIdx.y * 128;
    const int col0 = blockIdx.x * 128;

    if (mode == 0)
        for (int i = tid; i < 16 * 128; i += 256)
            biasS[i] = bias ? bias[col0 + (i & 127)] : 0.f;

    auto loadStage = [&](int s, int k0) {
        uint32_t ab = sbase + s * STG_BYTES;
        uint32_t bb = ab + STG_BYTES / 2;
#pragma unroll
        for (int p = 0; p < 2; ++p) {
            int i = tid + p * 256;
            int r = i >> 2, qq = i & 3;
            cpasync16s(ab + r * 80 + qq * 16,
                       (const char*)A + (((size_t)(row0 + r)) * Kp + k0 + qq * 8) * 2);
            cpasync16s(bb + r * 80 + qq * 16,
                       (const char*)B + (((size_t)(col0 + r)) * Kp + k0 + qq * 8) * 2);
        }
    };

    wmma::fragment<wmma::accumulator, 16, 16, 16, float> acc[4][2];
    __syncthreads();
    if (mode == 0) {
#pragma unroll
        for (int i = 0; i < 4; ++i)
#pragma unroll
            for (int j = 0; j < 2; ++j)
                wmma::load_matrix_sync(acc[i][j], &biasS[wn * 32 + j * 16], 128, wmma::mem_row_major);
    } else {
#pragma unroll
        for (int i = 0; i < 4; ++i)
#pragma unroll
            for (int j = 0; j < 2; ++j)
                wmma::fill_fragment(acc[i][j], 0.f);
    }

    loadStage(0, 0); cp_commit();
    loadStage(1, 32); cp_commit();

    const int nst = Kp / 32;
    for (int st = 0; st < nst; ++st) {
        if (st == nst - 1) cp_wait0(); else cp_wait1();
        __syncthreads();
        if (st + 2 < nst) { loadStage((st + 2) % NSTAGE, (st + 2) * 32); cp_commit(); }

        const __nv_bfloat16* as = (const __nv_bfloat16*)(sm + (st % NSTAGE) * STG_BYTES);
        const __nv_bfloat16* bs = as + STG_BYTES / 4;

#pragma unroll
        for (int kk = 0; kk < 2; ++kk) {
            wmma::fragment<wmma::matrix_a, 16, 16, 16, __nv_bfloat16, wmma::row_major> af[4];
            wmma::fragment<wmma::matrix_b, 16, 16, 16, __nv_bfloat16, wmma::col_major> bfr[2];
#pragma unroll
            for (int i = 0; i < 4; ++i)
                wmma::load_matrix_sync(af[i], as + (wm * 64 + i * 16) * LDS_ROW + kk * 16, LDS_ROW);
#pragma unroll
            for (int j = 0; j < 2; ++j)
                wmma::load_matrix_sync(bfr[j], bs + (wn * 32 + j * 16) * LDS_ROW + kk * 16, LDS_ROW);
#pragma unroll
            for (int i = 0; i < 4; ++i)
#pragma unroll
                for (int j = 0; j < 2; ++j)
                    wmma::mma_sync(acc[i][j], af[i], bfr[j], acc[i][j]);
        }
    }

    if (mode == 0) {
#pragma unroll
        for (int i = 0; i < 4; ++i)
#pragma unroll
            for (int j = 0; j < 2; ++j)
                wmma::store_matrix_sync(&C[(size_t)(row0 + wm * 64 + i * 16) * N + col0 + wn * 32 + j * 16],
                                        acc[i][j], N, wmma::mem_row_major);
        return;
    }

    __syncthreads();
    float* Cs = (float*)sm;   // [128][132]
#pragma unroll
    for (int i = 0; i < 4; ++i)
#pragma unroll
        for (int j = 0; j < 2; ++j)
            wmma::store_matrix_sync(&Cs[(size_t)(wm * 64 + i * 16) * 132 + wn * 32 + j * 16],
                                    acc[i][j], 132, wmma::mem_row_major);
    __syncthreads();

    if (mode == 1) {
        for (int idx = tid; idx < 128 * 128; idx += 256) {
            int r = idx >> 7, c = idx & 127;
            float v = Cs[r * 132 + c];
            __nv_bfloat16 hv, lv; split1(v, hv, lv);
            int bt = row0 + r, gc = col0 + c;
            int b = bt >> 10, t = bt & 1023;
            int h = gc >> 6, cc = gc & 63;
            __nv_bfloat16* o = q2o + (((size_t)(b * NHEAD + h) * TLEN + t)) * 128 + cc;
            o[0] = hv; o[64] = lv;
        }
    } else {
        for (int idx = tid; idx < 128 * 128; idx += 256) {
            int r = idx >> 7, c = idx & 127;
            float v = Cs[r * 132 + c];
            __nv_bfloat16 hv, lv; split1(v, hv, lv);
            int rg = row0 + r, gc = col0 + c;
            int b = rg >> 11, m = rg & 2047;
            __nv_bfloat16* dst = (gc < DMODEL) ? khlo : vhlo;
            int gcl = (gc < DMODEL) ? gc : gc - DMODEL;
            int h = gcl >> 6, cc = gcl & 63;
            __nv_bfloat16* o = dst + (((size_t)(b * NHEAD + h) * JDIM + m)) * 128 + cc;
            o[0] = hv; o[64] = lv;
        }
    }
}

// ---------------------------------------------------------------------------
// wmma flash attention: S via wmma, softmax SIMT, PV via raw mma.sync with
// register accumulators (known C-layout), incremental rel-R ring, K+V double
// buffered with loop-top prefetch.
// ---------------------------------------------------------------------------
struct __align__(16) AttnW {
    __nv_bfloat16 Q2s[64][136];       // [Qh(64) | Ql(64)]
    __nv_bfloat16 Khl[2][64][136];    // [Kh | Kl] double-buffered
    __nv_bfloat16 Vhl[2][64][136];    // [Vh | Vl] double-buffered
    __nv_bfloat16 Wh[2][64][72];      // W span ring (hi only)
    float         Sx[64][72];         // QK scores
    float         Rx[2][64][68];      // rel scores ring (64-col halves)
    __nv_bfloat16 Phl[64][136];       // [Ph | Pl]
    float m_s[64];
    float l_s[64];
    float alpha_s[64];
};

__device__ __forceinline__ void aw_pf_K(AttnW& S, int bb, const __nv_bfloat16* __restrict__ khl,
                                        size_t bh, int m0, int tid) {
#pragma unroll
    for (int p = 0; p < 4; ++p) {
        int i = tid + p * 256;
        int r = i >> 4, c = i & 15;
        cpasync16(&S.Khl[bb][r][c * 8], khl + (bh * JDIM + (size_t)(m0 + r)) * 128 + c * 8);
    }
}
__device__ __forceinline__ void aw_pf_V(AttnW& S, int bb, const __nv_bfloat16* __restrict__ vhl,
                                        size_t bh, int m0, int tid) {
#pragma unroll
    for (int p = 0; p < 4; ++p) {
        int i = tid + p * 256;
        int r = i >> 4, c = i & 15;
        cpasync16(&S.Vhl[bb][r][c * 8], vhl + (bh * JDIM + (size_t)(m0 + r)) * 128 + c * 8);
    }
}
__device__ __forceinline__ void aw_pf_W(AttnW& S, int slot, const __nv_bfloat16* __restrict__ rel2,
                                        int h, int ubase, int tid) {
#pragma unroll
    for (int p = 0; p < 2; ++p) {
        int i = tid + p * 256;
        int o = i >> 3, c = i & 7;
        int u = ubase + o; if (u > JDIM - 1) u = JDIM - 1;
        cpasync16(&S.Wh[slot][o][c * 8], rel2 + ((size_t)h * JDIM + u) * 64 + c * 8);
    }
}

__global__ __launch_bounds__(256, 1)
void attn_wmma(const __nv_bfloat16* __restrict__ q2,
               const __nv_bfloat16* __restrict__ khl,
               const __nv_bfloat16* __restrict__ vhl,
               const __nv_bfloat16* __restrict__ rel2,
               __nv_bfloat16* __restrict__ a2) {
    extern __shared__ char smem_raw[];
    AttnW& S = *reinterpret_cast<AttnW*>(smem_raw);

    const int b  = blockIdx.z;
    const int h  = blockIdx.y;
    const int rb = (int)gridDim.x - 1 - (int)blockIdx.x;   // long blocks first
    const int r0 = rb * 64;
    const size_t bh = (size_t)(b * NHEAD + h);
    const int tid = threadIdx.x;
    const int wid = tid >> 5;
    const int lane = tid & 31;
    const int wm = wid >> 2;     // 0..1 (wmma row half for S/R)
    const int wn = wid & 3;      // 0..3
    const int sy = tid >> 4;     // 0..15
    const int sx = tid & 15;     // 0..15
    // PV warp mapping
    const int wm2 = wid & 3;     // row tile (16 rows)
    const int wn2 = wid >> 2;    // col half (32 cols)
    const int g   = lane >> 2;
    const int tig = lane & 3;

#pragma unroll
    for (int p = 0; p < 4; ++p) {
        int i = tid + p * 256;
        int r = i >> 4, c = i & 15;
        cpasync16(&S.Q2s[r][c * 8],
                  q2 + (bh * TLEN + (size_t)(r0 + r)) * 128 + c * 8);
    }
    aw_pf_K(S, 0, khl, bh, 0, tid);
    aw_pf_V(S, 0, vhl, bh, 0, tid);
    aw_pf_W(S, 1, rel2, h, 960 - r0, tid);        // initial LEFT half
    aw_pf_W(S, 0, rel2, h, 1024 - r0, tid);       // tile-0 RIGHT half
    cp_commit();

    if (tid < 64) { S.m_s[tid] = -1e30f; S.l_s[tid] = 0.f; }

    float accf[4][4];
#pragma unroll
    for (int i = 0; i < 4; ++i)
#pragma unroll
        for (int j = 0; j < 4; ++j) accf[i][j] = 0.f;

    const int ntiles = min(32, rb + 17);

    for (int mt = 0; mt < ntiles; ++mt) {
        const int cur = mt & 1;
        const int prv = cur ^ 1;
        const int m0  = mt * 64;

        cp_wait0();
        __syncthreads();                    // K(t), V(t), Wnew(t) ready

        if (mt + 1 < ntiles) {
            aw_pf_K(S, prv, khl, bh, m0 + 64, tid);
            aw_pf_V(S, prv, vhl, bh, m0 + 64, tid);
            cp_commit();
        }

        // ---- S: 3 compensated wmma passes (64x64) ----
        {
            wmma::fragment<wmma::accumulator, 16, 16, 16, float> sacc[2];
#pragma unroll
            for (int i = 0; i < 2; ++i) wmma::fill_fragment(sacc[i], 0.f);
#pragma unroll
            for (int pass = 0; pass < 3; ++pass) {
                const int aoff = (pass == 1) ? 64 : 0;
                const int boff = (pass == 2) ? 64 : 0;
#pragma unroll
                for (int k16 = 0; k16 < 4; ++k16) {
                    wmma::fragment<wmma::matrix_a, 16, 16, 16, __nv_bfloat16, wmma::row_major> af[2];
                    wmma::fragment<wmma::matrix_b, 16, 16, 16, __nv_bfloat16, wmma::col_major> bfr;
#pragma unroll
                    for (int i = 0; i < 2; ++i)
                        wmma::load_matrix_sync(af[i], &S.Q2s[wm * 32 + i * 16][aoff + k16 * 16], 136);
                    wmma::load_matrix_sync(bfr, &S.Khl[cur][wn * 16][boff + k16 * 16], 136);
#pragma unroll
                    for (int i = 0; i < 2; ++i)
                        wmma::mma_sync(sacc[i], af[i], bfr, sacc[i]);
                }
            }
#pragma unroll
            for (int i = 0; i < 2; ++i)
                wmma::store_matrix_sync(&S.Sx[wm * 32 + i * 16][wn * 16], sacc[i], 72,
                                        wmma::mem_row_major);
        }
        // ---- R: new 64x64 half (Qh x Wnew^T); at mt==0 also the left half ----
        {
            const int nR = (mt == 0) ? 2 : 1;
            for (int rr = 0; rr < nR; ++rr) {
                const int slot = (rr == 0) ? cur : prv;
                wmma::fragment<wmma::accumulator, 16, 16, 16, float> racc[2];
#pragma unroll
                for (int i = 0; i < 2; ++i) wmma::fill_fragment(racc[i], 0.f);
#pragma unroll
                for (int k16 = 0; k16 < 4; ++k16) {
                    wmma::fragment<wmma::matrix_a, 16, 16, 16, __nv_bfloat16, wmma::row_major> af[2];
                    wmma::fragment<wmma::matrix_b, 16, 16, 16, __nv_bfloat16, wmma::col_major> bfr;
#pragma unroll
                    for (int i = 0; i < 2; ++i)
                        wmma::load_matrix_sync(af[i], &S.Q2s[wm * 32 + i * 16][k16 * 16], 136);
                    wmma::load_matrix_sync(bfr, &S.Wh[slot][wn * 16][k16 * 16], 72);
#pragma unroll
                    for (int i = 0; i < 2; ++i)
                        wmma::mma_sync(racc[i], af[i], bfr, racc[i]);
                }
#pragma unroll
                for (int i = 0; i < 2; ++i)
                    wmma::store_matrix_sync(&S.Rx[slot][wm * 32 + i * 16][wn * 16], racc[i], 68,
                                            wmma::mem_row_major);
            }
        }
        __syncthreads();                    // Sx, Rx visible; Wh consumed

        if (mt + 1 < ntiles) {
            aw_pf_W(S, (mt + 1) & 1, rel2, h, m0 + 1088 - r0, tid);
            cp_commit();
        }

        // ---- softmax (SIMT), P -> bf16 hi/lo ----
#pragma unroll
        for (int i = 0; i < 4; ++i) {
            const int rl = 4 * sy + i;
            const int mlim = r0 + rl + MEMLEN - m0;
            const int ro = 63 - rl;
            float4 sv = *(const float4*)&S.Sx[rl][4 * sx];
            float sraw[4] = {sv.x, sv.y, sv.z, sv.w};
            float sc[4];
#pragma unroll
            for (int j = 0; j < 4; ++j) {
                int o = 4 * sx + j + ro;
                float rv = (o < 64) ? S.Rx[prv][rl][o] : S.Rx[cur][rl][o - 64];
                sc[j] = (sraw[j] + rv) * 0.125f;
                if (4 * sx + j > mlim) sc[j] = -1e30f;
            }
            float rmax = fmaxf(fmaxf(sc[0], sc[1]), fmaxf(sc[2], sc[3]));
            rmax = fmaxf(rmax, __shfl_xor_sync(0xffffffffu, rmax, 1));
            rmax = fmaxf(rmax, __shfl_xor_sync(0xffffffffu, rmax, 2));
            rmax = fmaxf(rmax, __shfl_xor_sync(0xffffffffu, rmax, 4));
            rmax = fmaxf(rmax, __shfl_xor_sync(0xffffffffu, rmax, 8));
            float mold = S.m_s[rl];
            float mnew = fmaxf(mold, rmax);
            float alpha = __expf(mold - mnew);
            float lsum = 0.f;
            __nv_bfloat16 ph[4], pl[4];
#pragma unroll
            for (int j = 0; j < 4; ++j) {
                float p = __expf(sc[j] - mnew);
                lsum += p;
                ph[j] = __float2bfloat16(p);
                pl[j] = __float2bfloat16(p - __bfloat162float(ph[j]));
            }
            lsum += __shfl_xor_sync(0xffffffffu, lsum, 1);
            lsum += __shfl_xor_sync(0xffffffffu, lsum, 2);
            lsum += __shfl_xor_sync(0xffffffffu, lsum, 4);
            lsum += __shfl_xor_sync(0xffffffffu, lsum, 8);
            if (sx == 0) {
                S.m_s[rl] = mnew;
                S.l_s[rl] = S.l_s[rl] * alpha + lsum;
                S.alpha_s[rl] = alpha;
            }
            *(__nv_bfloat162*)&S.Phl[rl][4 * sx]          = __halves2bfloat162(ph[0], ph[1]);
            *(__nv_bfloat162*)&S.Phl[rl][4 * sx + 2]      = __halves2bfloat162(ph[2], ph[3]);
            *(__nv_bfloat162*)&S.Phl[rl][64 + 4 * sx]     = __halves2bfloat162(pl[0], pl[1]);
            *(__nv_bfloat162*)&S.Phl[rl][64 + 4 * sx + 2] = __halves2bfloat162(pl[2], pl[3]);
        }
        __syncthreads();                    // Phl, alpha_s visible

        // ---- PV: raw mma.sync, register accumulators ----
        {
            const int rowbase = wm2 * 16;
            const int colbase = wn2 * 32;
            float al1 = S.alpha_s[rowbase + g];
            float al2 = S.alpha_s[rowbase + 8 + g];
#pragma unroll
            for (int nt = 0; nt < 4; ++nt) {
                accf[nt][0] *= al1; accf[nt][1] *= al1;
                accf[nt][2] *= al2; accf[nt][3] *= al2;
            }
            // A fragments (Ph, Pl), canonical ldmatrix x4 layout
            uint32_t aPh[4][4], aPl[4][4];
            {
                int s = lane >> 3, rr2 = lane & 7;
                int arow = rowbase + (s & 1) * 8 + rr2;
                int acol = (s >> 1) * 8;
#pragma unroll
                for (int k16 = 0; k16 < 4; ++k16) {
                    ldmx4(aPh[k16], smem_u32(&S.Phl[arow][acol + k16 * 16]));
                    ldmx4(aPl[k16], smem_u32(&S.Phl[arow][64 + acol + k16 * 16]));
                }
            }
            // B from V via ldmatrix.x2.trans
            {
                int s = (lane >> 3) & 1, rr2 = lane & 7;
#pragma unroll
                for (int k16 = 0; k16 < 4; ++k16) {
                    int vrow = k16 * 16 + s * 8 + rr2;
#pragma unroll
                    for (int nt = 0; nt < 4; ++nt) {
                        uint32_t bhv[2], blv[2];
                        ldmx2t(bhv, smem_u32(&S.Vhl[cur][vrow][colbase + nt * 8]));
                        ldmx2t(blv, smem_u32(&S.Vhl[cur][vrow][64 + colbase + nt * 8]));
                        mma16816(accf[nt], aPh[k16], bhv);
                        mma16816(accf[nt], aPl[k16], bhv);
                        mma16816(accf[nt], aPh[k16], blv);
                    }
                }
            }
        }
        // no trailing sync: next loop-top sync orders Phl/V reuse
    }

    __syncthreads();
    // epilogue from fragments: write a2 [row][3072] = [h | l | h]
    {
        const int rowbase = wm2 * 16;
        const int colbase = wn2 * 32;
        int r1 = rowbase + g, r2 = r1 + 8;
        float inv1 = 1.f / S.l_s[r1];
        float inv2 = 1.f / S.l_s[r2];
        size_t grow1 = (size_t)(b * TLEN + r0 + r1) * KP3;
        size_t grow2 = (size_t)(b * TLEN + r0 + r2) * KP3;
#pragma unroll
        for (int nt = 0; nt < 4; ++nt) {
            int col = h * 64 + colbase + nt * 8 + 2 * tig;
            float v0 = accf[nt][0] * inv1, v1 = accf[nt][1] * inv1;
            float v2 = accf[nt][2] * inv2, v3 = accf[nt][3] * inv2;
            __nv_bfloat16 h0, l0, h1, l1, h2, l2, h3, l3;
            split1(v0, h0, l0); split1(v1, h1, l1);
            split1(v2, h2, l2); split1(v3, h3, l3);
            __nv_bfloat16* o1 = a2 + grow1 + col;
            __nv_bfloat16* o2 = a2 + grow2 + col;
            *(__nv_bfloat162*)(o1)              = __halves2bfloat162(h0, h1);
            *(__nv_bfloat162*)(o1 + DMODEL)     = __halves2bfloat162(l0, l1);
            *(__nv_bfloat162*)(o1 + 2 * DMODEL) = __halves2bfloat162(h0, h1);
            *(__nv_bfloat162*)(o2)              = __halves2bfloat162(h2, h3);
            *(__nv_bfloat162*)(o2 + DMODEL)     = __halves2bfloat162(l2, l3);
            *(__nv_bfloat162*)(o2 + 2 * DMODEL) = __halves2bfloat162(h2, h3);
        }
    }
}

// ---------------------------------------------------------------------------
extern "C" void kernel_launch(void* const* d_in, const int* in_sizes, int n_in,
                              void* d_out, int out_size) {
    const float* x    = (const float*)d_in[0];
    const float* mem  = (const float*)d_in[1];
    const float* wq   = (const float*)d_in[2];
    const float* wkv  = (const float*)d_in[3];
    const float* wo   = (const float*)d_in[4];
    const float* bo   = (const float*)d_in[5];
    const float* relw = (const float*)d_in[6];

    float* out_main = (float*)d_out;
    float* mem_next = out_main + (size_t)BATCH * TLEN * DMODEL;

    __nv_bfloat16 *x2, *kvin2, *a2, *wq2, *wkv2, *wo2, *q2, *rel2, *khl, *vhl;
    cudaGetSymbolAddress((void**)&x2,    g_x2);
    cudaGetSymbolAddress((void**)&kvin2, g_kvin2);
    cudaGetSymbolAddress((void**)&a2,    g_a2);
    cudaGetSymbolAddress((void**)&wq2,   g_wq2);
    cudaGetSymbolAddress((void**)&wkv2,  g_wkv2);
    cudaGetSymbolAddress((void**)&wo2,   g_wo2);
    cudaGetSymbolAddress((void**)&q2,    g_q2);
    cudaGetSymbolAddress((void**)&rel2,  g_rel2);
    cudaGetSymbolAddress((void**)&khl,   g_khl);
    cudaGetSymbolAddress((void**)&vhl,   g_vhl);

    const int TG_SMEM = NSTAGE * STG_BYTES + 16 * 128 * 4;
    const int AW_SMEM = (int)sizeof(AttnW);
    cudaFuncSetAttribute(tgemm_wmma, cudaFuncAttributeMaxDynamicSharedMemorySize, TG_SMEM);
    cudaFuncSetAttribute(attn_wmma,  cudaFuncAttributeMaxDynamicSharedMemorySize, AW_SMEM);

    // operand prep
    {
        size_t tot = (size_t)BATCH * TLEN * 256;
        split3_rows<<<(unsigned)((tot + 255) / 256), 256>>>(x, x2, tot);
    }
    {
        size_t tot = (size_t)BATCH * JDIM * 256;
        build_kvin_split3<<<(unsigned)((tot + 255) / 256), 256>>>(x, mem, kvin2);
    }
    transpose_split3<<<dim3(DMODEL / 32, DMODEL / 32), dim3(32, 8)>>>(wq, wq2, DMODEL);
    transpose_split3<<<dim3(2 * DMODEL / 32, DMODEL / 32), dim3(32, 8)>>>(wkv, wkv2, 2 * DMODEL);
    transpose_split3<<<dim3(DMODEL / 32, DMODEL / 32), dim3(32, 8)>>>(wo, wo2, DMODEL);
    {
        size_t tot = (size_t)JDIM * NHEAD * 16;
        build_rel2k<<<(unsigned)((tot + 255) / 256), 256>>>(relw, rel2);
    }

    // q-proj -> q2 (mode 1)
    tgemm_wmma<<<dim3(DMODEL / 128, BATCH * TLEN / 128), 256, TG_SMEM>>>(
        x2, wq2, nullptr, nullptr, q2, nullptr, nullptr, BATCH * TLEN, DMODEL, KP3, 1);
    // kv-proj -> khl/vhl (mode 2)
    tgemm_wmma<<<dim3(2 * DMODEL / 128, BATCH * JDIM / 128), 256, TG_SMEM>>>(
        kvin2, wkv2, nullptr, nullptr, nullptr, khl, vhl, BATCH * JDIM, 2 * DMODEL, KP3, 2);
    // flash attention -> a2
    attn_wmma<<<dim3(TLEN / 64, NHEAD, BATCH), 256, AW_SMEM>>>(q2, khl, vhl, rel2, a2);
    // out = attn @ wo + bo (mode 0)
    tgemm_wmma<<<dim3(DMODEL / 128, BATCH * TLEN / 128), 256, TG_SMEM>>>(
        a2, wo2, bo, out_main, nullptr, nullptr, nullptr, BATCH * TLEN, DMODEL, KP3, 0);
    // mem_next = x
    {
        size_t n4 = (size_t)BATCH * TLEN * DMODEL / 4;
        copy_x<<<(unsigned)((n4 + 255) / 256), 256>>>(x, mem_next);
    }
}